// round 10
// baseline (speedup 1.0000x reference)
#include <cuda_runtime.h>
#include <cuda_fp16.h>
#include <cstdint>
#include <math.h>

#define BB   8
#define CIN  512
#define CK   256
#define CV   512
#define HW   4096
#define SS   110

// Scratch (__device__ globals are zero-initialized; pad regions never written
// stay zero -> free zero-padding).
__device__ __align__(16) __half g_xh    [BB*CIN*HW];    // [b][k][n]
__device__ __align__(16) __half g_qkh   [BB*CK*HW];     // [b][c][n]
__device__ __align__(16) __half g_valh  [BB*CV*HW];     // [b][c][n]
__device__ __align__(16) __half g_keyh  [BB*128*CK];    // [b][s(pad128)][c]
__device__ __align__(16) __half g_vpsp  [BB*CV*112];    // [b][c][s(pad112)]
__device__ __align__(16) __half g_ph    [BB*112*HW];    // [b][s(pad112)][n]
__device__ __align__(16) __half g_yh    [BB*CV*HW];     // [b][c][n]
__device__ __align__(16) __half g_wq    [CK*CIN];
__device__ __align__(16) __half g_wv    [CV*CIN];
__device__ __align__(16) __half g_wo    [CIN*CV];

// ---------------------------------------------------------------------------
__device__ __forceinline__ uint32_t smem_u32(const void* p) {
    uint32_t a;
    asm("{ .reg .u64 t; cvta.to.shared.u64 t, %1; cvt.u32.u64 %0, t; }" : "=r"(a) : "l"(p));
    return a;
}
__device__ __forceinline__ void ldsm_x4(uint32_t* r, uint32_t addr) {
    asm volatile("ldmatrix.sync.aligned.m8n8.x4.shared.b16 {%0,%1,%2,%3}, [%4];"
        : "=r"(r[0]), "=r"(r[1]), "=r"(r[2]), "=r"(r[3]) : "r"(addr));
}
__device__ __forceinline__ void ldsm_x4_t(uint32_t* r, uint32_t addr) {
    asm volatile("ldmatrix.sync.aligned.m8n8.x4.trans.shared.b16 {%0,%1,%2,%3}, [%4];"
        : "=r"(r[0]), "=r"(r[1]), "=r"(r[2]), "=r"(r[3]) : "r"(addr));
}
__device__ __forceinline__ void mma_f16(float* c, const uint32_t* a, const uint32_t* b) {
    asm volatile(
        "mma.sync.aligned.m16n8k16.row.col.f32.f16.f16.f32 "
        "{%0,%1,%2,%3}, {%4,%5,%6,%7}, {%8,%9}, {%0,%1,%2,%3};"
        : "+f"(c[0]), "+f"(c[1]), "+f"(c[2]), "+f"(c[3])
        : "r"(a[0]), "r"(a[1]), "r"(a[2]), "r"(a[3]), "r"(b[0]), "r"(b[1]));
}
__device__ __forceinline__ void cpa16(uint32_t dst, const void* src) {
    asm volatile("cp.async.cg.shared.global [%0], [%1], 16;" :: "r"(dst), "l"(src));
}

// ---------------------------------------------------------------------------
// Generalized GEMM: out[b,m,n] = epi( sum_k A[m,k] * B[b,k,n] )
// CTA 128m x 128n, 8 warps (2x4), warp 64x32. K staged 64, 3-stage pipeline
// (halves barrier count vs K=32/4-stage; prefetch distance 2 stages > DRAM lat).
// FUSED: blockIdx.y<2 -> branch 1, else branch 2.
// SOFTMAX: epilogue computes column-softmax over m (valid rows < SS) and
//          writes fp16 probabilities directly (rows [SS,112) written 0).
// ---------------------------------------------------------------------------
#define A_STRH 72
#define B_STRH 136
#define A_STG  (128*A_STRH*2)              // 18432 B
#define B_STG  (64*B_STRH*2)               // 17408 B
#define STG    (A_STG + B_STG)             // 35840 B
#define NSTAGE 3
#define GEMM_SMEM (NSTAGE*STG)             // 107520 B

template<bool FUSED, bool BN, bool RELU, bool RESID, bool HALF_OUT, bool SOFTMAX>
__global__ __launch_bounds__(256, 2) void gemm_kernel(
    const __half* __restrict__ A, size_t a_bstride,
    const __half* __restrict__ Bm, size_t b_bstride,
    const float* __restrict__ gamma, const float* __restrict__ beta,
    const float* __restrict__ mean,  const float* __restrict__ var,
    float uscale,
    const float* __restrict__ resid,
    void* __restrict__ outp, size_t o_bstride,
    int Ktot,
    // FUSED branch-2 args
    const __half* __restrict__ A2,
    const float* __restrict__ gamma2, const float* __restrict__ beta2,
    const float* __restrict__ mean2,  const float* __restrict__ var2,
    void* __restrict__ outp2, size_t o_bstride2)
{
    extern __shared__ __align__(16) char smc[];
    const uint32_t sb = smem_u32(smc);
    const int tid = threadIdx.x, lane = tid & 31, wid = tid >> 5;
    const int gidr = lane >> 2, t4 = lane & 3;
    const int wm = wid >> 2, wn = wid & 3;
    const int n0 = blockIdx.x * 128, b = blockIdx.z;
    const int NK = Ktot >> 6;          // stages of K=64

    int m0 = blockIdx.y * 128;
    const __half* Ause = A;
    const float *g_ = gamma, *be_ = beta, *me_ = mean, *va_ = var;
    void* ouse = outp;
    size_t ostr = o_bstride;
    if (FUSED && blockIdx.y >= 2) {
        m0 = (blockIdx.y - 2) * 128;
        Ause = A2; g_ = gamma2; be_ = beta2; me_ = mean2; va_ = var2;
        ouse = outp2; ostr = o_bstride2;
    }

    const __half* gA = Ause + (size_t)b * a_bstride + (size_t)m0 * Ktot;
    const __half* gB = Bm + (size_t)b * b_bstride + n0;

    auto load_stage = [&](int s) {
        const uint32_t base = sb + (uint32_t)(s % NSTAGE) * STG;
        #pragma unroll
        for (int it = 0; it < 4; ++it) {            // A: 128r x 8 chunks
            int idx = it * 256 + tid;
            int r = idx >> 3, c = idx & 7;
            cpa16(base + (uint32_t)(r * A_STRH + c * 8) * 2,
                  gA + (size_t)r * Ktot + s * 64 + c * 8);
        }
        #pragma unroll
        for (int it = 0; it < 4; ++it) {            // B: 64r x 16 chunks
            int idx = it * 256 + tid;
            int r = idx >> 4, c = idx & 15;
            cpa16(base + A_STG + (uint32_t)(r * B_STRH + c * 8) * 2,
                  gB + (size_t)(s * 64 + r) * HW + c * 8);
        }
        asm volatile("cp.async.commit_group;" ::: "memory");
    };

    float acc[4][4][4];
    #pragma unroll
    for (int mt = 0; mt < 4; ++mt)
        #pragma unroll
        for (int nt = 0; nt < 4; ++nt)
            #pragma unroll
            for (int r = 0; r < 4; ++r) acc[mt][nt][r] = 0.f;

    load_stage(0); load_stage(1);
    asm volatile("cp.async.wait_group 1;" ::: "memory");
    __syncthreads();

    const int a_row = lane & 15, a_koff = (lane >> 4) * 8;
    const int b_krow = ((lane >> 3) & 1) * 8 + (lane & 7);
    const int b_noff = (lane >> 4) * 8;

    for (int kt = 0; kt < NK; ++kt) {
        if (kt + 2 < NK) load_stage(kt + 2);
        else asm volatile("cp.async.commit_group;" ::: "memory");

        const uint32_t sA = sb + (uint32_t)(kt % NSTAGE) * STG;
        const uint32_t sB = sA + A_STG;
        #pragma unroll
        for (int s16 = 0; s16 < 4; ++s16) {
            const int kk = s16 * 16;
            uint32_t af[4][4], bf[4][2];
            #pragma unroll
            for (int mt = 0; mt < 4; ++mt) {
                int row = wm * 64 + mt * 16 + a_row;
                ldsm_x4(af[mt], sA + (uint32_t)(row * A_STRH + kk + a_koff) * 2);
            }
            #pragma unroll
            for (int nt2 = 0; nt2 < 2; ++nt2) {
                uint32_t r4[4];
                int ncol = wn * 32 + nt2 * 16 + b_noff;
                ldsm_x4_t(r4, sB + (uint32_t)((kk + b_krow) * B_STRH + ncol) * 2);
                bf[nt2*2][0] = r4[0]; bf[nt2*2][1] = r4[1];
                bf[nt2*2+1][0] = r4[2]; bf[nt2*2+1][1] = r4[3];
            }
            #pragma unroll
            for (int mt = 0; mt < 4; ++mt)
                #pragma unroll
                for (int nt = 0; nt < 4; ++nt)
                    mma_f16(acc[mt][nt], af[mt], bf[nt]);
        }
        asm volatile("cp.async.wait_group 1;" ::: "memory");
        __syncthreads();
    }

    if (SOFTMAX) {
        // Column softmax over m rows (m0==0, grid.y==1). Valid rows: < SS.
        float* red = (float*)smc;              // reuse stage smem (512 floats)
        float cmax[4][2], csum[4][2];
        #pragma unroll
        for (int nt = 0; nt < 4; ++nt) { cmax[nt][0] = -3.4e38f; cmax[nt][1] = -3.4e38f; }
        #pragma unroll
        for (int mt = 0; mt < 4; ++mt) {
            const int r0 = wm * 64 + mt * 16 + gidr, r1 = r0 + 8;
            #pragma unroll
            for (int nt = 0; nt < 4; ++nt) {
                #pragma unroll
                for (int r = 0; r < 4; ++r) acc[mt][nt][r] *= uscale;
                if (r0 < SS) {
                    cmax[nt][0] = fmaxf(cmax[nt][0], acc[mt][nt][0]);
                    cmax[nt][1] = fmaxf(cmax[nt][1], acc[mt][nt][1]);
                }
                if (r1 < SS) {
                    cmax[nt][0] = fmaxf(cmax[nt][0], acc[mt][nt][2]);
                    cmax[nt][1] = fmaxf(cmax[nt][1], acc[mt][nt][3]);
                }
            }
        }
        #pragma unroll
        for (int nt = 0; nt < 4; ++nt)
            #pragma unroll
            for (int j = 0; j < 2; ++j) {
                float v = cmax[nt][j];
                v = fmaxf(v, __shfl_xor_sync(0xffffffffu, v, 4));
                v = fmaxf(v, __shfl_xor_sync(0xffffffffu, v, 8));
                v = fmaxf(v, __shfl_xor_sync(0xffffffffu, v, 16));
                cmax[nt][j] = v;
            }
        if (gidr == 0)
            #pragma unroll
            for (int nt = 0; nt < 4; ++nt)
                #pragma unroll
                for (int j = 0; j < 2; ++j)
                    red[wm*128 + wn*32 + nt*8 + 2*t4 + j] = cmax[nt][j];
        __syncthreads();
        #pragma unroll
        for (int nt = 0; nt < 4; ++nt)
            #pragma unroll
            for (int j = 0; j < 2; ++j)
                cmax[nt][j] = fmaxf(cmax[nt][j], red[(wm^1)*128 + wn*32 + nt*8 + 2*t4 + j]);

        #pragma unroll
        for (int nt = 0; nt < 4; ++nt) { csum[nt][0] = 0.f; csum[nt][1] = 0.f; }
        #pragma unroll
        for (int mt = 0; mt < 4; ++mt) {
            const int r0 = wm * 64 + mt * 16 + gidr, r1 = r0 + 8;
            #pragma unroll
            for (int nt = 0; nt < 4; ++nt) {
                float e0 = (r0 < SS) ? __expf(acc[mt][nt][0] - cmax[nt][0]) : 0.f;
                float e1 = (r0 < SS) ? __expf(acc[mt][nt][1] - cmax[nt][1]) : 0.f;
                float e2 = (r1 < SS) ? __expf(acc[mt][nt][2] - cmax[nt][0]) : 0.f;
                float e3 = (r1 < SS) ? __expf(acc[mt][nt][3] - cmax[nt][1]) : 0.f;
                acc[mt][nt][0] = e0; acc[mt][nt][1] = e1;
                acc[mt][nt][2] = e2; acc[mt][nt][3] = e3;
                csum[nt][0] += e0 + e2; csum[nt][1] += e1 + e3;
            }
        }
        #pragma unroll
        for (int nt = 0; nt < 4; ++nt)
            #pragma unroll
            for (int j = 0; j < 2; ++j) {
                float v = csum[nt][j];
                v += __shfl_xor_sync(0xffffffffu, v, 4);
                v += __shfl_xor_sync(0xffffffffu, v, 8);
                v += __shfl_xor_sync(0xffffffffu, v, 16);
                csum[nt][j] = v;
            }
        if (gidr == 0)
            #pragma unroll
            for (int nt = 0; nt < 4; ++nt)
                #pragma unroll
                for (int j = 0; j < 2; ++j)
                    red[256 + wm*128 + wn*32 + nt*8 + 2*t4 + j] = csum[nt][j];
        __syncthreads();
        #pragma unroll
        for (int nt = 0; nt < 4; ++nt)
            #pragma unroll
            for (int j = 0; j < 2; ++j)
                csum[nt][j] += red[256 + (wm^1)*128 + wn*32 + nt*8 + 2*t4 + j];

        __half* oh = (__half*)ouse + (size_t)b * ostr;
        #pragma unroll
        for (int mt = 0; mt < 4; ++mt) {
            const int r0 = wm * 64 + mt * 16 + gidr, r1 = r0 + 8;
            #pragma unroll
            for (int nt = 0; nt < 4; ++nt) {
                const int nn = n0 + wn * 32 + nt * 8 + 2 * t4;
                const float i0 = 1.f / csum[nt][0], i1 = 1.f / csum[nt][1];
                if (r0 < 112)
                    *(__half2*)(oh + (size_t)r0 * HW + nn) =
                        __floats2half2_rn(acc[mt][nt][0] * i0, acc[mt][nt][1] * i1);
                if (r1 < 112)
                    *(__half2*)(oh + (size_t)r1 * HW + nn) =
                        __floats2half2_rn(acc[mt][nt][2] * i0, acc[mt][nt][3] * i1);
            }
        }
        return;
    }

    // Standard epilogue
    #pragma unroll
    for (int mt = 0; mt < 4; ++mt) {
        const int ml = m0 + wm * 64 + mt * 16 + gidr;
        const int mh = ml + 8;
        float scl, ttl, sch, tth;
        if (BN) {
            scl = g_[ml] * rsqrtf(va_[ml] + 1e-5f);
            ttl = be_[ml] - me_[ml] * scl;
            sch = g_[mh] * rsqrtf(va_[mh] + 1e-5f);
            tth = be_[mh] - me_[mh] * sch;
        } else { scl = uscale; ttl = 0.f; sch = uscale; tth = 0.f; }
        #pragma unroll
        for (int nt = 0; nt < 4; ++nt) {
            const int nn = n0 + wn * 32 + nt * 8 + 2 * t4;
            float2 vl, vh;
            vl.x = acc[mt][nt][0] * scl + ttl;
            vl.y = acc[mt][nt][1] * scl + ttl;
            vh.x = acc[mt][nt][2] * sch + tth;
            vh.y = acc[mt][nt][3] * sch + tth;
            if (RELU) {
                vl.x = fmaxf(vl.x, 0.f); vl.y = fmaxf(vl.y, 0.f);
                vh.x = fmaxf(vh.x, 0.f); vh.y = fmaxf(vh.y, 0.f);
            }
            if (HALF_OUT) {
                __half* oh = (__half*)ouse + (size_t)b * ostr;
                *(__half2*)(oh + (size_t)ml * HW + nn) = __floats2half2_rn(vl.x, vl.y);
                *(__half2*)(oh + (size_t)mh * HW + nn) = __floats2half2_rn(vh.x, vh.y);
            } else {
                float* of = (float*)ouse + (size_t)b * ostr;
                if (RESID) {
                    const float* rp = resid + (size_t)b * ostr;
                    float2 rl = *(const float2*)(rp + (size_t)ml * HW + nn);
                    float2 rh = *(const float2*)(rp + (size_t)mh * HW + nn);
                    vl.x += rl.x; vl.y += rl.y; vh.x += rh.x; vh.y += rh.y;
                }
                *(float2*)(of + (size_t)ml * HW + nn) = vl;
                *(float2*)(of + (size_t)mh * HW + nn) = vh;
            }
        }
    }
}

// ---------------------------------------------------------------------------
// attn_out: y[b][c][n] = sum_s Vp[b][c][s] * P[b][s][n]  (K=112 single shot)
// ---------------------------------------------------------------------------
#define AO_ASTR 120
#define AO_SMEM (128*AO_ASTR*2 + 112*B_STRH*2)   // 61184

__global__ __launch_bounds__(256, 2) void attn_out_kernel(
    const __half* __restrict__ Vp, const __half* __restrict__ P, __half* __restrict__ y)
{
    extern __shared__ __align__(16) char smc[];
    const uint32_t sb = smem_u32(smc);
    const uint32_t sA = sb, sB = sb + 128*AO_ASTR*2;
    const int tid = threadIdx.x, lane = tid & 31, wid = tid >> 5;
    const int gidr = lane >> 2, t4 = lane & 3;
    const int wm = wid >> 2, wn = wid & 3;
    const int n0 = blockIdx.x * 128, c0 = blockIdx.y * 128, b = blockIdx.z;

    const __half* gA = Vp + (size_t)b * CV * 112 + (size_t)c0 * 112;
    const __half* gB = P + (size_t)b * 112 * HW + n0;

    #pragma unroll
    for (int it = 0; it < 7; ++it) {
        int idx = it * 256 + tid;
        int r = idx / 14, c = idx - r * 14;
        cpa16(sA + (uint32_t)(r * AO_ASTR + c * 8) * 2, gA + (size_t)r * 112 + c * 8);
    }
    #pragma unroll
    for (int it = 0; it < 7; ++it) {
        int idx = it * 256 + tid;
        int r = idx >> 4, c = idx & 15;
        cpa16(sB + (uint32_t)(r * B_STRH + c * 8) * 2, gB + (size_t)r * HW + c * 8);
    }
    asm volatile("cp.async.commit_group;\ncp.async.wait_group 0;" ::: "memory");
    __syncthreads();

    const int a_row = lane & 15, a_koff = (lane >> 4) * 8;
    const int b_krow = ((lane >> 3) & 1) * 8 + (lane & 7);
    const int b_noff = (lane >> 4) * 8;

    float acc[4][4][4];
    #pragma unroll
    for (int mt = 0; mt < 4; ++mt)
        #pragma unroll
        for (int nt = 0; nt < 4; ++nt)
            #pragma unroll
            for (int r = 0; r < 4; ++r) acc[mt][nt][r] = 0.f;

    #pragma unroll
    for (int s16 = 0; s16 < 7; ++s16) {
        const int kk = s16 * 16;
        uint32_t af[4][4], bf[4][2];
        #pragma unroll
        for (int mt = 0; mt < 4; ++mt) {
            int row = wm * 64 + mt * 16 + a_row;
            ldsm_x4(af[mt], sA + (uint32_t)(row * AO_ASTR + kk + a_koff) * 2);
        }
        #pragma unroll
        for (int nt2 = 0; nt2 < 2; ++nt2) {
            uint32_t r4[4];
            int ncol = wn * 32 + nt2 * 16 + b_noff;
            ldsm_x4_t(r4, sB + (uint32_t)((kk + b_krow) * B_STRH + ncol) * 2);
            bf[nt2*2][0] = r4[0]; bf[nt2*2][1] = r4[1];
            bf[nt2*2+1][0] = r4[2]; bf[nt2*2+1][1] = r4[3];
        }
        #pragma unroll
        for (int mt = 0; mt < 4; ++mt)
            #pragma unroll
            for (int nt = 0; nt < 4; ++nt)
                mma_f16(acc[mt][nt], af[mt], bf[nt]);
    }

    __half* yb = y + (size_t)b * CV * HW;
    #pragma unroll
    for (int mt = 0; mt < 4; ++mt) {
        const int ml = c0 + wm * 64 + mt * 16 + gidr;
        #pragma unroll
        for (int nt = 0; nt < 4; ++nt) {
            const int nn = n0 + wn * 32 + nt * 8 + 2 * t4;
            *(__half2*)(yb + (size_t)ml * HW + nn) =
                __floats2half2_rn(acc[mt][nt][0], acc[mt][nt][1]);
            *(__half2*)(yb + (size_t)(ml + 8) * HW + nn) =
                __floats2half2_rn(acc[mt][nt][2], acc[mt][nt][3]);
        }
    }
}

// ---------------------------------------------------------------------------
// All fp16 conversions in ONE launch: blocks [0,8192) convert x (v8),
// blocks [8192, 9216) convert the three weight matrices.
// ---------------------------------------------------------------------------
__global__ __launch_bounds__(256) void cvt_all_kernel(
    const float4* __restrict__ x, uint4* __restrict__ xh,
    const float* __restrict__ wq, const float* __restrict__ wv,
    const float* __restrict__ wo,
    __half* __restrict__ oq, __half* __restrict__ ov, __half* __restrict__ oo)
{
    if (blockIdx.x < 8192) {
        int i = blockIdx.x * 256 + threadIdx.x;
        float4 f0 = x[2*i], f1 = x[2*i+1];
        __half2 h0 = __floats2half2_rn(f0.x, f0.y);
        __half2 h1 = __floats2half2_rn(f0.z, f0.w);
        __half2 h2 = __floats2half2_rn(f1.x, f1.y);
        __half2 h3 = __floats2half2_rn(f1.z, f1.w);
        uint4 u;
        u.x = *(uint32_t*)&h0; u.y = *(uint32_t*)&h1;
        u.z = *(uint32_t*)&h2; u.w = *(uint32_t*)&h3;
        xh[i] = u;
    } else {
        int i = (blockIdx.x - 8192) * 256 + threadIdx.x;
        if (i < CK*CIN) oq[i] = __float2half_rn(wq[i]);
        if (i < CV*CIN) { ov[i] = __float2half_rn(wv[i]); oo[i] = __float2half_rn(wo[i]); }
    }
}

// ---------------------------------------------------------------------------
// PSP adaptive max pool, BOTH tensors in one launch. Plane in fp16 smem
// (stride 66), phase-1 vectorized with __hmax2. 2 planes per 256-thread block.
// ---------------------------------------------------------------------------
#define SPH_STR 66
#define RM_STR  65
#define QK_BLOCKS (BB*CK/2)          // 1024
#define PSP_BLOCKS (BB*(CK+CV)/2)    // 3072

__global__ __launch_bounds__(256) void psp_kernel(
    const __half* __restrict__ qk_in, __half* __restrict__ key_out,
    const __half* __restrict__ val_in, __half* __restrict__ val_out)
{
    __shared__ __align__(16) __half sph[2][64 * SPH_STR];
    __shared__ float rm[2][17 * RM_STR];
    __shared__ float s8v[2][64];
    const int pl = threadIdx.x >> 7;
    const int tid = threadIdx.x & 127;

    const __half* in; __half* out; int C, mode, bc;
    if (blockIdx.x < QK_BLOCKS) {
        in = qk_in; out = key_out; C = CK; mode = 1;
        bc = blockIdx.x * 2 + pl;
    } else {
        in = val_in; out = val_out; C = CV; mode = 0;
        bc = (blockIdx.x - QK_BLOCKS) * 2 + pl;
    }
    const int b = bc / C, c = bc - b * C;
    __half* spp = sph[pl];
    float* rmp = rm[pl];
    const __half* plane = in + (size_t)bc * 4096;

    for (int i = tid; i < 512; i += 128) {
        uint4 u = ((const uint4*)plane)[i];
        int row = i >> 3, col = (i & 7) * 8;
        uint32_t* d = (uint32_t*)(spp + row * SPH_STR + col);
        d[0] = u.x; d[1] = u.y; d[2] = u.z; d[3] = u.w;
    }
    __syncthreads();

    // Phase 1: per-(seg,row) column-range maxes, fp16 pairwise.
    const int cs[17] = {0,21,42, 0,10,21,32,42,53, 0,8,16,24,32,40,48,56};
    const int ce[17] = {22,43,64, 11,22,32,43,54,64, 8,16,24,32,40,48,56,64};
    for (int idx = tid; idx < 17 * 64; idx += 128) {
        int seg = idx >> 6, row = idx & 63;
        const __half* rp = spp + row * SPH_STR;
        int a = cs[seg], bnd = ce[seg];
        float m = -3.402823e38f;
        if (a & 1) { m = __half2float(rp[a]); ++a; }
        if (bnd & 1) { m = fmaxf(m, __half2float(rp[bnd - 1])); --bnd; }
        __half2 m2 = __floats2half2_rn(-65504.f, -65504.f);
        const __half2* rp2 = (const __half2*)rp;
        for (int c2 = a >> 1; c2 < (bnd >> 1); ++c2) m2 = __hmax2(m2, rp2[c2]);
        m = fmaxf(m, fmaxf(__low2float(m2), __high2float(m2)));
        rmp[seg * RM_STR + row] = m;
    }
    __syncthreads();

    // Phase 2: cells
    float m = -3.402823e38f;
    int cell = -1;
    if (tid < 64) {                        // s=8
        int i = tid >> 3, j = tid & 7;
        for (int r = i * 8; r < i * 8 + 8; ++r) m = fmaxf(m, rmp[(9 + j) * RM_STR + r]);
        s8v[pl][tid] = m; cell = 46 + tid;
    } else if (tid < 100) {                // s=6
        const int st[6] = {0,10,21,32,42,53}, en[6] = {11,22,32,43,54,64};
        int t = tid - 64, i = t / 6, j = t - i * 6;
        for (int r = st[i]; r < en[i]; ++r) m = fmaxf(m, rmp[(3 + j) * RM_STR + r]);
        cell = 10 + t;
    } else if (tid < 109) {                // s=3
        const int st[3] = {0,21,42}, en[3] = {22,43,64};
        int t = tid - 100, i = t / 3, j = t - i * 3;
        for (int r = st[i]; r < en[i]; ++r) m = fmaxf(m, rmp[j * RM_STR + r]);
        cell = 1 + t;
    }
    if (cell >= 0) {
        size_t o = mode ? ((size_t)(b * 128 + cell) * C + c)
                        : ((size_t)bc * 112 + cell);
        out[o] = __float2half_rn(m);
    }
    __syncthreads();
    if (tid == 0) {                        // s=1 from the 64 exact 8x8 cells
        float mm = s8v[pl][0];
        for (int i = 1; i < 64; ++i) mm = fmaxf(mm, s8v[pl][i]);
        size_t o = mode ? ((size_t)(b * 128) * C + c) : ((size_t)bc * 112);
        out[o] = __float2half_rn(mm);
    }
}

// ---------------------------------------------------------------------------
extern "C" void kernel_launch(void* const* d_in, const int* in_sizes, int n_in,
                              void* d_out, int out_size)
{
    const float* x        = (const float*)d_in[0];
    const float* qk_w     = (const float*)d_in[1];
    const float* qk_gamma = (const float*)d_in[2];
    const float* qk_beta  = (const float*)d_in[3];
    const float* qk_mean  = (const float*)d_in[4];
    const float* qk_var   = (const float*)d_in[5];
    const float* v_w      = (const float*)d_in[6];
    const float* v_gamma  = (const float*)d_in[7];
    const float* v_beta   = (const float*)d_in[8];
    const float* v_mean   = (const float*)d_in[9];
    const float* v_var    = (const float*)d_in[10];
    const float* out_w    = (const float*)d_in[11];
    const float* o_gamma  = (const float*)d_in[12];
    const float* o_beta   = (const float*)d_in[13];
    const float* o_mean   = (const float*)d_in[14];
    const float* o_var    = (const float*)d_in[15];
    float* out = (float*)d_out;

    __half *xh, *qkh, *valh, *keyh, *vpsp, *ph, *yh, *wq, *wv, *wo;
    cudaGetSymbolAddress((void**)&xh,   g_xh);
    cudaGetSymbolAddress((void**)&qkh,  g_qkh);
    cudaGetSymbolAddress((void**)&valh, g_valh);
    cudaGetSymbolAddress((void**)&keyh, g_keyh);
    cudaGetSymbolAddress((void**)&vpsp, g_vpsp);
    cudaGetSymbolAddress((void**)&ph,   g_ph);
    cudaGetSymbolAddress((void**)&yh,   g_yh);
    cudaGetSymbolAddress((void**)&wq,   g_wq);
    cudaGetSymbolAddress((void**)&wv,   g_wv);
    cudaGetSymbolAddress((void**)&wo,   g_wo);

    cudaFuncSetAttribute(gemm_kernel<true, true, true, false, true, false>,
                         cudaFuncAttributeMaxDynamicSharedMemorySize, GEMM_SMEM);
    cudaFuncSetAttribute(gemm_kernel<false, false, false, false, true, true>,
                         cudaFuncAttributeMaxDynamicSharedMemorySize, GEMM_SMEM);
    cudaFuncSetAttribute(gemm_kernel<false, true, false, true, false, false>,
                         cudaFuncAttributeMaxDynamicSharedMemorySize, GEMM_SMEM);
    cudaFuncSetAttribute(attn_out_kernel,
                         cudaFuncAttributeMaxDynamicSharedMemorySize, AO_SMEM);

    // 0) all fp16 conversions, one launch
    cvt_all_kernel<<<8192 + 1024, 256>>>(
        (const float4*)x, (uint4*)xh, qk_w, v_w, out_w, wq, wv, wo);

    // 1+2) fused: qk = relu(bn(conv(x,wq))), val = relu(bn(conv(x,wv)))
    gemm_kernel<true, true, true, false, true, false><<<dim3(32, 6, BB), 256, GEMM_SMEM>>>(
        wq, 0, xh, (size_t)CIN*HW, qk_gamma, qk_beta, qk_mean, qk_var,
        1.f, nullptr, qkh, (size_t)CK*HW, CIN,
        wv, v_gamma, v_beta, v_mean, v_var, valh, (size_t)CV*HW);
    // 3) key = psp(qk) [s][c]  AND  value = psp(val) [c][s]  (one launch)
    psp_kernel<<<PSP_BLOCKS, 256>>>(qkh, keyh, valh, vpsp);
    // 4) P = softmax_s( (key @ qk) / 16 )  -- softmax fused into GEMM epilogue
    gemm_kernel<false, false, false, false, true, true><<<dim3(32, 1, BB), 256, GEMM_SMEM>>>(
        keyh, (size_t)128*CK, qkh, (size_t)CK*HW, nullptr, nullptr, nullptr, nullptr,
        0.0625f, nullptr, ph, (size_t)112*HW, CK,
        nullptr, nullptr, nullptr, nullptr, nullptr, nullptr, 0);
    // 5) y[c][n] = value[c][s] @ p[s][n]
    attn_out_kernel<<<dim3(32, 4, BB), 256, AO_SMEM>>>(vpsp, ph, yh);
    // 6) out = x + bn(conv(y, wo))
    gemm_kernel<false, true, false, true, false, false><<<dim3(32, 4, BB), 256, GEMM_SMEM>>>(
        wo, 0, yh, (size_t)CV*HW, o_gamma, o_beta, o_mean, o_var,
        1.f, x, out, (size_t)CIN*HW, CV,
        nullptr, nullptr, nullptr, nullptr, nullptr, nullptr, 0);
}

// round 11
// speedup vs baseline: 1.4483x; 1.4483x over previous
#include <cuda_runtime.h>
#include <cuda_fp16.h>
#include <cstdint>
#include <math.h>

#define BB   8
#define CIN  512
#define CK   256
#define CV   512
#define HW   4096
#define SS   110

// Scratch (__device__ globals are zero-initialized; pad regions never written
// stay zero -> free zero-padding).
__device__ __align__(16) __half g_xh    [BB*CIN*HW];    // [b][k][n]
__device__ __align__(16) __half g_qkh   [BB*CK*HW];     // [b][c][n]
__device__ __align__(16) __half g_valh  [BB*CV*HW];     // [b][c][n]
__device__ __align__(16) __half g_keyh  [BB*128*CK];    // [b][s(pad128)][c]
__device__ __align__(16) __half g_vpsp  [BB*CV*112];    // [b][c][s(pad112)]
__device__ __align__(16) __half g_ph    [BB*112*HW];    // [b][s(pad112)][n]
__device__ __align__(16) __half g_yh    [BB*CV*HW];     // [b][c][n]
__device__ __align__(16) __half g_wq    [CK*CIN];
__device__ __align__(16) __half g_wv    [CV*CIN];
__device__ __align__(16) __half g_wo    [CIN*CV];

// ---------------------------------------------------------------------------
__device__ __forceinline__ uint32_t smem_u32(const void* p) {
    uint32_t a;
    asm("{ .reg .u64 t; cvta.to.shared.u64 t, %1; cvt.u32.u64 %0, t; }" : "=r"(a) : "l"(p));
    return a;
}
__device__ __forceinline__ void ldsm_x4(uint32_t* r, uint32_t addr) {
    asm volatile("ldmatrix.sync.aligned.m8n8.x4.shared.b16 {%0,%1,%2,%3}, [%4];"
        : "=r"(r[0]), "=r"(r[1]), "=r"(r[2]), "=r"(r[3]) : "r"(addr));
}
__device__ __forceinline__ void ldsm_x4_t(uint32_t* r, uint32_t addr) {
    asm volatile("ldmatrix.sync.aligned.m8n8.x4.trans.shared.b16 {%0,%1,%2,%3}, [%4];"
        : "=r"(r[0]), "=r"(r[1]), "=r"(r[2]), "=r"(r[3]) : "r"(addr));
}
__device__ __forceinline__ void mma_f16(float* c, const uint32_t* a, const uint32_t* b) {
    asm volatile(
        "mma.sync.aligned.m16n8k16.row.col.f32.f16.f16.f32 "
        "{%0,%1,%2,%3}, {%4,%5,%6,%7}, {%8,%9}, {%0,%1,%2,%3};"
        : "+f"(c[0]), "+f"(c[1]), "+f"(c[2]), "+f"(c[3])
        : "r"(a[0]), "r"(a[1]), "r"(a[2]), "r"(a[3]), "r"(b[0]), "r"(b[1]));
}
__device__ __forceinline__ void cpa16(uint32_t dst, const void* src) {
    asm volatile("cp.async.cg.shared.global [%0], [%1], 16;" :: "r"(dst), "l"(src));
}

// ---------------------------------------------------------------------------
// Generalized GEMM: out[b,m,n] = epi( sum_k A[m,k] * B[b,k,n] )
// CTA 128m x 128n, 8 warps (2x4), warp 64x32. K staged 32, 4-stage pipeline.
// (75.8KB smem/CTA -> 2 CTAs/SM resident; proven best config.)
// FUSED: blockIdx.y<2 -> branch 1, else branch 2.
// SOFTMAX: epilogue computes column-softmax over m (valid rows < SS) and
//          writes fp16 probabilities directly (rows [SS,112) written 0).
// ---------------------------------------------------------------------------
#define A_STRH 40
#define B_STRH 136
#define A_STG  (128*A_STRH*2)              // 10240 B
#define B_STG  (32*B_STRH*2)               // 8704 B
#define STG    (A_STG + B_STG)             // 18944 B
#define NSTAGE 4
#define GEMM_SMEM (NSTAGE*STG)             // 75776 B

template<bool FUSED, bool BN, bool RELU, bool RESID, bool HALF_OUT, bool SOFTMAX>
__global__ __launch_bounds__(256, 2) void gemm_kernel(
    const __half* __restrict__ A, size_t a_bstride,
    const __half* __restrict__ Bm, size_t b_bstride,
    const float* __restrict__ gamma, const float* __restrict__ beta,
    const float* __restrict__ mean,  const float* __restrict__ var,
    float uscale,
    const float* __restrict__ resid,
    void* __restrict__ outp, size_t o_bstride,
    int Ktot,
    // FUSED branch-2 args
    const __half* __restrict__ A2,
    const float* __restrict__ gamma2, const float* __restrict__ beta2,
    const float* __restrict__ mean2,  const float* __restrict__ var2,
    void* __restrict__ outp2, size_t o_bstride2)
{
    extern __shared__ __align__(16) char smc[];
    const uint32_t sb = smem_u32(smc);
    const int tid = threadIdx.x, lane = tid & 31, wid = tid >> 5;
    const int gidr = lane >> 2, t4 = lane & 3;
    const int wm = wid >> 2, wn = wid & 3;
    const int n0 = blockIdx.x * 128, b = blockIdx.z;
    const int NK = Ktot >> 5;

    int m0 = blockIdx.y * 128;
    const __half* Ause = A;
    const float *g_ = gamma, *be_ = beta, *me_ = mean, *va_ = var;
    void* ouse = outp;
    size_t ostr = o_bstride;
    if (FUSED && blockIdx.y >= 2) {
        m0 = (blockIdx.y - 2) * 128;
        Ause = A2; g_ = gamma2; be_ = beta2; me_ = mean2; va_ = var2;
        ouse = outp2; ostr = o_bstride2;
    }

    const __half* gA = Ause + (size_t)b * a_bstride + (size_t)m0 * Ktot;
    const __half* gB = Bm + (size_t)b * b_bstride + n0;

    auto load_stage = [&](int s) {
        const uint32_t base = sb + (uint32_t)(s & (NSTAGE-1)) * STG;
        #pragma unroll
        for (int it = 0; it < 2; ++it) {            // A: 128r x 4 chunks
            int idx = it * 256 + tid;
            int r = idx >> 2, c = idx & 3;
            cpa16(base + (uint32_t)(r * A_STRH + c * 8) * 2,
                  gA + (size_t)r * Ktot + s * 32 + c * 8);
        }
        #pragma unroll
        for (int it = 0; it < 2; ++it) {            // B: 32r x 16 chunks
            int idx = it * 256 + tid;
            int r = idx >> 4, c = idx & 15;
            cpa16(base + A_STG + (uint32_t)(r * B_STRH + c * 8) * 2,
                  gB + (size_t)(s * 32 + r) * HW + c * 8);
        }
        asm volatile("cp.async.commit_group;" ::: "memory");
    };

    float acc[4][4][4];
    #pragma unroll
    for (int mt = 0; mt < 4; ++mt)
        #pragma unroll
        for (int nt = 0; nt < 4; ++nt)
            #pragma unroll
            for (int r = 0; r < 4; ++r) acc[mt][nt][r] = 0.f;

    for (int s = 0; s < NSTAGE - 1 && s < NK; ++s) load_stage(s);
    asm volatile("cp.async.wait_group 2;" ::: "memory");
    __syncthreads();

    const int a_row = lane & 15, a_koff = (lane >> 4) * 8;
    const int b_krow = ((lane >> 3) & 1) * 8 + (lane & 7);
    const int b_noff = (lane >> 4) * 8;

    for (int kt = 0; kt < NK; ++kt) {
        if (kt + NSTAGE - 1 < NK) load_stage(kt + NSTAGE - 1);
        else asm volatile("cp.async.commit_group;" ::: "memory");

        const uint32_t sA = sb + (uint32_t)(kt & (NSTAGE-1)) * STG;
        const uint32_t sB = sA + A_STG;
        #pragma unroll
        for (int s16 = 0; s16 < 2; ++s16) {
            const int kk = s16 * 16;
            uint32_t af[4][4], bf[4][2];
            #pragma unroll
            for (int mt = 0; mt < 4; ++mt) {
                int row = wm * 64 + mt * 16 + a_row;
                ldsm_x4(af[mt], sA + (uint32_t)(row * A_STRH + kk + a_koff) * 2);
            }
            #pragma unroll
            for (int nt2 = 0; nt2 < 2; ++nt2) {
                uint32_t r4[4];
                int ncol = wn * 32 + nt2 * 16 + b_noff;
                ldsm_x4_t(r4, sB + (uint32_t)((kk + b_krow) * B_STRH + ncol) * 2);
                bf[nt2*2][0] = r4[0]; bf[nt2*2][1] = r4[1];
                bf[nt2*2+1][0] = r4[2]; bf[nt2*2+1][1] = r4[3];
            }
            #pragma unroll
            for (int mt = 0; mt < 4; ++mt)
                #pragma unroll
                for (int nt = 0; nt < 4; ++nt)
                    mma_f16(acc[mt][nt], af[mt], bf[nt]);
        }
        asm volatile("cp.async.wait_group 2;" ::: "memory");
        __syncthreads();
    }

    if (SOFTMAX) {
        // Column softmax over m rows (m0==0, grid.y==1). Valid rows: < SS.
        float* red = (float*)smc;              // reuse stage smem (512 floats)
        float cmax[4][2], csum[4][2];
        #pragma unroll
        for (int nt = 0; nt < 4; ++nt) { cmax[nt][0] = -3.4e38f; cmax[nt][1] = -3.4e38f; }
        #pragma unroll
        for (int mt = 0; mt < 4; ++mt) {
            const int r0 = wm * 64 + mt * 16 + gidr, r1 = r0 + 8;
            #pragma unroll
            for (int nt = 0; nt < 4; ++nt) {
                #pragma unroll
                for (int r = 0; r < 4; ++r) acc[mt][nt][r] *= uscale;
                if (r0 < SS) {
                    cmax[nt][0] = fmaxf(cmax[nt][0], acc[mt][nt][0]);
                    cmax[nt][1] = fmaxf(cmax[nt][1], acc[mt][nt][1]);
                }
                if (r1 < SS) {
                    cmax[nt][0] = fmaxf(cmax[nt][0], acc[mt][nt][2]);
                    cmax[nt][1] = fmaxf(cmax[nt][1], acc[mt][nt][3]);
                }
            }
        }
        #pragma unroll
        for (int nt = 0; nt < 4; ++nt)
            #pragma unroll
            for (int j = 0; j < 2; ++j) {
                float v = cmax[nt][j];
                v = fmaxf(v, __shfl_xor_sync(0xffffffffu, v, 4));
                v = fmaxf(v, __shfl_xor_sync(0xffffffffu, v, 8));
                v = fmaxf(v, __shfl_xor_sync(0xffffffffu, v, 16));
                cmax[nt][j] = v;
            }
        if (gidr == 0)
            #pragma unroll
            for (int nt = 0; nt < 4; ++nt)
                #pragma unroll
                for (int j = 0; j < 2; ++j)
                    red[wm*128 + wn*32 + nt*8 + 2*t4 + j] = cmax[nt][j];
        __syncthreads();
        #pragma unroll
        for (int nt = 0; nt < 4; ++nt)
            #pragma unroll
            for (int j = 0; j < 2; ++j)
                cmax[nt][j] = fmaxf(cmax[nt][j], red[(wm^1)*128 + wn*32 + nt*8 + 2*t4 + j]);

        #pragma unroll
        for (int nt = 0; nt < 4; ++nt) { csum[nt][0] = 0.f; csum[nt][1] = 0.f; }
        #pragma unroll
        for (int mt = 0; mt < 4; ++mt) {
            const int r0 = wm * 64 + mt * 16 + gidr, r1 = r0 + 8;
            #pragma unroll
            for (int nt = 0; nt < 4; ++nt) {
                float e0 = (r0 < SS) ? __expf(acc[mt][nt][0] - cmax[nt][0]) : 0.f;
                float e1 = (r0 < SS) ? __expf(acc[mt][nt][1] - cmax[nt][1]) : 0.f;
                float e2 = (r1 < SS) ? __expf(acc[mt][nt][2] - cmax[nt][0]) : 0.f;
                float e3 = (r1 < SS) ? __expf(acc[mt][nt][3] - cmax[nt][1]) : 0.f;
                acc[mt][nt][0] = e0; acc[mt][nt][1] = e1;
                acc[mt][nt][2] = e2; acc[mt][nt][3] = e3;
                csum[nt][0] += e0 + e2; csum[nt][1] += e1 + e3;
            }
        }
        #pragma unroll
        for (int nt = 0; nt < 4; ++nt)
            #pragma unroll
            for (int j = 0; j < 2; ++j) {
                float v = csum[nt][j];
                v += __shfl_xor_sync(0xffffffffu, v, 4);
                v += __shfl_xor_sync(0xffffffffu, v, 8);
                v += __shfl_xor_sync(0xffffffffu, v, 16);
                csum[nt][j] = v;
            }
        if (gidr == 0)
            #pragma unroll
            for (int nt = 0; nt < 4; ++nt)
                #pragma unroll
                for (int j = 0; j < 2; ++j)
                    red[256 + wm*128 + wn*32 + nt*8 + 2*t4 + j] = csum[nt][j];
        __syncthreads();
        #pragma unroll
        for (int nt = 0; nt < 4; ++nt)
            #pragma unroll
            for (int j = 0; j < 2; ++j)
                csum[nt][j] += red[256 + (wm^1)*128 + wn*32 + nt*8 + 2*t4 + j];

        __half* oh = (__half*)ouse + (size_t)b * ostr;
        #pragma unroll
        for (int mt = 0; mt < 4; ++mt) {
            const int r0 = wm * 64 + mt * 16 + gidr, r1 = r0 + 8;
            #pragma unroll
            for (int nt = 0; nt < 4; ++nt) {
                const int nn = n0 + wn * 32 + nt * 8 + 2 * t4;
                const float i0 = 1.f / csum[nt][0], i1 = 1.f / csum[nt][1];
                if (r0 < 112)
                    *(__half2*)(oh + (size_t)r0 * HW + nn) =
                        __floats2half2_rn(acc[mt][nt][0] * i0, acc[mt][nt][1] * i1);
                if (r1 < 112)
                    *(__half2*)(oh + (size_t)r1 * HW + nn) =
                        __floats2half2_rn(acc[mt][nt][2] * i0, acc[mt][nt][3] * i1);
            }
        }
        return;
    }

    // Standard epilogue
    #pragma unroll
    for (int mt = 0; mt < 4; ++mt) {
        const int ml = m0 + wm * 64 + mt * 16 + gidr;
        const int mh = ml + 8;
        float scl, ttl, sch, tth;
        if (BN) {
            scl = g_[ml] * rsqrtf(va_[ml] + 1e-5f);
            ttl = be_[ml] - me_[ml] * scl;
            sch = g_[mh] * rsqrtf(va_[mh] + 1e-5f);
            tth = be_[mh] - me_[mh] * sch;
        } else { scl = uscale; ttl = 0.f; sch = uscale; tth = 0.f; }
        #pragma unroll
        for (int nt = 0; nt < 4; ++nt) {
            const int nn = n0 + wn * 32 + nt * 8 + 2 * t4;
            float2 vl, vh;
            vl.x = acc[mt][nt][0] * scl + ttl;
            vl.y = acc[mt][nt][1] * scl + ttl;
            vh.x = acc[mt][nt][2] * sch + tth;
            vh.y = acc[mt][nt][3] * sch + tth;
            if (RELU) {
                vl.x = fmaxf(vl.x, 0.f); vl.y = fmaxf(vl.y, 0.f);
                vh.x = fmaxf(vh.x, 0.f); vh.y = fmaxf(vh.y, 0.f);
            }
            if (HALF_OUT) {
                __half* oh = (__half*)ouse + (size_t)b * ostr;
                *(__half2*)(oh + (size_t)ml * HW + nn) = __floats2half2_rn(vl.x, vl.y);
                *(__half2*)(oh + (size_t)mh * HW + nn) = __floats2half2_rn(vh.x, vh.y);
            } else {
                float* of = (float*)ouse + (size_t)b * ostr;
                if (RESID) {
                    const float* rp = resid + (size_t)b * ostr;
                    float2 rl = *(const float2*)(rp + (size_t)ml * HW + nn);
                    float2 rh = *(const float2*)(rp + (size_t)mh * HW + nn);
                    vl.x += rl.x; vl.y += rl.y; vh.x += rh.x; vh.y += rh.y;
                }
                *(float2*)(of + (size_t)ml * HW + nn) = vl;
                *(float2*)(of + (size_t)mh * HW + nn) = vh;
            }
        }
    }
}

// ---------------------------------------------------------------------------
// attn_out: y[b][c][n] = sum_s Vp[b][c][s] * P[b][s][n]  (K=112 single shot)
// ---------------------------------------------------------------------------
#define AO_ASTR 120
#define AO_SMEM (128*AO_ASTR*2 + 112*B_STRH*2)   // 61184

__global__ __launch_bounds__(256, 2) void attn_out_kernel(
    const __half* __restrict__ Vp, const __half* __restrict__ P, __half* __restrict__ y)
{
    extern __shared__ __align__(16) char smc[];
    const uint32_t sb = smem_u32(smc);
    const uint32_t sA = sb, sB = sb + 128*AO_ASTR*2;
    const int tid = threadIdx.x, lane = tid & 31, wid = tid >> 5;
    const int gidr = lane >> 2, t4 = lane & 3;
    const int wm = wid >> 2, wn = wid & 3;
    const int n0 = blockIdx.x * 128, c0 = blockIdx.y * 128, b = blockIdx.z;

    const __half* gA = Vp + (size_t)b * CV * 112 + (size_t)c0 * 112;
    const __half* gB = P + (size_t)b * 112 * HW + n0;

    #pragma unroll
    for (int it = 0; it < 7; ++it) {
        int idx = it * 256 + tid;
        int r = idx / 14, c = idx - r * 14;
        cpa16(sA + (uint32_t)(r * AO_ASTR + c * 8) * 2, gA + (size_t)r * 112 + c * 8);
    }
    #pragma unroll
    for (int it = 0; it < 7; ++it) {
        int idx = it * 256 + tid;
        int r = idx >> 4, c = idx & 15;
        cpa16(sB + (uint32_t)(r * B_STRH + c * 8) * 2, gB + (size_t)r * HW + c * 8);
    }
    asm volatile("cp.async.commit_group;\ncp.async.wait_group 0;" ::: "memory");
    __syncthreads();

    const int a_row = lane & 15, a_koff = (lane >> 4) * 8;
    const int b_krow = ((lane >> 3) & 1) * 8 + (lane & 7);
    const int b_noff = (lane >> 4) * 8;

    float acc[4][4][4];
    #pragma unroll
    for (int mt = 0; mt < 4; ++mt)
        #pragma unroll
        for (int nt = 0; nt < 4; ++nt)
            #pragma unroll
            for (int r = 0; r < 4; ++r) acc[mt][nt][r] = 0.f;

    #pragma unroll
    for (int s16 = 0; s16 < 7; ++s16) {
        const int kk = s16 * 16;
        uint32_t af[4][4], bf[4][2];
        #pragma unroll
        for (int mt = 0; mt < 4; ++mt) {
            int row = wm * 64 + mt * 16 + a_row;
            ldsm_x4(af[mt], sA + (uint32_t)(row * AO_ASTR + kk + a_koff) * 2);
        }
        #pragma unroll
        for (int nt2 = 0; nt2 < 2; ++nt2) {
            uint32_t r4[4];
            int ncol = wn * 32 + nt2 * 16 + b_noff;
            ldsm_x4_t(r4, sB + (uint32_t)((kk + b_krow) * B_STRH + ncol) * 2);
            bf[nt2*2][0] = r4[0]; bf[nt2*2][1] = r4[1];
            bf[nt2*2+1][0] = r4[2]; bf[nt2*2+1][1] = r4[3];
        }
        #pragma unroll
        for (int mt = 0; mt < 4; ++mt)
            #pragma unroll
            for (int nt = 0; nt < 4; ++nt)
                mma_f16(acc[mt][nt], af[mt], bf[nt]);
    }

    __half* yb = y + (size_t)b * CV * HW;
    #pragma unroll
    for (int mt = 0; mt < 4; ++mt) {
        const int ml = c0 + wm * 64 + mt * 16 + gidr;
        #pragma unroll
        for (int nt = 0; nt < 4; ++nt) {
            const int nn = n0 + wn * 32 + nt * 8 + 2 * t4;
            *(__half2*)(yb + (size_t)ml * HW + nn) =
                __floats2half2_rn(acc[mt][nt][0], acc[mt][nt][1]);
            *(__half2*)(yb + (size_t)(ml + 8) * HW + nn) =
                __floats2half2_rn(acc[mt][nt][2], acc[mt][nt][3]);
        }
    }
}

// ---------------------------------------------------------------------------
// All fp16 conversions in ONE launch. x-blocks process TWO uint4 pairs each
// (MLP 4) for higher DRAM utilization; weight blocks follow.
// ---------------------------------------------------------------------------
#define XHALF (BB*CIN*HW/16)      // 1048576 -> 4096 blocks of 256
__global__ __launch_bounds__(256) void cvt_all_kernel(
    const float4* __restrict__ x, uint4* __restrict__ xh,
    const float* __restrict__ wq, const float* __restrict__ wv,
    const float* __restrict__ wo,
    __half* __restrict__ oq, __half* __restrict__ ov, __half* __restrict__ oo)
{
    if (blockIdx.x < 4096) {
        int i = blockIdx.x * 256 + threadIdx.x;
        float4 a0 = x[2*i], a1 = x[2*i+1];
        float4 b0 = x[2*(i + XHALF)], b1 = x[2*(i + XHALF)+1];
        __half2 h0 = __floats2half2_rn(a0.x, a0.y), h1 = __floats2half2_rn(a0.z, a0.w);
        __half2 h2 = __floats2half2_rn(a1.x, a1.y), h3 = __floats2half2_rn(a1.z, a1.w);
        __half2 g0 = __floats2half2_rn(b0.x, b0.y), g1 = __floats2half2_rn(b0.z, b0.w);
        __half2 g2 = __floats2half2_rn(b1.x, b1.y), g3 = __floats2half2_rn(b1.z, b1.w);
        uint4 u, v;
        u.x = *(uint32_t*)&h0; u.y = *(uint32_t*)&h1;
        u.z = *(uint32_t*)&h2; u.w = *(uint32_t*)&h3;
        v.x = *(uint32_t*)&g0; v.y = *(uint32_t*)&g1;
        v.z = *(uint32_t*)&g2; v.w = *(uint32_t*)&g3;
        xh[i] = u;
        xh[i + XHALF] = v;
    } else {
        int i = (blockIdx.x - 4096) * 256 + threadIdx.x;
        if (i < CK*CIN) oq[i] = __float2half_rn(wq[i]);
        if (i < CV*CIN) { ov[i] = __float2half_rn(wv[i]); oo[i] = __float2half_rn(wo[i]); }
    }
}

// ---------------------------------------------------------------------------
// PSP adaptive max pool, BOTH tensors in one launch. Plane in fp16 smem
// (stride 66), phase-1 vectorized with __hmax2. 2 planes per 256-thread block.
// ---------------------------------------------------------------------------
#define SPH_STR 66
#define RM_STR  65
#define QK_BLOCKS (BB*CK/2)          // 1024
#define PSP_BLOCKS (BB*(CK+CV)/2)    // 3072

__global__ __launch_bounds__(256) void psp_kernel(
    const __half* __restrict__ qk_in, __half* __restrict__ key_out,
    const __half* __restrict__ val_in, __half* __restrict__ val_out)
{
    __shared__ __align__(16) __half sph[2][64 * SPH_STR];
    __shared__ float rm[2][17 * RM_STR];
    __shared__ float s8v[2][64];
    const int pl = threadIdx.x >> 7;
    const int tid = threadIdx.x & 127;

    const __half* in; __half* out; int C, mode, bc;
    if (blockIdx.x < QK_BLOCKS) {
        in = qk_in; out = key_out; C = CK; mode = 1;
        bc = blockIdx.x * 2 + pl;
    } else {
        in = val_in; out = val_out; C = CV; mode = 0;
        bc = (blockIdx.x - QK_BLOCKS) * 2 + pl;
    }
    const int b = bc / C, c = bc - b * C;
    __half* spp = sph[pl];
    float* rmp = rm[pl];
    const __half* plane = in + (size_t)bc * 4096;

    for (int i = tid; i < 512; i += 128) {
        uint4 u = ((const uint4*)plane)[i];
        int row = i >> 3, col = (i & 7) * 8;
        uint32_t* d = (uint32_t*)(spp + row * SPH_STR + col);
        d[0] = u.x; d[1] = u.y; d[2] = u.z; d[3] = u.w;
    }
    __syncthreads();

    // Phase 1: per-(seg,row) column-range maxes, fp16 pairwise.
    const int cs[17] = {0,21,42, 0,10,21,32,42,53, 0,8,16,24,32,40,48,56};
    const int ce[17] = {22,43,64, 11,22,32,43,54,64, 8,16,24,32,40,48,56,64};
    for (int idx = tid; idx < 17 * 64; idx += 128) {
        int seg = idx >> 6, row = idx & 63;
        const __half* rp = spp + row * SPH_STR;
        int a = cs[seg], bnd = ce[seg];
        float m = -3.402823e38f;
        if (a & 1) { m = __half2float(rp[a]); ++a; }
        if (bnd & 1) { m = fmaxf(m, __half2float(rp[bnd - 1])); --bnd; }
        __half2 m2 = __floats2half2_rn(-65504.f, -65504.f);
        const __half2* rp2 = (const __half2*)rp;
        for (int c2 = a >> 1; c2 < (bnd >> 1); ++c2) m2 = __hmax2(m2, rp2[c2]);
        m = fmaxf(m, fmaxf(__low2float(m2), __high2float(m2)));
        rmp[seg * RM_STR + row] = m;
    }
    __syncthreads();

    // Phase 2: cells
    float m = -3.402823e38f;
    int cell = -1;
    if (tid < 64) {                        // s=8
        int i = tid >> 3, j = tid & 7;
        for (int r = i * 8; r < i * 8 + 8; ++r) m = fmaxf(m, rmp[(9 + j) * RM_STR + r]);
        s8v[pl][tid] = m; cell = 46 + tid;
    } else if (tid < 100) {                // s=6
        const int st[6] = {0,10,21,32,42,53}, en[6] = {11,22,32,43,54,64};
        int t = tid - 64, i = t / 6, j = t - i * 6;
        for (int r = st[i]; r < en[i]; ++r) m = fmaxf(m, rmp[(3 + j) * RM_STR + r]);
        cell = 10 + t;
    } else if (tid < 109) {                // s=3
        const int st[3] = {0,21,42}, en[3] = {22,43,64};
        int t = tid - 100, i = t / 3, j = t - i * 3;
        for (int r = st[i]; r < en[i]; ++r) m = fmaxf(m, rmp[j * RM_STR + r]);
        cell = 1 + t;
    }
    if (cell >= 0) {
        size_t o = mode ? ((size_t)(b * 128 + cell) * C + c)
                        : ((size_t)bc * 112 + cell);
        out[o] = __float2half_rn(m);
    }
    __syncthreads();
    if (tid == 0) {                        // s=1 from the 64 exact 8x8 cells
        float mm = s8v[pl][0];
        for (int i = 1; i < 64; ++i) mm = fmaxf(mm, s8v[pl][i]);
        size_t o = mode ? ((size_t)(b * 128) * C + c) : ((size_t)bc * 112);
        out[o] = __float2half_rn(mm);
    }
}

// ---------------------------------------------------------------------------
extern "C" void kernel_launch(void* const* d_in, const int* in_sizes, int n_in,
                              void* d_out, int out_size)
{
    const float* x        = (const float*)d_in[0];
    const float* qk_w     = (const float*)d_in[1];
    const float* qk_gamma = (const float*)d_in[2];
    const float* qk_beta  = (const float*)d_in[3];
    const float* qk_mean  = (const float*)d_in[4];
    const float* qk_var   = (const float*)d_in[5];
    const float* v_w      = (const float*)d_in[6];
    const float* v_gamma  = (const float*)d_in[7];
    const float* v_beta   = (const float*)d_in[8];
    const float* v_mean   = (const float*)d_in[9];
    const float* v_var    = (const float*)d_in[10];
    const float* out_w    = (const float*)d_in[11];
    const float* o_gamma  = (const float*)d_in[12];
    const float* o_beta   = (const float*)d_in[13];
    const float* o_mean   = (const float*)d_in[14];
    const float* o_var    = (const float*)d_in[15];
    float* out = (float*)d_out;

    __half *xh, *qkh, *valh, *keyh, *vpsp, *ph, *yh, *wq, *wv, *wo;
    cudaGetSymbolAddress((void**)&xh,   g_xh);
    cudaGetSymbolAddress((void**)&qkh,  g_qkh);
    cudaGetSymbolAddress((void**)&valh, g_valh);
    cudaGetSymbolAddress((void**)&keyh, g_keyh);
    cudaGetSymbolAddress((void**)&vpsp, g_vpsp);
    cudaGetSymbolAddress((void**)&ph,   g_ph);
    cudaGetSymbolAddress((void**)&yh,   g_yh);
    cudaGetSymbolAddress((void**)&wq,   g_wq);
    cudaGetSymbolAddress((void**)&wv,   g_wv);
    cudaGetSymbolAddress((void**)&wo,   g_wo);

    cudaFuncSetAttribute(gemm_kernel<true, true, true, false, true, false>,
                         cudaFuncAttributeMaxDynamicSharedMemorySize, GEMM_SMEM);
    cudaFuncSetAttribute(gemm_kernel<false, false, false, false, true, true>,
                         cudaFuncAttributeMaxDynamicSharedMemorySize, GEMM_SMEM);
    cudaFuncSetAttribute(gemm_kernel<false, true, false, true, false, false>,
                         cudaFuncAttributeMaxDynamicSharedMemorySize, GEMM_SMEM);
    cudaFuncSetAttribute(attn_out_kernel,
                         cudaFuncAttributeMaxDynamicSharedMemorySize, AO_SMEM);

    // 0) all fp16 conversions, one launch
    cvt_all_kernel<<<4096 + 1024, 256>>>(
        (const float4*)x, (uint4*)xh, qk_w, v_w, out_w, wq, wv, wo);

    // 1+2) fused: qk = relu(bn(conv(x,wq))), val = relu(bn(conv(x,wv)))
    gemm_kernel<true, true, true, false, true, false><<<dim3(32, 6, BB), 256, GEMM_SMEM>>>(
        wq, 0, xh, (size_t)CIN*HW, qk_gamma, qk_beta, qk_mean, qk_var,
        1.f, nullptr, qkh, (size_t)CK*HW, CIN,
        wv, v_gamma, v_beta, v_mean, v_var, valh, (size_t)CV*HW);
    // 3) key = psp(qk) [s][c]  AND  value = psp(val) [c][s]  (one launch)
    psp_kernel<<<PSP_BLOCKS, 256>>>(qkh, keyh, valh, vpsp);
    // 4) P = softmax_s( (key @ qk) / 16 )  -- softmax fused into GEMM epilogue
    gemm_kernel<false, false, false, false, true, true><<<dim3(32, 1, BB), 256, GEMM_SMEM>>>(
        keyh, (size_t)128*CK, qkh, (size_t)CK*HW, nullptr, nullptr, nullptr, nullptr,
        0.0625f, nullptr, ph, (size_t)112*HW, CK,
        nullptr, nullptr, nullptr, nullptr, nullptr, nullptr, 0);
    // 5) y[c][n] = value[c][s] @ p[s][n]
    attn_out_kernel<<<dim3(32, 4, BB), 256, AO_SMEM>>>(vpsp, ph, yh);
    // 6) out = x + bn(conv(y, wo))
    gemm_kernel<false, true, false, true, false, false><<<dim3(32, 4, BB), 256, GEMM_SMEM>>>(
        wo, 0, yh, (size_t)CV*HW, o_gamma, o_beta, o_mean, o_var,
        1.f, x, out, (size_t)CIN*HW, CV,
        nullptr, nullptr, nullptr, nullptr, nullptr, nullptr, 0);
}

// round 12
// speedup vs baseline: 1.4498x; 1.0010x over previous
#include <cuda_runtime.h>
#include <cuda_fp16.h>
#include <cstdint>
#include <math.h>

#define BB   8
#define CIN  512
#define CK   256
#define CV   512
#define HW   4096
#define SS   110

// Scratch (__device__ globals are zero-initialized; pad regions never written
// stay zero -> free zero-padding).
__device__ __align__(16) __half g_xh    [BB*CIN*HW];    // [b][k][n]
__device__ __align__(16) __half g_qkh   [BB*CK*HW];     // [b][c][n]
__device__ __align__(16) __half g_valh  [BB*CV*HW];     // [b][c][n]
__device__ __align__(16) __half g_keyh  [BB*128*CK];    // [b][s(pad128)][c]
__device__ __align__(16) __half g_vpsp  [BB*CV*112];    // [b][c][s(pad112)]
__device__ __align__(16) __half g_ph    [BB*112*HW];    // [b][s(pad112)][n]
__device__ __align__(16) __half g_yh    [BB*CV*HW];     // [b][c][n]
__device__ __align__(16) __half g_wq    [CK*CIN];
__device__ __align__(16) __half g_wv    [CV*CIN];
__device__ __align__(16) __half g_wo    [CIN*CV];

// ---------------------------------------------------------------------------
__device__ __forceinline__ uint32_t smem_u32(const void* p) {
    uint32_t a;
    asm("{ .reg .u64 t; cvta.to.shared.u64 t, %1; cvt.u32.u64 %0, t; }" : "=r"(a) : "l"(p));
    return a;
}
__device__ __forceinline__ void ldsm_x4(uint32_t* r, uint32_t addr) {
    asm volatile("ldmatrix.sync.aligned.m8n8.x4.shared.b16 {%0,%1,%2,%3}, [%4];"
        : "=r"(r[0]), "=r"(r[1]), "=r"(r[2]), "=r"(r[3]) : "r"(addr));
}
__device__ __forceinline__ void ldsm_x4_t(uint32_t* r, uint32_t addr) {
    asm volatile("ldmatrix.sync.aligned.m8n8.x4.trans.shared.b16 {%0,%1,%2,%3}, [%4];"
        : "=r"(r[0]), "=r"(r[1]), "=r"(r[2]), "=r"(r[3]) : "r"(addr));
}
__device__ __forceinline__ void mma_f16(float* c, const uint32_t* a, const uint32_t* b) {
    asm volatile(
        "mma.sync.aligned.m16n8k16.row.col.f32.f16.f16.f32 "
        "{%0,%1,%2,%3}, {%4,%5,%6,%7}, {%8,%9}, {%0,%1,%2,%3};"
        : "+f"(c[0]), "+f"(c[1]), "+f"(c[2]), "+f"(c[3])
        : "r"(a[0]), "r"(a[1]), "r"(a[2]), "r"(a[3]), "r"(b[0]), "r"(b[1]));
}
__device__ __forceinline__ void cpa16(uint32_t dst, const void* src) {
    asm volatile("cp.async.cg.shared.global [%0], [%1], 16;" :: "r"(dst), "l"(src));
}

// ---------------------------------------------------------------------------
// Generalized GEMM: out[b,m,n] = epi( sum_k A[m,k] * B[b,k,n] )
// CTA 128m x 128n, 8 warps (2x4), warp 64x32. K staged 32, 4-stage pipeline.
// (75.8KB smem/CTA -> 2 CTAs/SM resident; proven best config.)
// FUSED: blockIdx.y<2 -> branch 1, else branch 2.
// SOFTMAX: epilogue computes column-softmax over m (valid rows < SS) and
//          writes fp16 probabilities directly (rows [SS,112) written 0).
// ---------------------------------------------------------------------------
#define A_STRH 40
#define B_STRH 136
#define A_STG  (128*A_STRH*2)              // 10240 B
#define B_STG  (32*B_STRH*2)               // 8704 B
#define STG    (A_STG + B_STG)             // 18944 B
#define NSTAGE 4
#define GEMM_SMEM (NSTAGE*STG)             // 75776 B

template<bool FUSED, bool BN, bool RELU, bool RESID, bool HALF_OUT, bool SOFTMAX>
__global__ __launch_bounds__(256, 2) void gemm_kernel(
    const __half* __restrict__ A, size_t a_bstride,
    const __half* __restrict__ Bm, size_t b_bstride,
    const float* __restrict__ gamma, const float* __restrict__ beta,
    const float* __restrict__ mean,  const float* __restrict__ var,
    float uscale,
    const float* __restrict__ resid,
    void* __restrict__ outp, size_t o_bstride,
    int Ktot,
    // FUSED branch-2 args
    const __half* __restrict__ A2,
    const float* __restrict__ gamma2, const float* __restrict__ beta2,
    const float* __restrict__ mean2,  const float* __restrict__ var2,
    void* __restrict__ outp2, size_t o_bstride2)
{
    extern __shared__ __align__(16) char smc[];
    const uint32_t sb = smem_u32(smc);
    const int tid = threadIdx.x, lane = tid & 31, wid = tid >> 5;
    const int gidr = lane >> 2, t4 = lane & 3;
    const int wm = wid >> 2, wn = wid & 3;
    const int n0 = blockIdx.x * 128, b = blockIdx.z;
    const int NK = Ktot >> 5;

    int m0 = blockIdx.y * 128;
    const __half* Ause = A;
    const float *g_ = gamma, *be_ = beta, *me_ = mean, *va_ = var;
    void* ouse = outp;
    size_t ostr = o_bstride;
    if (FUSED && blockIdx.y >= 2) {
        m0 = (blockIdx.y - 2) * 128;
        Ause = A2; g_ = gamma2; be_ = beta2; me_ = mean2; va_ = var2;
        ouse = outp2; ostr = o_bstride2;
    }

    const __half* gA = Ause + (size_t)b * a_bstride + (size_t)m0 * Ktot;
    const __half* gB = Bm + (size_t)b * b_bstride + n0;

    auto load_stage = [&](int s) {
        const uint32_t base = sb + (uint32_t)(s & (NSTAGE-1)) * STG;
        #pragma unroll
        for (int it = 0; it < 2; ++it) {            // A: 128r x 4 chunks
            int idx = it * 256 + tid;
            int r = idx >> 2, c = idx & 3;
            cpa16(base + (uint32_t)(r * A_STRH + c * 8) * 2,
                  gA + (size_t)r * Ktot + s * 32 + c * 8);
        }
        #pragma unroll
        for (int it = 0; it < 2; ++it) {            // B: 32r x 16 chunks
            int idx = it * 256 + tid;
            int r = idx >> 4, c = idx & 15;
            cpa16(base + A_STG + (uint32_t)(r * B_STRH + c * 8) * 2,
                  gB + (size_t)(s * 32 + r) * HW + c * 8);
        }
        asm volatile("cp.async.commit_group;" ::: "memory");
    };

    float acc[4][4][4];
    #pragma unroll
    for (int mt = 0; mt < 4; ++mt)
        #pragma unroll
        for (int nt = 0; nt < 4; ++nt)
            #pragma unroll
            for (int r = 0; r < 4; ++r) acc[mt][nt][r] = 0.f;

    for (int s = 0; s < NSTAGE - 1 && s < NK; ++s) load_stage(s);
    asm volatile("cp.async.wait_group 2;" ::: "memory");
    __syncthreads();

    const int a_row = lane & 15, a_koff = (lane >> 4) * 8;
    const int b_krow = ((lane >> 3) & 1) * 8 + (lane & 7);
    const int b_noff = (lane >> 4) * 8;

    for (int kt = 0; kt < NK; ++kt) {
        if (kt + NSTAGE - 1 < NK) load_stage(kt + NSTAGE - 1);
        else asm volatile("cp.async.commit_group;" ::: "memory");

        const uint32_t sA = sb + (uint32_t)(kt & (NSTAGE-1)) * STG;
        const uint32_t sB = sA + A_STG;
        #pragma unroll
        for (int s16 = 0; s16 < 2; ++s16) {
            const int kk = s16 * 16;
            uint32_t af[4][4], bf[4][2];
            #pragma unroll
            for (int mt = 0; mt < 4; ++mt) {
                int row = wm * 64 + mt * 16 + a_row;
                ldsm_x4(af[mt], sA + (uint32_t)(row * A_STRH + kk + a_koff) * 2);
            }
            #pragma unroll
            for (int nt2 = 0; nt2 < 2; ++nt2) {
                uint32_t r4[4];
                int ncol = wn * 32 + nt2 * 16 + b_noff;
                ldsm_x4_t(r4, sB + (uint32_t)((kk + b_krow) * B_STRH + ncol) * 2);
                bf[nt2*2][0] = r4[0]; bf[nt2*2][1] = r4[1];
                bf[nt2*2+1][0] = r4[2]; bf[nt2*2+1][1] = r4[3];
            }
            #pragma unroll
            for (int mt = 0; mt < 4; ++mt)
                #pragma unroll
                for (int nt = 0; nt < 4; ++nt)
                    mma_f16(acc[mt][nt], af[mt], bf[nt]);
        }
        asm volatile("cp.async.wait_group 2;" ::: "memory");
        __syncthreads();
    }

    if (SOFTMAX) {
        // Column softmax over m rows (m0==0, grid.y==1). Valid rows: < SS.
        float* red = (float*)smc;              // reuse stage smem (512 floats)
        float cmax[4][2], csum[4][2];
        #pragma unroll
        for (int nt = 0; nt < 4; ++nt) { cmax[nt][0] = -3.4e38f; cmax[nt][1] = -3.4e38f; }
        #pragma unroll
        for (int mt = 0; mt < 4; ++mt) {
            const int r0 = wm * 64 + mt * 16 + gidr, r1 = r0 + 8;
            #pragma unroll
            for (int nt = 0; nt < 4; ++nt) {
                #pragma unroll
                for (int r = 0; r < 4; ++r) acc[mt][nt][r] *= uscale;
                if (r0 < SS) {
                    cmax[nt][0] = fmaxf(cmax[nt][0], acc[mt][nt][0]);
                    cmax[nt][1] = fmaxf(cmax[nt][1], acc[mt][nt][1]);
                }
                if (r1 < SS) {
                    cmax[nt][0] = fmaxf(cmax[nt][0], acc[mt][nt][2]);
                    cmax[nt][1] = fmaxf(cmax[nt][1], acc[mt][nt][3]);
                }
            }
        }
        #pragma unroll
        for (int nt = 0; nt < 4; ++nt)
            #pragma unroll
            for (int j = 0; j < 2; ++j) {
                float v = cmax[nt][j];
                v = fmaxf(v, __shfl_xor_sync(0xffffffffu, v, 4));
                v = fmaxf(v, __shfl_xor_sync(0xffffffffu, v, 8));
                v = fmaxf(v, __shfl_xor_sync(0xffffffffu, v, 16));
                cmax[nt][j] = v;
            }
        if (gidr == 0)
            #pragma unroll
            for (int nt = 0; nt < 4; ++nt)
                #pragma unroll
                for (int j = 0; j < 2; ++j)
                    red[wm*128 + wn*32 + nt*8 + 2*t4 + j] = cmax[nt][j];
        __syncthreads();
        #pragma unroll
        for (int nt = 0; nt < 4; ++nt)
            #pragma unroll
            for (int j = 0; j < 2; ++j)
                cmax[nt][j] = fmaxf(cmax[nt][j], red[(wm^1)*128 + wn*32 + nt*8 + 2*t4 + j]);

        #pragma unroll
        for (int nt = 0; nt < 4; ++nt) { csum[nt][0] = 0.f; csum[nt][1] = 0.f; }
        #pragma unroll
        for (int mt = 0; mt < 4; ++mt) {
            const int r0 = wm * 64 + mt * 16 + gidr, r1 = r0 + 8;
            #pragma unroll
            for (int nt = 0; nt < 4; ++nt) {
                float e0 = (r0 < SS) ? __expf(acc[mt][nt][0] - cmax[nt][0]) : 0.f;
                float e1 = (r0 < SS) ? __expf(acc[mt][nt][1] - cmax[nt][1]) : 0.f;
                float e2 = (r1 < SS) ? __expf(acc[mt][nt][2] - cmax[nt][0]) : 0.f;
                float e3 = (r1 < SS) ? __expf(acc[mt][nt][3] - cmax[nt][1]) : 0.f;
                acc[mt][nt][0] = e0; acc[mt][nt][1] = e1;
                acc[mt][nt][2] = e2; acc[mt][nt][3] = e3;
                csum[nt][0] += e0 + e2; csum[nt][1] += e1 + e3;
            }
        }
        #pragma unroll
        for (int nt = 0; nt < 4; ++nt)
            #pragma unroll
            for (int j = 0; j < 2; ++j) {
                float v = csum[nt][j];
                v += __shfl_xor_sync(0xffffffffu, v, 4);
                v += __shfl_xor_sync(0xffffffffu, v, 8);
                v += __shfl_xor_sync(0xffffffffu, v, 16);
                csum[nt][j] = v;
            }
        if (gidr == 0)
            #pragma unroll
            for (int nt = 0; nt < 4; ++nt)
                #pragma unroll
                for (int j = 0; j < 2; ++j)
                    red[256 + wm*128 + wn*32 + nt*8 + 2*t4 + j] = csum[nt][j];
        __syncthreads();
        #pragma unroll
        for (int nt = 0; nt < 4; ++nt)
            #pragma unroll
            for (int j = 0; j < 2; ++j)
                csum[nt][j] += red[256 + (wm^1)*128 + wn*32 + nt*8 + 2*t4 + j];

        __half* oh = (__half*)ouse + (size_t)b * ostr;
        #pragma unroll
        for (int mt = 0; mt < 4; ++mt) {
            const int r0 = wm * 64 + mt * 16 + gidr, r1 = r0 + 8;
            #pragma unroll
            for (int nt = 0; nt < 4; ++nt) {
                const int nn = n0 + wn * 32 + nt * 8 + 2 * t4;
                const float i0 = 1.f / csum[nt][0], i1 = 1.f / csum[nt][1];
                if (r0 < 112)
                    *(__half2*)(oh + (size_t)r0 * HW + nn) =
                        __floats2half2_rn(acc[mt][nt][0] * i0, acc[mt][nt][1] * i1);
                if (r1 < 112)
                    *(__half2*)(oh + (size_t)r1 * HW + nn) =
                        __floats2half2_rn(acc[mt][nt][2] * i0, acc[mt][nt][3] * i1);
            }
        }
        return;
    }

    // Standard epilogue
    #pragma unroll
    for (int mt = 0; mt < 4; ++mt) {
        const int ml = m0 + wm * 64 + mt * 16 + gidr;
        const int mh = ml + 8;
        float scl, ttl, sch, tth;
        if (BN) {
            scl = g_[ml] * rsqrtf(va_[ml] + 1e-5f);
            ttl = be_[ml] - me_[ml] * scl;
            sch = g_[mh] * rsqrtf(va_[mh] + 1e-5f);
            tth = be_[mh] - me_[mh] * sch;
        } else { scl = uscale; ttl = 0.f; sch = uscale; tth = 0.f; }
        #pragma unroll
        for (int nt = 0; nt < 4; ++nt) {
            const int nn = n0 + wn * 32 + nt * 8 + 2 * t4;
            float2 vl, vh;
            vl.x = acc[mt][nt][0] * scl + ttl;
            vl.y = acc[mt][nt][1] * scl + ttl;
            vh.x = acc[mt][nt][2] * sch + tth;
            vh.y = acc[mt][nt][3] * sch + tth;
            if (RELU) {
                vl.x = fmaxf(vl.x, 0.f); vl.y = fmaxf(vl.y, 0.f);
                vh.x = fmaxf(vh.x, 0.f); vh.y = fmaxf(vh.y, 0.f);
            }
            if (HALF_OUT) {
                __half* oh = (__half*)ouse + (size_t)b * ostr;
                *(__half2*)(oh + (size_t)ml * HW + nn) = __floats2half2_rn(vl.x, vl.y);
                *(__half2*)(oh + (size_t)mh * HW + nn) = __floats2half2_rn(vh.x, vh.y);
            } else {
                float* of = (float*)ouse + (size_t)b * ostr;
                if (RESID) {
                    const float* rp = resid + (size_t)b * ostr;
                    float2 rl = *(const float2*)(rp + (size_t)ml * HW + nn);
                    float2 rh = *(const float2*)(rp + (size_t)mh * HW + nn);
                    vl.x += rl.x; vl.y += rl.y; vh.x += rh.x; vh.y += rh.y;
                }
                *(float2*)(of + (size_t)ml * HW + nn) = vl;
                *(float2*)(of + (size_t)mh * HW + nn) = vh;
            }
        }
    }
}

// ---------------------------------------------------------------------------
// attn_out: y[b][c][n] = sum_s Vp[b][c][s] * P[b][s][n]  (K=112 single shot)
// ---------------------------------------------------------------------------
#define AO_ASTR 120
#define AO_SMEM (128*AO_ASTR*2 + 112*B_STRH*2)   // 61184

__global__ __launch_bounds__(256, 2) void attn_out_kernel(
    const __half* __restrict__ Vp, const __half* __restrict__ P, __half* __restrict__ y)
{
    extern __shared__ __align__(16) char smc[];
    const uint32_t sb = smem_u32(smc);
    const uint32_t sA = sb, sB = sb + 128*AO_ASTR*2;
    const int tid = threadIdx.x, lane = tid & 31, wid = tid >> 5;
    const int gidr = lane >> 2, t4 = lane & 3;
    const int wm = wid >> 2, wn = wid & 3;
    const int n0 = blockIdx.x * 128, c0 = blockIdx.y * 128, b = blockIdx.z;

    const __half* gA = Vp + (size_t)b * CV * 112 + (size_t)c0 * 112;
    const __half* gB = P + (size_t)b * 112 * HW + n0;

    #pragma unroll
    for (int it = 0; it < 7; ++it) {
        int idx = it * 256 + tid;
        int r = idx / 14, c = idx - r * 14;
        cpa16(sA + (uint32_t)(r * AO_ASTR + c * 8) * 2, gA + (size_t)r * 112 + c * 8);
    }
    #pragma unroll
    for (int it = 0; it < 7; ++it) {
        int idx = it * 256 + tid;
        int r = idx >> 4, c = idx & 15;
        cpa16(sB + (uint32_t)(r * B_STRH + c * 8) * 2, gB + (size_t)r * HW + c * 8);
    }
    asm volatile("cp.async.commit_group;\ncp.async.wait_group 0;" ::: "memory");
    __syncthreads();

    const int a_row = lane & 15, a_koff = (lane >> 4) * 8;
    const int b_krow = ((lane >> 3) & 1) * 8 + (lane & 7);
    const int b_noff = (lane >> 4) * 8;

    float acc[4][4][4];
    #pragma unroll
    for (int mt = 0; mt < 4; ++mt)
        #pragma unroll
        for (int nt = 0; nt < 4; ++nt)
            #pragma unroll
            for (int r = 0; r < 4; ++r) acc[mt][nt][r] = 0.f;

    #pragma unroll
    for (int s16 = 0; s16 < 7; ++s16) {
        const int kk = s16 * 16;
        uint32_t af[4][4], bf[4][2];
        #pragma unroll
        for (int mt = 0; mt < 4; ++mt) {
            int row = wm * 64 + mt * 16 + a_row;
            ldsm_x4(af[mt], sA + (uint32_t)(row * AO_ASTR + kk + a_koff) * 2);
        }
        #pragma unroll
        for (int nt2 = 0; nt2 < 2; ++nt2) {
            uint32_t r4[4];
            int ncol = wn * 32 + nt2 * 16 + b_noff;
            ldsm_x4_t(r4, sB + (uint32_t)((kk + b_krow) * B_STRH + ncol) * 2);
            bf[nt2*2][0] = r4[0]; bf[nt2*2][1] = r4[1];
            bf[nt2*2+1][0] = r4[2]; bf[nt2*2+1][1] = r4[3];
        }
        #pragma unroll
        for (int mt = 0; mt < 4; ++mt)
            #pragma unroll
            for (int nt = 0; nt < 4; ++nt)
                mma_f16(acc[mt][nt], af[mt], bf[nt]);
    }

    __half* yb = y + (size_t)b * CV * HW;
    #pragma unroll
    for (int mt = 0; mt < 4; ++mt) {
        const int ml = c0 + wm * 64 + mt * 16 + gidr;
        #pragma unroll
        for (int nt = 0; nt < 4; ++nt) {
            const int nn = n0 + wn * 32 + nt * 8 + 2 * t4;
            *(__half2*)(yb + (size_t)ml * HW + nn) =
                __floats2half2_rn(acc[mt][nt][0], acc[mt][nt][1]);
            *(__half2*)(yb + (size_t)(ml + 8) * HW + nn) =
                __floats2half2_rn(acc[mt][nt][2], acc[mt][nt][3]);
        }
    }
}

// ---------------------------------------------------------------------------
// All fp16 conversions in ONE launch. x-blocks process TWO uint4 pairs each
// (MLP 4) for higher DRAM utilization; weight blocks follow.
// ---------------------------------------------------------------------------
#define XHALF (BB*CIN*HW/16)      // 1048576 -> 4096 blocks of 256
__global__ __launch_bounds__(256) void cvt_all_kernel(
    const float4* __restrict__ x, uint4* __restrict__ xh,
    const float* __restrict__ wq, const float* __restrict__ wv,
    const float* __restrict__ wo,
    __half* __restrict__ oq, __half* __restrict__ ov, __half* __restrict__ oo)
{
    if (blockIdx.x < 4096) {
        int i = blockIdx.x * 256 + threadIdx.x;
        float4 a0 = x[2*i], a1 = x[2*i+1];
        float4 b0 = x[2*(i + XHALF)], b1 = x[2*(i + XHALF)+1];
        __half2 h0 = __floats2half2_rn(a0.x, a0.y), h1 = __floats2half2_rn(a0.z, a0.w);
        __half2 h2 = __floats2half2_rn(a1.x, a1.y), h3 = __floats2half2_rn(a1.z, a1.w);
        __half2 g0 = __floats2half2_rn(b0.x, b0.y), g1 = __floats2half2_rn(b0.z, b0.w);
        __half2 g2 = __floats2half2_rn(b1.x, b1.y), g3 = __floats2half2_rn(b1.z, b1.w);
        uint4 u, v;
        u.x = *(uint32_t*)&h0; u.y = *(uint32_t*)&h1;
        u.z = *(uint32_t*)&h2; u.w = *(uint32_t*)&h3;
        v.x = *(uint32_t*)&g0; v.y = *(uint32_t*)&g1;
        v.z = *(uint32_t*)&g2; v.w = *(uint32_t*)&g3;
        xh[i] = u;
        xh[i + XHALF] = v;
    } else {
        int i = (blockIdx.x - 4096) * 256 + threadIdx.x;
        if (i < CK*CIN) oq[i] = __float2half_rn(wq[i]);
        if (i < CV*CIN) { ov[i] = __float2half_rn(wv[i]); oo[i] = __float2half_rn(wo[i]); }
    }
}

// ---------------------------------------------------------------------------
// PSP adaptive max pool (single tensor per launch so the two tensors can run
// on different streams). Plane in fp16 smem (stride 66), __hmax2 phase 1,
// 2 planes per 256-thread block.
// mode 0: out[(b*C + c)*112 + cell]   (value: [c][s] pad 112)
// mode 1: out[(b*128 + cell)*C + c]   (key:   [s pad128][c])
// ---------------------------------------------------------------------------
#define SPH_STR 66
#define RM_STR  65

__global__ __launch_bounds__(256) void psp_kernel(
    const __half* __restrict__ in, __half* __restrict__ out, int C, int mode)
{
    __shared__ __align__(16) __half sph[2][64 * SPH_STR];
    __shared__ float rm[2][17 * RM_STR];
    __shared__ float s8v[2][64];
    const int pl = threadIdx.x >> 7;
    const int tid = threadIdx.x & 127;
    const int bc = blockIdx.x * 2 + pl;
    const int b = bc / C, c = bc - b * C;
    __half* spp = sph[pl];
    float* rmp = rm[pl];
    const __half* plane = in + (size_t)bc * 4096;

    for (int i = tid; i < 512; i += 128) {
        uint4 u = ((const uint4*)plane)[i];
        int row = i >> 3, col = (i & 7) * 8;
        uint32_t* d = (uint32_t*)(spp + row * SPH_STR + col);
        d[0] = u.x; d[1] = u.y; d[2] = u.z; d[3] = u.w;
    }
    __syncthreads();

    // Phase 1: per-(seg,row) column-range maxes, fp16 pairwise.
    const int cs[17] = {0,21,42, 0,10,21,32,42,53, 0,8,16,24,32,40,48,56};
    const int ce[17] = {22,43,64, 11,22,32,43,54,64, 8,16,24,32,40,48,56,64};
    for (int idx = tid; idx < 17 * 64; idx += 128) {
        int seg = idx >> 6, row = idx & 63;
        const __half* rp = spp + row * SPH_STR;
        int a = cs[seg], bnd = ce[seg];
        float m = -3.402823e38f;
        if (a & 1) { m = __half2float(rp[a]); ++a; }
        if (bnd & 1) { m = fmaxf(m, __half2float(rp[bnd - 1])); --bnd; }
        __half2 m2 = __floats2half2_rn(-65504.f, -65504.f);
        const __half2* rp2 = (const __half2*)rp;
        for (int c2 = a >> 1; c2 < (bnd >> 1); ++c2) m2 = __hmax2(m2, rp2[c2]);
        m = fmaxf(m, fmaxf(__low2float(m2), __high2float(m2)));
        rmp[seg * RM_STR + row] = m;
    }
    __syncthreads();

    // Phase 2: cells
    float m = -3.402823e38f;
    int cell = -1;
    if (tid < 64) {                        // s=8
        int i = tid >> 3, j = tid & 7;
        for (int r = i * 8; r < i * 8 + 8; ++r) m = fmaxf(m, rmp[(9 + j) * RM_STR + r]);
        s8v[pl][tid] = m; cell = 46 + tid;
    } else if (tid < 100) {                // s=6
        const int st[6] = {0,10,21,32,42,53}, en[6] = {11,22,32,43,54,64};
        int t = tid - 64, i = t / 6, j = t - i * 6;
        for (int r = st[i]; r < en[i]; ++r) m = fmaxf(m, rmp[(3 + j) * RM_STR + r]);
        cell = 10 + t;
    } else if (tid < 109) {                // s=3
        const int st[3] = {0,21,42}, en[3] = {22,43,64};
        int t = tid - 100, i = t / 3, j = t - i * 3;
        for (int r = st[i]; r < en[i]; ++r) m = fmaxf(m, rmp[j * RM_STR + r]);
        cell = 1 + t;
    }
    if (cell >= 0) {
        size_t o = mode ? ((size_t)(b * 128 + cell) * C + c)
                        : ((size_t)bc * 112 + cell);
        out[o] = __float2half_rn(m);
    }
    __syncthreads();
    if (tid == 0) {                        // s=1 from the 64 exact 8x8 cells
        float mm = s8v[pl][0];
        for (int i = 1; i < 64; ++i) mm = fmaxf(mm, s8v[pl][i]);
        size_t o = mode ? ((size_t)(b * 128) * C + c) : ((size_t)bc * 112);
        out[o] = __float2half_rn(mm);
    }
}

// ---------------------------------------------------------------------------
extern "C" void kernel_launch(void* const* d_in, const int* in_sizes, int n_in,
                              void* d_out, int out_size)
{
    const float* x        = (const float*)d_in[0];
    const float* qk_w     = (const float*)d_in[1];
    const float* qk_gamma = (const float*)d_in[2];
    const float* qk_beta  = (const float*)d_in[3];
    const float* qk_mean  = (const float*)d_in[4];
    const float* qk_var   = (const float*)d_in[5];
    const float* v_w      = (const float*)d_in[6];
    const float* v_gamma  = (const float*)d_in[7];
    const float* v_beta   = (const float*)d_in[8];
    const float* v_mean   = (const float*)d_in[9];
    const float* v_var    = (const float*)d_in[10];
    const float* out_w    = (const float*)d_in[11];
    const float* o_gamma  = (const float*)d_in[12];
    const float* o_beta   = (const float*)d_in[13];
    const float* o_mean   = (const float*)d_in[14];
    const float* o_var    = (const float*)d_in[15];
    float* out = (float*)d_out;

    __half *xh, *qkh, *valh, *keyh, *vpsp, *ph, *yh, *wq, *wv, *wo;
    cudaGetSymbolAddress((void**)&xh,   g_xh);
    cudaGetSymbolAddress((void**)&qkh,  g_qkh);
    cudaGetSymbolAddress((void**)&valh, g_valh);
    cudaGetSymbolAddress((void**)&keyh, g_keyh);
    cudaGetSymbolAddress((void**)&vpsp, g_vpsp);
    cudaGetSymbolAddress((void**)&ph,   g_ph);
    cudaGetSymbolAddress((void**)&yh,   g_yh);
    cudaGetSymbolAddress((void**)&wq,   g_wq);
    cudaGetSymbolAddress((void**)&wv,   g_wv);
    cudaGetSymbolAddress((void**)&wo,   g_wo);

    cudaFuncSetAttribute(gemm_kernel<true, true, true, false, true, false>,
                         cudaFuncAttributeMaxDynamicSharedMemorySize, GEMM_SMEM);
    cudaFuncSetAttribute(gemm_kernel<false, false, false, false, true, true>,
                         cudaFuncAttributeMaxDynamicSharedMemorySize, GEMM_SMEM);
    cudaFuncSetAttribute(gemm_kernel<false, true, false, true, false, false>,
                         cudaFuncAttributeMaxDynamicSharedMemorySize, GEMM_SMEM);
    cudaFuncSetAttribute(attn_out_kernel,
                         cudaFuncAttributeMaxDynamicSharedMemorySize, AO_SMEM);

    // Side stream + events, created once on the first (uncaptured) call.
    static cudaStream_t s1 = nullptr;
    static cudaEvent_t ev_fork = nullptr, ev_join = nullptr;
    if (s1 == nullptr) {
        cudaStreamCreateWithFlags(&s1, cudaStreamNonBlocking);
        cudaEventCreateWithFlags(&ev_fork, cudaEventDisableTiming);
        cudaEventCreateWithFlags(&ev_join, cudaEventDisableTiming);
    }

    // 0) all fp16 conversions, one launch
    cvt_all_kernel<<<4096 + 1024, 256>>>(
        (const float4*)x, (uint4*)xh, qk_w, v_w, out_w, wq, wv, wo);

    // 1+2) fused: qk = relu(bn(conv(x,wq))), val = relu(bn(conv(x,wv)))
    gemm_kernel<true, true, true, false, true, false><<<dim3(32, 6, BB), 256, GEMM_SMEM>>>(
        wq, 0, xh, (size_t)CIN*HW, qk_gamma, qk_beta, qk_mean, qk_var,
        1.f, nullptr, qkh, (size_t)CK*HW, CIN,
        wv, v_gamma, v_beta, v_mean, v_var, valh, (size_t)CV*HW);

    // Fork: psp_val runs on side stream, overlapped with psp_qk + scores.
    cudaEventRecord(ev_fork, 0);
    cudaStreamWaitEvent(s1, ev_fork, 0);
    psp_kernel<<<BB * CV / 2, 256, 0, s1>>>(valh, vpsp, CV, 0);
    cudaEventRecord(ev_join, s1);

    // 3a) key = psp(qk) [s][c]   (capture stream)
    psp_kernel<<<BB * CK / 2, 256>>>(qkh, keyh, CK, 1);
    // 4) P = softmax_s( (key @ qk) / 16 )  -- softmax fused into GEMM epilogue
    gemm_kernel<false, false, false, false, true, true><<<dim3(32, 1, BB), 256, GEMM_SMEM>>>(
        keyh, (size_t)128*CK, qkh, (size_t)CK*HW, nullptr, nullptr, nullptr, nullptr,
        0.0625f, nullptr, ph, (size_t)112*HW, CK,
        nullptr, nullptr, nullptr, nullptr, nullptr, nullptr, 0);

    // Join: attn_out needs vpsp (side stream) and ph (capture stream).
    cudaStreamWaitEvent(0, ev_join, 0);

    // 5) y[c][n] = value[c][s] @ p[s][n]
    attn_out_kernel<<<dim3(32, 4, BB), 256, AO_SMEM>>>(vpsp, ph, yh);
    // 6) out = x + bn(conv(y, wo))
    gemm_kernel<false, true, false, true, false, false><<<dim3(32, 4, BB), 256, GEMM_SMEM>>>(
        wo, 0, yh, (size_t)CV*HW, o_gamma, o_beta, o_mean, o_var,
        1.f, x, out, (size_t)CIN*HW, CV,
        nullptr, nullptr, nullptr, nullptr, nullptr, nullptr, 0);
}

// round 13
// speedup vs baseline: 1.5512x; 1.0700x over previous
#include <cuda_runtime.h>
#include <cuda_fp16.h>
#include <cstdint>
#include <math.h>

#define BB   8
#define CIN  512
#define CK   256
#define CV   512
#define HW   4096
#define SS   110

// Scratch (__device__ globals are zero-initialized; pad regions never written
// stay zero -> free zero-padding).
__device__ __align__(16) __half g_xh    [BB*CIN*HW];    // [b][k][n]
__device__ __align__(16) __half g_qkh   [BB*CK*HW];     // [b][c][n]
__device__ __align__(16) __half g_valh  [BB*CV*HW];     // [b][c][n]
__device__ __align__(16) __half g_keyh  [BB*128*CK];    // [b][s(pad128)][c]
__device__ __align__(16) __half g_vpsp  [BB*CV*112];    // [b][c][s(pad112)]
__device__ __align__(16) __half g_ph    [BB*112*HW];    // [b][s(pad112)][n]
__device__ __align__(16) __half g_yh    [BB*CV*HW];     // [b][c][n]
__device__ __align__(16) __half g_wq    [CK*CIN];
__device__ __align__(16) __half g_wv    [CV*CIN];
__device__ __align__(16) __half g_wo    [CIN*CV];

// ---------------------------------------------------------------------------
__device__ __forceinline__ uint32_t smem_u32(const void* p) {
    uint32_t a;
    asm("{ .reg .u64 t; cvta.to.shared.u64 t, %1; cvt.u32.u64 %0, t; }" : "=r"(a) : "l"(p));
    return a;
}
__device__ __forceinline__ void ldsm_x4(uint32_t* r, uint32_t addr) {
    asm volatile("ldmatrix.sync.aligned.m8n8.x4.shared.b16 {%0,%1,%2,%3}, [%4];"
        : "=r"(r[0]), "=r"(r[1]), "=r"(r[2]), "=r"(r[3]) : "r"(addr));
}
__device__ __forceinline__ void ldsm_x4_t(uint32_t* r, uint32_t addr) {
    asm volatile("ldmatrix.sync.aligned.m8n8.x4.trans.shared.b16 {%0,%1,%2,%3}, [%4];"
        : "=r"(r[0]), "=r"(r[1]), "=r"(r[2]), "=r"(r[3]) : "r"(addr));
}
__device__ __forceinline__ void mma_f16(float* c, const uint32_t* a, const uint32_t* b) {
    asm volatile(
        "mma.sync.aligned.m16n8k16.row.col.f32.f16.f16.f32 "
        "{%0,%1,%2,%3}, {%4,%5,%6,%7}, {%8,%9}, {%0,%1,%2,%3};"
        : "+f"(c[0]), "+f"(c[1]), "+f"(c[2]), "+f"(c[3])
        : "r"(a[0]), "r"(a[1]), "r"(a[2]), "r"(a[3]), "r"(b[0]), "r"(b[1]));
}
__device__ __forceinline__ void cpa16(uint32_t dst, const void* src) {
    asm volatile("cp.async.cg.shared.global [%0], [%1], 16;" :: "r"(dst), "l"(src));
}

// ---------------------------------------------------------------------------
// Generalized GEMM: out[b,m,n] = epi( sum_k A[m,k] * B[b,k,n] )
// CTA 128m x 128n, 8 warps (2x4), warp 64x32. K staged 32, 4-stage pipeline.
// (75.8KB smem/CTA -> 2 CTAs/SM resident; proven best config.)
// ---------------------------------------------------------------------------
#define A_STRH 40
#define B_STRH 136
#define A_STG  (128*A_STRH*2)              // 10240 B
#define B_STG  (32*B_STRH*2)               // 8704 B
#define STG    (A_STG + B_STG)             // 18944 B
#define NSTAGE 4
#define GEMM_SMEM (NSTAGE*STG)             // 75776 B

template<bool FUSED, bool BN, bool RELU, bool RESID, bool HALF_OUT, bool SOFTMAX>
__global__ __launch_bounds__(256, 2) void gemm_kernel(
    const __half* __restrict__ A, size_t a_bstride,
    const __half* __restrict__ Bm, size_t b_bstride,
    const float* __restrict__ gamma, const float* __restrict__ beta,
    const float* __restrict__ mean,  const float* __restrict__ var,
    float uscale,
    const float* __restrict__ resid,
    void* __restrict__ outp, size_t o_bstride,
    int Ktot,
    const __half* __restrict__ A2,
    const float* __restrict__ gamma2, const float* __restrict__ beta2,
    const float* __restrict__ mean2,  const float* __restrict__ var2,
    void* __restrict__ outp2, size_t o_bstride2)
{
    extern __shared__ __align__(16) char smc[];
    const uint32_t sb = smem_u32(smc);
    const int tid = threadIdx.x, lane = tid & 31, wid = tid >> 5;
    const int gidr = lane >> 2, t4 = lane & 3;
    const int wm = wid >> 2, wn = wid & 3;
    const int n0 = blockIdx.x * 128, b = blockIdx.z;
    const int NK = Ktot >> 5;

    int m0 = blockIdx.y * 128;
    const __half* Ause = A;
    const float *g_ = gamma, *be_ = beta, *me_ = mean, *va_ = var;
    void* ouse = outp;
    size_t ostr = o_bstride;
    if (FUSED && blockIdx.y >= 2) {
        m0 = (blockIdx.y - 2) * 128;
        Ause = A2; g_ = gamma2; be_ = beta2; me_ = mean2; va_ = var2;
        ouse = outp2; ostr = o_bstride2;
    }

    const __half* gA = Ause + (size_t)b * a_bstride + (size_t)m0 * Ktot;
    const __half* gB = Bm + (size_t)b * b_bstride + n0;

    auto load_stage = [&](int s) {
        const uint32_t base = sb + (uint32_t)(s & (NSTAGE-1)) * STG;
        #pragma unroll
        for (int it = 0; it < 2; ++it) {            // A: 128r x 4 chunks
            int idx = it * 256 + tid;
            int r = idx >> 2, c = idx & 3;
            cpa16(base + (uint32_t)(r * A_STRH + c * 8) * 2,
                  gA + (size_t)r * Ktot + s * 32 + c * 8);
        }
        #pragma unroll
        for (int it = 0; it < 2; ++it) {            // B: 32r x 16 chunks
            int idx = it * 256 + tid;
            int r = idx >> 4, c = idx & 15;
            cpa16(base + A_STG + (uint32_t)(r * B_STRH + c * 8) * 2,
                  gB + (size_t)(s * 32 + r) * HW + c * 8);
        }
        asm volatile("cp.async.commit_group;" ::: "memory");
    };

    float acc[4][4][4];
    #pragma unroll
    for (int mt = 0; mt < 4; ++mt)
        #pragma unroll
        for (int nt = 0; nt < 4; ++nt)
            #pragma unroll
            for (int r = 0; r < 4; ++r) acc[mt][nt][r] = 0.f;

    for (int s = 0; s < NSTAGE - 1 && s < NK; ++s) load_stage(s);
    asm volatile("cp.async.wait_group 2;" ::: "memory");
    __syncthreads();

    const int a_row = lane & 15, a_koff = (lane >> 4) * 8;
    const int b_krow = ((lane >> 3) & 1) * 8 + (lane & 7);
    const int b_noff = (lane >> 4) * 8;

    for (int kt = 0; kt < NK; ++kt) {
        if (kt + NSTAGE - 1 < NK) load_stage(kt + NSTAGE - 1);
        else asm volatile("cp.async.commit_group;" ::: "memory");

        const uint32_t sA = sb + (uint32_t)(kt & (NSTAGE-1)) * STG;
        const uint32_t sB = sA + A_STG;
        #pragma unroll
        for (int s16 = 0; s16 < 2; ++s16) {
            const int kk = s16 * 16;
            uint32_t af[4][4], bf[4][2];
            #pragma unroll
            for (int mt = 0; mt < 4; ++mt) {
                int row = wm * 64 + mt * 16 + a_row;
                ldsm_x4(af[mt], sA + (uint32_t)(row * A_STRH + kk + a_koff) * 2);
            }
            #pragma unroll
            for (int nt2 = 0; nt2 < 2; ++nt2) {
                uint32_t r4[4];
                int ncol = wn * 32 + nt2 * 16 + b_noff;
                ldsm_x4_t(r4, sB + (uint32_t)((kk + b_krow) * B_STRH + ncol) * 2);
                bf[nt2*2][0] = r4[0]; bf[nt2*2][1] = r4[1];
                bf[nt2*2+1][0] = r4[2]; bf[nt2*2+1][1] = r4[3];
            }
            #pragma unroll
            for (int mt = 0; mt < 4; ++mt)
                #pragma unroll
                for (int nt = 0; nt < 4; ++nt)
                    mma_f16(acc[mt][nt], af[mt], bf[nt]);
        }
        asm volatile("cp.async.wait_group 2;" ::: "memory");
        __syncthreads();
    }

    if (SOFTMAX) {
        float* red = (float*)smc;
        float cmax[4][2], csum[4][2];
        #pragma unroll
        for (int nt = 0; nt < 4; ++nt) { cmax[nt][0] = -3.4e38f; cmax[nt][1] = -3.4e38f; }
        #pragma unroll
        for (int mt = 0; mt < 4; ++mt) {
            const int r0 = wm * 64 + mt * 16 + gidr, r1 = r0 + 8;
            #pragma unroll
            for (int nt = 0; nt < 4; ++nt) {
                #pragma unroll
                for (int r = 0; r < 4; ++r) acc[mt][nt][r] *= uscale;
                if (r0 < SS) {
                    cmax[nt][0] = fmaxf(cmax[nt][0], acc[mt][nt][0]);
                    cmax[nt][1] = fmaxf(cmax[nt][1], acc[mt][nt][1]);
                }
                if (r1 < SS) {
                    cmax[nt][0] = fmaxf(cmax[nt][0], acc[mt][nt][2]);
                    cmax[nt][1] = fmaxf(cmax[nt][1], acc[mt][nt][3]);
                }
            }
        }
        #pragma unroll
        for (int nt = 0; nt < 4; ++nt)
            #pragma unroll
            for (int j = 0; j < 2; ++j) {
                float v = cmax[nt][j];
                v = fmaxf(v, __shfl_xor_sync(0xffffffffu, v, 4));
                v = fmaxf(v, __shfl_xor_sync(0xffffffffu, v, 8));
                v = fmaxf(v, __shfl_xor_sync(0xffffffffu, v, 16));
                cmax[nt][j] = v;
            }
        if (gidr == 0)
            #pragma unroll
            for (int nt = 0; nt < 4; ++nt)
                #pragma unroll
                for (int j = 0; j < 2; ++j)
                    red[wm*128 + wn*32 + nt*8 + 2*t4 + j] = cmax[nt][j];
        __syncthreads();
        #pragma unroll
        for (int nt = 0; nt < 4; ++nt)
            #pragma unroll
            for (int j = 0; j < 2; ++j)
                cmax[nt][j] = fmaxf(cmax[nt][j], red[(wm^1)*128 + wn*32 + nt*8 + 2*t4 + j]);

        #pragma unroll
        for (int nt = 0; nt < 4; ++nt) { csum[nt][0] = 0.f; csum[nt][1] = 0.f; }
        #pragma unroll
        for (int mt = 0; mt < 4; ++mt) {
            const int r0 = wm * 64 + mt * 16 + gidr, r1 = r0 + 8;
            #pragma unroll
            for (int nt = 0; nt < 4; ++nt) {
                float e0 = (r0 < SS) ? __expf(acc[mt][nt][0] - cmax[nt][0]) : 0.f;
                float e1 = (r0 < SS) ? __expf(acc[mt][nt][1] - cmax[nt][1]) : 0.f;
                float e2 = (r1 < SS) ? __expf(acc[mt][nt][2] - cmax[nt][0]) : 0.f;
                float e3 = (r1 < SS) ? __expf(acc[mt][nt][3] - cmax[nt][1]) : 0.f;
                acc[mt][nt][0] = e0; acc[mt][nt][1] = e1;
                acc[mt][nt][2] = e2; acc[mt][nt][3] = e3;
                csum[nt][0] += e0 + e2; csum[nt][1] += e1 + e3;
            }
        }
        #pragma unroll
        for (int nt = 0; nt < 4; ++nt)
            #pragma unroll
            for (int j = 0; j < 2; ++j) {
                float v = csum[nt][j];
                v += __shfl_xor_sync(0xffffffffu, v, 4);
                v += __shfl_xor_sync(0xffffffffu, v, 8);
                v += __shfl_xor_sync(0xffffffffu, v, 16);
                csum[nt][j] = v;
            }
        if (gidr == 0)
            #pragma unroll
            for (int nt = 0; nt < 4; ++nt)
                #pragma unroll
                for (int j = 0; j < 2; ++j)
                    red[256 + wm*128 + wn*32 + nt*8 + 2*t4 + j] = csum[nt][j];
        __syncthreads();
        #pragma unroll
        for (int nt = 0; nt < 4; ++nt)
            #pragma unroll
            for (int j = 0; j < 2; ++j)
                csum[nt][j] += red[256 + (wm^1)*128 + wn*32 + nt*8 + 2*t4 + j];

        __half* oh = (__half*)ouse + (size_t)b * ostr;
        #pragma unroll
        for (int mt = 0; mt < 4; ++mt) {
            const int r0 = wm * 64 + mt * 16 + gidr, r1 = r0 + 8;
            #pragma unroll
            for (int nt = 0; nt < 4; ++nt) {
                const int nn = n0 + wn * 32 + nt * 8 + 2 * t4;
                const float i0 = 1.f / csum[nt][0], i1 = 1.f / csum[nt][1];
                if (r0 < 112)
                    *(__half2*)(oh + (size_t)r0 * HW + nn) =
                        __floats2half2_rn(acc[mt][nt][0] * i0, acc[mt][nt][1] * i1);
                if (r1 < 112)
                    *(__half2*)(oh + (size_t)r1 * HW + nn) =
                        __floats2half2_rn(acc[mt][nt][2] * i0, acc[mt][nt][3] * i1);
            }
        }
        return;
    }

    // Standard epilogue
    #pragma unroll
    for (int mt = 0; mt < 4; ++mt) {
        const int ml = m0 + wm * 64 + mt * 16 + gidr;
        const int mh = ml + 8;
        float scl, ttl, sch, tth;
        if (BN) {
            scl = g_[ml] * rsqrtf(va_[ml] + 1e-5f);
            ttl = be_[ml] - me_[ml] * scl;
            sch = g_[mh] * rsqrtf(va_[mh] + 1e-5f);
            tth = be_[mh] - me_[mh] * sch;
        } else { scl = uscale; ttl = 0.f; sch = uscale; tth = 0.f; }
        #pragma unroll
        for (int nt = 0; nt < 4; ++nt) {
            const int nn = n0 + wn * 32 + nt * 8 + 2 * t4;
            float2 vl, vh;
            vl.x = acc[mt][nt][0] * scl + ttl;
            vl.y = acc[mt][nt][1] * scl + ttl;
            vh.x = acc[mt][nt][2] * sch + tth;
            vh.y = acc[mt][nt][3] * sch + tth;
            if (RELU) {
                vl.x = fmaxf(vl.x, 0.f); vl.y = fmaxf(vl.y, 0.f);
                vh.x = fmaxf(vh.x, 0.f); vh.y = fmaxf(vh.y, 0.f);
            }
            if (HALF_OUT) {
                __half* oh = (__half*)ouse + (size_t)b * ostr;
                *(__half2*)(oh + (size_t)ml * HW + nn) = __floats2half2_rn(vl.x, vl.y);
                *(__half2*)(oh + (size_t)mh * HW + nn) = __floats2half2_rn(vh.x, vh.y);
            } else {
                float* of = (float*)ouse + (size_t)b * ostr;
                if (RESID) {
                    const float* rp = resid + (size_t)b * ostr;
                    float2 rl = *(const float2*)(rp + (size_t)ml * HW + nn);
                    float2 rh = *(const float2*)(rp + (size_t)mh * HW + nn);
                    vl.x += rl.x; vl.y += rl.y; vh.x += rh.x; vh.y += rh.y;
                }
                *(float2*)(of + (size_t)ml * HW + nn) = vl;
                *(float2*)(of + (size_t)mh * HW + nn) = vh;
            }
        }
    }
}

// ---------------------------------------------------------------------------
// attn_out: y[b][c][n] = sum_s Vp[b][c][s] * P[b][s][n]  (K=112 single shot)
// ---------------------------------------------------------------------------
#define AO_ASTR 120
#define AO_SMEM (128*AO_ASTR*2 + 112*B_STRH*2)   // 61184

__global__ __launch_bounds__(256, 2) void attn_out_kernel(
    const __half* __restrict__ Vp, const __half* __restrict__ P, __half* __restrict__ y)
{
    extern __shared__ __align__(16) char smc[];
    const uint32_t sb = smem_u32(smc);
    const uint32_t sA = sb, sB = sb + 128*AO_ASTR*2;
    const int tid = threadIdx.x, lane = tid & 31, wid = tid >> 5;
    const int gidr = lane >> 2, t4 = lane & 3;
    const int wm = wid >> 2, wn = wid & 3;
    const int n0 = blockIdx.x * 128, c0 = blockIdx.y * 128, b = blockIdx.z;

    const __half* gA = Vp + (size_t)b * CV * 112 + (size_t)c0 * 112;
    const __half* gB = P + (size_t)b * 112 * HW + n0;

    #pragma unroll
    for (int it = 0; it < 7; ++it) {
        int idx = it * 256 + tid;
        int r = idx / 14, c = idx - r * 14;
        cpa16(sA + (uint32_t)(r * AO_ASTR + c * 8) * 2, gA + (size_t)r * 112 + c * 8);
    }
    #pragma unroll
    for (int it = 0; it < 7; ++it) {
        int idx = it * 256 + tid;
        int r = idx >> 4, c = idx & 15;
        cpa16(sB + (uint32_t)(r * B_STRH + c * 8) * 2, gB + (size_t)r * HW + c * 8);
    }
    asm volatile("cp.async.commit_group;\ncp.async.wait_group 0;" ::: "memory");
    __syncthreads();

    const int a_row = lane & 15, a_koff = (lane >> 4) * 8;
    const int b_krow = ((lane >> 3) & 1) * 8 + (lane & 7);
    const int b_noff = (lane >> 4) * 8;

    float acc[4][4][4];
    #pragma unroll
    for (int mt = 0; mt < 4; ++mt)
        #pragma unroll
        for (int nt = 0; nt < 4; ++nt)
            #pragma unroll
            for (int r = 0; r < 4; ++r) acc[mt][nt][r] = 0.f;

    #pragma unroll
    for (int s16 = 0; s16 < 7; ++s16) {
        const int kk = s16 * 16;
        uint32_t af[4][4], bf[4][2];
        #pragma unroll
        for (int mt = 0; mt < 4; ++mt) {
            int row = wm * 64 + mt * 16 + a_row;
            ldsm_x4(af[mt], sA + (uint32_t)(row * AO_ASTR + kk + a_koff) * 2);
        }
        #pragma unroll
        for (int nt2 = 0; nt2 < 2; ++nt2) {
            uint32_t r4[4];
            int ncol = wn * 32 + nt2 * 16 + b_noff;
            ldsm_x4_t(r4, sB + (uint32_t)((kk + b_krow) * B_STRH + ncol) * 2);
            bf[nt2*2][0] = r4[0]; bf[nt2*2][1] = r4[1];
            bf[nt2*2+1][0] = r4[2]; bf[nt2*2+1][1] = r4[3];
        }
        #pragma unroll
        for (int mt = 0; mt < 4; ++mt)
            #pragma unroll
            for (int nt = 0; nt < 4; ++nt)
                mma_f16(acc[mt][nt], af[mt], bf[nt]);
    }

    __half* yb = y + (size_t)b * CV * HW;
    #pragma unroll
    for (int mt = 0; mt < 4; ++mt) {
        const int ml = c0 + wm * 64 + mt * 16 + gidr;
        #pragma unroll
        for (int nt = 0; nt < 4; ++nt) {
            const int nn = n0 + wn * 32 + nt * 8 + 2 * t4;
            *(__half2*)(yb + (size_t)ml * HW + nn) =
                __floats2half2_rn(acc[mt][nt][0], acc[mt][nt][1]);
            *(__half2*)(yb + (size_t)(ml + 8) * HW + nn) =
                __floats2half2_rn(acc[mt][nt][2], acc[mt][nt][3]);
        }
    }
}

// ---------------------------------------------------------------------------
// All fp16 conversions in ONE launch.
// ---------------------------------------------------------------------------
#define XHALF (BB*CIN*HW/16)      // 1048576 -> 4096 blocks of 256
__global__ __launch_bounds__(256) void cvt_all_kernel(
    const float4* __restrict__ x, uint4* __restrict__ xh,
    const float* __restrict__ wq, const float* __restrict__ wv,
    const float* __restrict__ wo,
    __half* __restrict__ oq, __half* __restrict__ ov, __half* __restrict__ oo)
{
    if (blockIdx.x < 4096) {
        int i = blockIdx.x * 256 + threadIdx.x;
        float4 a0 = x[2*i], a1 = x[2*i+1];
        float4 b0 = x[2*(i + XHALF)], b1 = x[2*(i + XHALF)+1];
        __half2 h0 = __floats2half2_rn(a0.x, a0.y), h1 = __floats2half2_rn(a0.z, a0.w);
        __half2 h2 = __floats2half2_rn(a1.x, a1.y), h3 = __floats2half2_rn(a1.z, a1.w);
        __half2 g0 = __floats2half2_rn(b0.x, b0.y), g1 = __floats2half2_rn(b0.z, b0.w);
        __half2 g2 = __floats2half2_rn(b1.x, b1.y), g3 = __floats2half2_rn(b1.z, b1.w);
        uint4 u, v;
        u.x = *(uint32_t*)&h0; u.y = *(uint32_t*)&h1;
        u.z = *(uint32_t*)&h2; u.w = *(uint32_t*)&h3;
        v.x = *(uint32_t*)&g0; v.y = *(uint32_t*)&g1;
        v.z = *(uint32_t*)&g2; v.w = *(uint32_t*)&g3;
        xh[i] = u;
        xh[i + XHALF] = v;
    } else {
        int i = (blockIdx.x - 4096) * 256 + threadIdx.x;
        if (i < CK*CIN) oq[i] = __float2half_rn(wq[i]);
        if (i < CV*CIN) { ov[i] = __float2half_rn(wv[i]); oo[i] = __float2half_rn(wo[i]); }
    }
}

// ---------------------------------------------------------------------------
// PSP adaptive max pool, register-resident phase 1.
// One thread owns one image row (64 halves via 8x LDG.128); all 17 column-
// segment maxes are computed in registers with compile-time bounds; only the
// 17 per-row results go to smem. 4 planes per 256-thread block.
// mode 0: out[(b*C + c)*112 + cell]   (value: [c][s] pad 112)
// mode 1: out[(b*128 + cell)*C + c]   (key:   [s pad128][c])
// ---------------------------------------------------------------------------
#define RM_STR 65

template<int A, int B>
__device__ __forceinline__ float segmax(const __half2* h) {
    constexpr int a2 = (A + 1) >> 1, b2 = B >> 1;
    __half2 m2 = __floats2half2_rn(-65504.f, -65504.f);
    #pragma unroll
    for (int c = a2; c < b2; ++c) m2 = __hmax2(m2, h[c]);
    float m = fmaxf(__low2float(m2), __high2float(m2));
    if (A & 1) m = fmaxf(m, __high2float(h[A >> 1]));
    if (B & 1) m = fmaxf(m, __low2float(h[B >> 1]));
    return m;
}

__global__ __launch_bounds__(256) void psp_kernel(
    const __half* __restrict__ in, __half* __restrict__ out, int C, int mode)
{
    __shared__ float rm[4][17 * RM_STR];
    __shared__ float s8v[4][64];
    const int pl = threadIdx.x >> 6;          // plane within block (0..3)
    const int row = threadIdx.x & 63;         // this thread's image row
    const int bc = blockIdx.x * 4 + pl;
    const int b = bc / C, c = bc - b * C;
    float* rmp = rm[pl];

    // Load this row (64 halves = 8 x uint4) into registers.
    __half2 h[32];
    {
        const uint4* rp = (const uint4*)(in + (size_t)bc * 4096 + row * 64);
        uint4* hv = (uint4*)h;
        #pragma unroll
        for (int i = 0; i < 8; ++i) hv[i] = rp[i];
    }

    // 17 segment maxes, fully unrolled in registers.
    // segs: 0-2 s3 {0,22}{21,43}{42,64}; 3-8 s6; 9-16 s8.
    rmp[ 0*RM_STR + row] = segmax< 0,22>(h);
    rmp[ 1*RM_STR + row] = segmax<21,43>(h);
    rmp[ 2*RM_STR + row] = segmax<42,64>(h);
    rmp[ 3*RM_STR + row] = segmax< 0,11>(h);
    rmp[ 4*RM_STR + row] = segmax<10,22>(h);
    rmp[ 5*RM_STR + row] = segmax<21,32>(h);
    rmp[ 6*RM_STR + row] = segmax<32,43>(h);
    rmp[ 7*RM_STR + row] = segmax<42,54>(h);
    rmp[ 8*RM_STR + row] = segmax<53,64>(h);
    rmp[ 9*RM_STR + row] = segmax< 0, 8>(h);
    rmp[10*RM_STR + row] = segmax< 8,16>(h);
    rmp[11*RM_STR + row] = segmax<16,24>(h);
    rmp[12*RM_STR + row] = segmax<24,32>(h);
    rmp[13*RM_STR + row] = segmax<32,40>(h);
    rmp[14*RM_STR + row] = segmax<40,48>(h);
    rmp[15*RM_STR + row] = segmax<48,56>(h);
    rmp[16*RM_STR + row] = segmax<56,64>(h);
    __syncthreads();

    // Phase 2a: s=8 cells (64 threads = 64 cells).
    {
        int i = row >> 3, j = row & 7;
        float m = rmp[(9 + j) * RM_STR + i * 8];
        #pragma unroll
        for (int r = 1; r < 8; ++r) m = fmaxf(m, rmp[(9 + j) * RM_STR + i * 8 + r]);
        s8v[pl][row] = m;
        int cell = 46 + row;
        size_t o = mode ? ((size_t)(b * 128 + cell) * C + c)
                        : ((size_t)bc * 112 + cell);
        out[o] = __float2half_rn(m);
    }
    __syncthreads();

    // Phase 2b: s=6 (36 cells), s=3 (9 cells), s=1 (from s8 cells).
    float m = -3.402823e38f;
    int cell = -1;
    if (row < 36) {
        const int st[6] = {0,10,21,32,42,53}, en[6] = {11,22,32,43,54,64};
        int i = row / 6, j = row - i * 6;
        m = rmp[(3 + j) * RM_STR + st[i]];
        for (int r = st[i] + 1; r < en[i]; ++r) m = fmaxf(m, rmp[(3 + j) * RM_STR + r]);
        cell = 10 + row;
    } else if (row < 45) {
        const int st[3] = {0,21,42}, en[3] = {22,43,64};
        int t = row - 36, i = t / 3, j = t - i * 3;
        m = rmp[j * RM_STR + st[i]];
        for (int r = st[i] + 1; r < en[i]; ++r) m = fmaxf(m, rmp[j * RM_STR + r]);
        cell = 1 + t;
    } else if (row == 45) {
        m = s8v[pl][0];
        for (int i = 1; i < 64; ++i) m = fmaxf(m, s8v[pl][i]);
        cell = 0;
    }
    if (cell >= 0) {
        size_t o = mode ? ((size_t)(b * 128 + cell) * C + c)
                        : ((size_t)bc * 112 + cell);
        out[o] = __float2half_rn(m);
    }
}

// ---------------------------------------------------------------------------
extern "C" void kernel_launch(void* const* d_in, const int* in_sizes, int n_in,
                              void* d_out, int out_size)
{
    const float* x        = (const float*)d_in[0];
    const float* qk_w     = (const float*)d_in[1];
    const float* qk_gamma = (const float*)d_in[2];
    const float* qk_beta  = (const float*)d_in[3];
    const float* qk_mean  = (const float*)d_in[4];
    const float* qk_var   = (const float*)d_in[5];
    const float* v_w      = (const float*)d_in[6];
    const float* v_gamma  = (const float*)d_in[7];
    const float* v_beta   = (const float*)d_in[8];
    const float* v_mean   = (const float*)d_in[9];
    const float* v_var    = (const float*)d_in[10];
    const float* out_w    = (const float*)d_in[11];
    const float* o_gamma  = (const float*)d_in[12];
    const float* o_beta   = (const float*)d_in[13];
    const float* o_mean   = (const float*)d_in[14];
    const float* o_var    = (const float*)d_in[15];
    float* out = (float*)d_out;

    __half *xh, *qkh, *valh, *keyh, *vpsp, *ph, *yh, *wq, *wv, *wo;
    cudaGetSymbolAddress((void**)&xh,   g_xh);
    cudaGetSymbolAddress((void**)&qkh,  g_qkh);
    cudaGetSymbolAddress((void**)&valh, g_valh);
    cudaGetSymbolAddress((void**)&keyh, g_keyh);
    cudaGetSymbolAddress((void**)&vpsp, g_vpsp);
    cudaGetSymbolAddress((void**)&ph,   g_ph);
    cudaGetSymbolAddress((void**)&yh,   g_yh);
    cudaGetSymbolAddress((void**)&wq,   g_wq);
    cudaGetSymbolAddress((void**)&wv,   g_wv);
    cudaGetSymbolAddress((void**)&wo,   g_wo);

    cudaFuncSetAttribute(gemm_kernel<true, true, true, false, true, false>,
                         cudaFuncAttributeMaxDynamicSharedMemorySize, GEMM_SMEM);
    cudaFuncSetAttribute(gemm_kernel<false, false, false, false, true, true>,
                         cudaFuncAttributeMaxDynamicSharedMemorySize, GEMM_SMEM);
    cudaFuncSetAttribute(gemm_kernel<false, true, false, true, false, false>,
                         cudaFuncAttributeMaxDynamicSharedMemorySize, GEMM_SMEM);
    cudaFuncSetAttribute(attn_out_kernel,
                         cudaFuncAttributeMaxDynamicSharedMemorySize, AO_SMEM);

    // Side stream + events, created once on the first (uncaptured) call.
    static cudaStream_t s1 = nullptr;
    static cudaEvent_t ev_fork = nullptr, ev_join = nullptr;
    if (s1 == nullptr) {
        cudaStreamCreateWithFlags(&s1, cudaStreamNonBlocking);
        cudaEventCreateWithFlags(&ev_fork, cudaEventDisableTiming);
        cudaEventCreateWithFlags(&ev_join, cudaEventDisableTiming);
    }

    // 0) all fp16 conversions, one launch
    cvt_all_kernel<<<4096 + 1024, 256>>>(
        (const float4*)x, (uint4*)xh, qk_w, v_w, out_w, wq, wv, wo);

    // 1+2) fused: qk = relu(bn(conv(x,wq))), val = relu(bn(conv(x,wv)))
    gemm_kernel<true, true, true, false, true, false><<<dim3(32, 6, BB), 256, GEMM_SMEM>>>(
        wq, 0, xh, (size_t)CIN*HW, qk_gamma, qk_beta, qk_mean, qk_var,
        1.f, nullptr, qkh, (size_t)CK*HW, CIN,
        wv, v_gamma, v_beta, v_mean, v_var, valh, (size_t)CV*HW);

    // Fork: psp_val runs on side stream, overlapped with psp_qk + scores.
    cudaEventRecord(ev_fork, 0);
    cudaStreamWaitEvent(s1, ev_fork, 0);
    psp_kernel<<<BB * CV / 4, 256, 0, s1>>>(valh, vpsp, CV, 0);
    cudaEventRecord(ev_join, s1);

    // 3a) key = psp(qk) [s][c]   (capture stream)
    psp_kernel<<<BB * CK / 4, 256>>>(qkh, keyh, CK, 1);
    // 4) P = softmax_s( (key @ qk) / 16 )  -- softmax fused into GEMM epilogue
    gemm_kernel<false, false, false, false, true, true><<<dim3(32, 1, BB), 256, GEMM_SMEM>>>(
        keyh, (size_t)128*CK, qkh, (size_t)CK*HW, nullptr, nullptr, nullptr, nullptr,
        0.0625f, nullptr, ph, (size_t)112*HW, CK,
        nullptr, nullptr, nullptr, nullptr, nullptr, nullptr, 0);

    // Join: attn_out needs vpsp (side stream) and ph (capture stream).
    cudaStreamWaitEvent(0, ev_join, 0);

    // 5) y[c][n] = value[c][s] @ p[s][n]
    attn_out_kernel<<<dim3(32, 4, BB), 256, AO_SMEM>>>(vpsp, ph, yh);
    // 6) out = x + bn(conv(y, wo))
    gemm_kernel<false, true, false, true, false, false><<<dim3(32, 4, BB), 256, GEMM_SMEM>>>(
        wo, 0, yh, (size_t)CV*HW, o_gamma, o_beta, o_mean, o_var,
        1.f, x, out, (size_t)CIN*HW, CV,
        nullptr, nullptr, nullptr, nullptr, nullptr, nullptr, 0);
}

// round 14
// speedup vs baseline: 1.5836x; 1.0209x over previous
#include <cuda_runtime.h>
#include <cuda_fp16.h>
#include <cstdint>
#include <math.h>

#define BB   8
#define CIN  512
#define CK   256
#define CV   512
#define HW   4096
#define SS   110

// Scratch (__device__ globals are zero-initialized; pad regions never written
// stay zero -> free zero-padding).
__device__ __align__(16) __half g_xh    [BB*CIN*HW];    // [b][k][n]
__device__ __align__(16) __half g_qkh   [BB*CK*HW];     // [b][c][n]
__device__ __align__(16) __half g_valh  [BB*CV*HW];     // [b][c][n]
__device__ __align__(16) __half g_keyh  [BB*128*CK];    // [b][s(pad128)][c]
__device__ __align__(16) __half g_vpsp  [BB*CV*112];    // [b][c][s(pad112)]
__device__ __align__(16) __half g_yh    [BB*CV*HW];     // [b][c][n]
__device__ __align__(16) __half g_wq    [CK*CIN];
__device__ __align__(16) __half g_wv    [CV*CIN];
__device__ __align__(16) __half g_wo    [CIN*CV];

// ---------------------------------------------------------------------------
__device__ __forceinline__ uint32_t smem_u32(const void* p) {
    uint32_t a;
    asm("{ .reg .u64 t; cvta.to.shared.u64 t, %1; cvt.u32.u64 %0, t; }" : "=r"(a) : "l"(p));
    return a;
}
__device__ __forceinline__ void ldsm_x4(uint32_t* r, uint32_t addr) {
    asm volatile("ldmatrix.sync.aligned.m8n8.x4.shared.b16 {%0,%1,%2,%3}, [%4];"
        : "=r"(r[0]), "=r"(r[1]), "=r"(r[2]), "=r"(r[3]) : "r"(addr));
}
__device__ __forceinline__ void ldsm_x4_t(uint32_t* r, uint32_t addr) {
    asm volatile("ldmatrix.sync.aligned.m8n8.x4.trans.shared.b16 {%0,%1,%2,%3}, [%4];"
        : "=r"(r[0]), "=r"(r[1]), "=r"(r[2]), "=r"(r[3]) : "r"(addr));
}
__device__ __forceinline__ void mma_f16(float* c, const uint32_t* a, const uint32_t* b) {
    asm volatile(
        "mma.sync.aligned.m16n8k16.row.col.f32.f16.f16.f32 "
        "{%0,%1,%2,%3}, {%4,%5,%6,%7}, {%8,%9}, {%0,%1,%2,%3};"
        : "+f"(c[0]), "+f"(c[1]), "+f"(c[2]), "+f"(c[3])
        : "r"(a[0]), "r"(a[1]), "r"(a[2]), "r"(a[3]), "r"(b[0]), "r"(b[1]));
}
__device__ __forceinline__ void cpa16(uint32_t dst, const void* src) {
    asm volatile("cp.async.cg.shared.global [%0], [%1], 16;" :: "r"(dst), "l"(src));
}

// ---------------------------------------------------------------------------
// Generalized GEMM: out[b,m,n] = epi( sum_k A[m,k] * B[b,k,n] )
// CTA 128m x 128n, 8 warps (2x4), warp 64x32. K staged 32, 4-stage pipeline.
// (75.8KB smem/CTA -> 2 CTAs/SM resident; proven best config.)
// ---------------------------------------------------------------------------
#define A_STRH 40
#define B_STRH 136
#define A_STG  (128*A_STRH*2)              // 10240 B
#define B_STG  (32*B_STRH*2)               // 8704 B
#define STG    (A_STG + B_STG)             // 18944 B
#define NSTAGE 4
#define GEMM_SMEM (NSTAGE*STG)             // 75776 B

template<bool FUSED, bool RELU, bool RESID, bool HALF_OUT>
__global__ __launch_bounds__(256, 2) void gemm_kernel(
    const __half* __restrict__ A, size_t a_bstride,
    const __half* __restrict__ Bm, size_t b_bstride,
    const float* __restrict__ gamma, const float* __restrict__ beta,
    const float* __restrict__ mean,  const float* __restrict__ var,
    const float* __restrict__ resid,
    void* __restrict__ outp, size_t o_bstride,
    int Ktot,
    const __half* __restrict__ A2,
    const float* __restrict__ gamma2, const float* __restrict__ beta2,
    const float* __restrict__ mean2,  const float* __restrict__ var2,
    void* __restrict__ outp2, size_t o_bstride2)
{
    extern __shared__ __align__(16) char smc[];
    const uint32_t sb = smem_u32(smc);
    const int tid = threadIdx.x, lane = tid & 31, wid = tid >> 5;
    const int gidr = lane >> 2, t4 = lane & 3;
    const int wm = wid >> 2, wn = wid & 3;
    const int n0 = blockIdx.x * 128, b = blockIdx.z;
    const int NK = Ktot >> 5;

    int m0 = blockIdx.y * 128;
    const __half* Ause = A;
    const float *g_ = gamma, *be_ = beta, *me_ = mean, *va_ = var;
    void* ouse = outp;
    size_t ostr = o_bstride;
    if (FUSED && blockIdx.y >= 2) {
        m0 = (blockIdx.y - 2) * 128;
        Ause = A2; g_ = gamma2; be_ = beta2; me_ = mean2; va_ = var2;
        ouse = outp2; ostr = o_bstride2;
    }

    const __half* gA = Ause + (size_t)b * a_bstride + (size_t)m0 * Ktot;
    const __half* gB = Bm + (size_t)b * b_bstride + n0;

    auto load_stage = [&](int s) {
        const uint32_t base = sb + (uint32_t)(s & (NSTAGE-1)) * STG;
        #pragma unroll
        for (int it = 0; it < 2; ++it) {            // A: 128r x 4 chunks
            int idx = it * 256 + tid;
            int r = idx >> 2, c = idx & 3;
            cpa16(base + (uint32_t)(r * A_STRH + c * 8) * 2,
                  gA + (size_t)r * Ktot + s * 32 + c * 8);
        }
        #pragma unroll
        for (int it = 0; it < 2; ++it) {            // B: 32r x 16 chunks
            int idx = it * 256 + tid;
            int r = idx >> 4, c = idx & 15;
            cpa16(base + A_STG + (uint32_t)(r * B_STRH + c * 8) * 2,
                  gB + (size_t)(s * 32 + r) * HW + c * 8);
        }
        asm volatile("cp.async.commit_group;" ::: "memory");
    };

    float acc[4][4][4];
    #pragma unroll
    for (int mt = 0; mt < 4; ++mt)
        #pragma unroll
        for (int nt = 0; nt < 4; ++nt)
            #pragma unroll
            for (int r = 0; r < 4; ++r) acc[mt][nt][r] = 0.f;

    for (int s = 0; s < NSTAGE - 1 && s < NK; ++s) load_stage(s);
    asm volatile("cp.async.wait_group 2;" ::: "memory");
    __syncthreads();

    const int a_row = lane & 15, a_koff = (lane >> 4) * 8;
    const int b_krow = ((lane >> 3) & 1) * 8 + (lane & 7);
    const int b_noff = (lane >> 4) * 8;

    for (int kt = 0; kt < NK; ++kt) {
        if (kt + NSTAGE - 1 < NK) load_stage(kt + NSTAGE - 1);
        else asm volatile("cp.async.commit_group;" ::: "memory");

        const uint32_t sA = sb + (uint32_t)(kt & (NSTAGE-1)) * STG;
        const uint32_t sB = sA + A_STG;
        #pragma unroll
        for (int s16 = 0; s16 < 2; ++s16) {
            const int kk = s16 * 16;
            uint32_t af[4][4], bf[4][2];
            #pragma unroll
            for (int mt = 0; mt < 4; ++mt) {
                int row = wm * 64 + mt * 16 + a_row;
                ldsm_x4(af[mt], sA + (uint32_t)(row * A_STRH + kk + a_koff) * 2);
            }
            #pragma unroll
            for (int nt2 = 0; nt2 < 2; ++nt2) {
                uint32_t r4[4];
                int ncol = wn * 32 + nt2 * 16 + b_noff;
                ldsm_x4_t(r4, sB + (uint32_t)((kk + b_krow) * B_STRH + ncol) * 2);
                bf[nt2*2][0] = r4[0]; bf[nt2*2][1] = r4[1];
                bf[nt2*2+1][0] = r4[2]; bf[nt2*2+1][1] = r4[3];
            }
            #pragma unroll
            for (int mt = 0; mt < 4; ++mt)
                #pragma unroll
                for (int nt = 0; nt < 4; ++nt)
                    mma_f16(acc[mt][nt], af[mt], bf[nt]);
        }
        asm volatile("cp.async.wait_group 2;" ::: "memory");
        __syncthreads();
    }

    // Epilogue: BN (+ReLU) (+residual)
    #pragma unroll
    for (int mt = 0; mt < 4; ++mt) {
        const int ml = m0 + wm * 64 + mt * 16 + gidr;
        const int mh = ml + 8;
        const float scl = g_[ml] * rsqrtf(va_[ml] + 1e-5f);
        const float ttl = be_[ml] - me_[ml] * scl;
        const float sch = g_[mh] * rsqrtf(va_[mh] + 1e-5f);
        const float tth = be_[mh] - me_[mh] * sch;
        #pragma unroll
        for (int nt = 0; nt < 4; ++nt) {
            const int nn = n0 + wn * 32 + nt * 8 + 2 * t4;
            float2 vl, vh;
            vl.x = acc[mt][nt][0] * scl + ttl;
            vl.y = acc[mt][nt][1] * scl + ttl;
            vh.x = acc[mt][nt][2] * sch + tth;
            vh.y = acc[mt][nt][3] * sch + tth;
            if (RELU) {
                vl.x = fmaxf(vl.x, 0.f); vl.y = fmaxf(vl.y, 0.f);
                vh.x = fmaxf(vh.x, 0.f); vh.y = fmaxf(vh.y, 0.f);
            }
            if (HALF_OUT) {
                __half* oh = (__half*)ouse + (size_t)b * ostr;
                *(__half2*)(oh + (size_t)ml * HW + nn) = __floats2half2_rn(vl.x, vl.y);
                *(__half2*)(oh + (size_t)mh * HW + nn) = __floats2half2_rn(vh.x, vh.y);
            } else {
                float* of = (float*)ouse + (size_t)b * ostr;
                if (RESID) {
                    const float* rp = resid + (size_t)b * ostr;
                    float2 rl = *(const float2*)(rp + (size_t)ml * HW + nn);
                    float2 rh = *(const float2*)(rp + (size_t)mh * HW + nn);
                    vl.x += rl.x; vl.y += rl.y; vh.x += rh.x; vh.y += rh.y;
                }
                *(float2*)(of + (size_t)ml * HW + nn) = vl;
                *(float2*)(of + (size_t)mh * HW + nn) = vh;
            }
        }
    }
}

// ---------------------------------------------------------------------------
// Fused attention: per CTA (n-block, batch):
//   Phase 1: S = (key @ qk)/16 via mma pipeline (K=256), column softmax over
//            s (<SS) in registers, P stored fp16 to smem B-tile layout.
//   Phase 2: loop 4 Vp tiles [128c x 112s]: y[c][n] = Vp @ P from smem.
// smem: [0,30464) sP; [30464,61184) sVp; [63232,65280) red. Fits GEMM_SMEM.
// ---------------------------------------------------------------------------
#define AO_ASTR 120
#define ATT_SA  (112*B_STRH*2)          // 30464
#define ATT_RED (ATT_SA + 128*AO_ASTR*2)// 61184 (red floats at 63232.. OK)

__global__ __launch_bounds__(256, 2) void attn_kernel(
    const __half* __restrict__ Kh, const __half* __restrict__ Q,
    const __half* __restrict__ Vp, __half* __restrict__ y)
{
    extern __shared__ __align__(16) char smc[];
    const uint32_t sb = smem_u32(smc);
    const int tid = threadIdx.x, lane = tid & 31, wid = tid >> 5;
    const int gidr = lane >> 2, t4 = lane & 3;
    const int wm = wid >> 2, wn = wid & 3;
    const int n0 = blockIdx.x * 128, b = blockIdx.y;

    const __half* gA = Kh + (size_t)b * 128 * CK;
    const __half* gB = Q + (size_t)b * CK * HW + n0;

    auto load_stage = [&](int s) {
        const uint32_t base = sb + (uint32_t)(s & (NSTAGE-1)) * STG;
        #pragma unroll
        for (int it = 0; it < 2; ++it) {
            int idx = it * 256 + tid;
            int r = idx >> 2, c = idx & 3;
            cpa16(base + (uint32_t)(r * A_STRH + c * 8) * 2,
                  gA + (size_t)r * CK + s * 32 + c * 8);
        }
        #pragma unroll
        for (int it = 0; it < 2; ++it) {
            int idx = it * 256 + tid;
            int r = idx >> 4, c = idx & 15;
            cpa16(base + A_STG + (uint32_t)(r * B_STRH + c * 8) * 2,
                  gB + (size_t)(s * 32 + r) * HW + c * 8);
        }
        asm volatile("cp.async.commit_group;" ::: "memory");
    };

    float acc[4][4][4];
    #pragma unroll
    for (int mt = 0; mt < 4; ++mt)
        #pragma unroll
        for (int nt = 0; nt < 4; ++nt)
            #pragma unroll
            for (int r = 0; r < 4; ++r) acc[mt][nt][r] = 0.f;

    for (int s = 0; s < NSTAGE - 1; ++s) load_stage(s);
    asm volatile("cp.async.wait_group 2;" ::: "memory");
    __syncthreads();

    const int a_row = lane & 15, a_koff = (lane >> 4) * 8;
    const int b_krow = ((lane >> 3) & 1) * 8 + (lane & 7);
    const int b_noff = (lane >> 4) * 8;

    #pragma unroll 1
    for (int kt = 0; kt < 8; ++kt) {                // K = 256
        if (kt + NSTAGE - 1 < 8) load_stage(kt + NSTAGE - 1);
        else asm volatile("cp.async.commit_group;" ::: "memory");

        const uint32_t sA = sb + (uint32_t)(kt & (NSTAGE-1)) * STG;
        const uint32_t sB = sA + A_STG;
        #pragma unroll
        for (int s16 = 0; s16 < 2; ++s16) {
            const int kk = s16 * 16;
            uint32_t af[4][4], bf[4][2];
            #pragma unroll
            for (int mt = 0; mt < 4; ++mt) {
                int row = wm * 64 + mt * 16 + a_row;
                ldsm_x4(af[mt], sA + (uint32_t)(row * A_STRH + kk + a_koff) * 2);
            }
            #pragma unroll
            for (int nt2 = 0; nt2 < 2; ++nt2) {
                uint32_t r4[4];
                int ncol = wn * 32 + nt2 * 16 + b_noff;
                ldsm_x4_t(r4, sB + (uint32_t)((kk + b_krow) * B_STRH + ncol) * 2);
                bf[nt2*2][0] = r4[0]; bf[nt2*2][1] = r4[1];
                bf[nt2*2+1][0] = r4[2]; bf[nt2*2+1][1] = r4[3];
            }
            #pragma unroll
            for (int mt = 0; mt < 4; ++mt)
                #pragma unroll
                for (int nt = 0; nt < 4; ++nt)
                    mma_f16(acc[mt][nt], af[mt], bf[nt]);
        }
        asm volatile("cp.async.wait_group 2;" ::: "memory");
        __syncthreads();
    }

    // Column softmax over s (valid rows < SS), P -> smem fp16.
    {
        float* red = (float*)(smc + ATT_RED + 2048);  // 512 floats at 63232
        float cmax[4][2], csum[4][2];
        #pragma unroll
        for (int nt = 0; nt < 4; ++nt) { cmax[nt][0] = -3.4e38f; cmax[nt][1] = -3.4e38f; }
        #pragma unroll
        for (int mt = 0; mt < 4; ++mt) {
            const int r0 = wm * 64 + mt * 16 + gidr, r1 = r0 + 8;
            #pragma unroll
            for (int nt = 0; nt < 4; ++nt) {
                #pragma unroll
                for (int r = 0; r < 4; ++r) acc[mt][nt][r] *= 0.0625f;
                if (r0 < SS) {
                    cmax[nt][0] = fmaxf(cmax[nt][0], acc[mt][nt][0]);
                    cmax[nt][1] = fmaxf(cmax[nt][1], acc[mt][nt][1]);
                }
                if (r1 < SS) {
                    cmax[nt][0] = fmaxf(cmax[nt][0], acc[mt][nt][2]);
                    cmax[nt][1] = fmaxf(cmax[nt][1], acc[mt][nt][3]);
                }
            }
        }
        #pragma unroll
        for (int nt = 0; nt < 4; ++nt)
            #pragma unroll
            for (int j = 0; j < 2; ++j) {
                float v = cmax[nt][j];
                v = fmaxf(v, __shfl_xor_sync(0xffffffffu, v, 4));
                v = fmaxf(v, __shfl_xor_sync(0xffffffffu, v, 8));
                v = fmaxf(v, __shfl_xor_sync(0xffffffffu, v, 16));
                cmax[nt][j] = v;
            }
        if (gidr == 0)
            #pragma unroll
            for (int nt = 0; nt < 4; ++nt)
                #pragma unroll
                for (int j = 0; j < 2; ++j)
                    red[wm*128 + wn*32 + nt*8 + 2*t4 + j] = cmax[nt][j];
        __syncthreads();
        #pragma unroll
        for (int nt = 0; nt < 4; ++nt)
            #pragma unroll
            for (int j = 0; j < 2; ++j)
                cmax[nt][j] = fmaxf(cmax[nt][j], red[(wm^1)*128 + wn*32 + nt*8 + 2*t4 + j]);

        #pragma unroll
        for (int nt = 0; nt < 4; ++nt) { csum[nt][0] = 0.f; csum[nt][1] = 0.f; }
        #pragma unroll
        for (int mt = 0; mt < 4; ++mt) {
            const int r0 = wm * 64 + mt * 16 + gidr, r1 = r0 + 8;
            #pragma unroll
            for (int nt = 0; nt < 4; ++nt) {
                float e0 = (r0 < SS) ? __expf(acc[mt][nt][0] - cmax[nt][0]) : 0.f;
                float e1 = (r0 < SS) ? __expf(acc[mt][nt][1] - cmax[nt][1]) : 0.f;
                float e2 = (r1 < SS) ? __expf(acc[mt][nt][2] - cmax[nt][0]) : 0.f;
                float e3 = (r1 < SS) ? __expf(acc[mt][nt][3] - cmax[nt][1]) : 0.f;
                acc[mt][nt][0] = e0; acc[mt][nt][1] = e1;
                acc[mt][nt][2] = e2; acc[mt][nt][3] = e3;
                csum[nt][0] += e0 + e2; csum[nt][1] += e1 + e3;
            }
        }
        #pragma unroll
        for (int nt = 0; nt < 4; ++nt)
            #pragma unroll
            for (int j = 0; j < 2; ++j) {
                float v = csum[nt][j];
                v += __shfl_xor_sync(0xffffffffu, v, 4);
                v += __shfl_xor_sync(0xffffffffu, v, 8);
                v += __shfl_xor_sync(0xffffffffu, v, 16);
                csum[nt][j] = v;
            }
        if (gidr == 0)
            #pragma unroll
            for (int nt = 0; nt < 4; ++nt)
                #pragma unroll
                for (int j = 0; j < 2; ++j)
                    red[256 + wm*128 + wn*32 + nt*8 + 2*t4 + j] = csum[nt][j];
        __syncthreads();
        #pragma unroll
        for (int nt = 0; nt < 4; ++nt)
            #pragma unroll
            for (int j = 0; j < 2; ++j)
                csum[nt][j] += red[256 + (wm^1)*128 + wn*32 + nt*8 + 2*t4 + j];
        __syncthreads();   // red reads done before sP (offset 0..30464) reuse

        __half* sP = (__half*)smc;
        #pragma unroll
        for (int mt = 0; mt < 4; ++mt) {
            const int r0 = wm * 64 + mt * 16 + gidr, r1 = r0 + 8;
            #pragma unroll
            for (int nt = 0; nt < 4; ++nt) {
                const int nn = wn * 32 + nt * 8 + 2 * t4;
                const float i0 = 1.f / csum[nt][0], i1 = 1.f / csum[nt][1];
                if (r0 < 112)
                    *(__half2*)(sP + r0 * B_STRH + nn) =
                        __floats2half2_rn(acc[mt][nt][0] * i0, acc[mt][nt][1] * i1);
                if (r1 < 112)
                    *(__half2*)(sP + r1 * B_STRH + nn) =
                        __floats2half2_rn(acc[mt][nt][2] * i0, acc[mt][nt][3] * i1);
            }
        }
    }
    __syncthreads();

    // Phase 2: y[c][n] = Vp[c][s] @ P[s][n], 4 Vp tiles of 128c.
    const uint32_t sSP = sb;
    const uint32_t sVA = sb + ATT_SA;
    __half* yb = y + (size_t)b * CV * HW;

    #pragma unroll 1
    for (int cb = 0; cb < 4; ++cb) {
        if (cb) __syncthreads();
        const __half* gV = Vp + (size_t)b * CV * 112 + (size_t)(cb * 128) * 112;
        #pragma unroll
        for (int it = 0; it < 7; ++it) {
            int idx = it * 256 + tid;
            int r = idx / 14, c = idx - r * 14;
            cpa16(sVA + (uint32_t)(r * AO_ASTR + c * 8) * 2, gV + (size_t)r * 112 + c * 8);
        }
        asm volatile("cp.async.commit_group;\ncp.async.wait_group 0;" ::: "memory");
        __syncthreads();

        #pragma unroll
        for (int mt = 0; mt < 4; ++mt)
            #pragma unroll
            for (int nt = 0; nt < 4; ++nt)
                #pragma unroll
                for (int r = 0; r < 4; ++r) acc[mt][nt][r] = 0.f;

        #pragma unroll
        for (int s16 = 0; s16 < 7; ++s16) {
            const int kk = s16 * 16;
            uint32_t af[4][4], bf[4][2];
            #pragma unroll
            for (int mt = 0; mt < 4; ++mt) {
                int row = wm * 64 + mt * 16 + a_row;
                ldsm_x4(af[mt], sVA + (uint32_t)(row * AO_ASTR + kk + a_koff) * 2);
            }
            #pragma unroll
            for (int nt2 = 0; nt2 < 2; ++nt2) {
                uint32_t r4[4];
                int ncol = wn * 32 + nt2 * 16 + b_noff;
                ldsm_x4_t(r4, sSP + (uint32_t)((kk + b_krow) * B_STRH + ncol) * 2);
                bf[nt2*2][0] = r4[0]; bf[nt2*2][1] = r4[1];
                bf[nt2*2+1][0] = r4[2]; bf[nt2*2+1][1] = r4[3];
            }
            #pragma unroll
            for (int mt = 0; mt < 4; ++mt)
                #pragma unroll
                for (int nt = 0; nt < 4; ++nt)
                    mma_f16(acc[mt][nt], af[mt], bf[nt]);
        }

        #pragma unroll
        for (int mt = 0; mt < 4; ++mt) {
            const int ml = cb * 128 + wm * 64 + mt * 16 + gidr;
            #pragma unroll
            for (int nt = 0; nt < 4; ++nt) {
                const int nn = n0 + wn * 32 + nt * 8 + 2 * t4;
                *(__half2*)(yb + (size_t)ml * HW + nn) =
                    __floats2half2_rn(acc[mt][nt][0], acc[mt][nt][1]);
                *(__half2*)(yb + (size_t)(ml + 8) * HW + nn) =
                    __floats2half2_rn(acc[mt][nt][2], acc[mt][nt][3]);
            }
        }
    }
}

// ---------------------------------------------------------------------------
// All fp16 conversions in ONE launch.
// ---------------------------------------------------------------------------
#define XHALF (BB*CIN*HW/16)      // 1048576 -> 4096 blocks of 256
__global__ __launch_bounds__(256) void cvt_all_kernel(
    const float4* __restrict__ x, uint4* __restrict__ xh,
    const float* __restrict__ wq, const float* __restrict__ wv,
    const float* __restrict__ wo,
    __half* __restrict__ oq, __half* __restrict__ ov, __half* __restrict__ oo)
{
    if (blockIdx.x < 4096) {
        int i = blockIdx.x * 256 + threadIdx.x;
        float4 a0 = x[2*i], a1 = x[2*i+1];
        float4 b0 = x[2*(i + XHALF)], b1 = x[2*(i + XHALF)+1];
        __half2 h0 = __floats2half2_rn(a0.x, a0.y), h1 = __floats2half2_rn(a0.z, a0.w);
        __half2 h2 = __floats2half2_rn(a1.x, a1.y), h3 = __floats2half2_rn(a1.z, a1.w);
        __half2 g0 = __floats2half2_rn(b0.x, b0.y), g1 = __floats2half2_rn(b0.z, b0.w);
        __half2 g2 = __floats2half2_rn(b1.x, b1.y), g3 = __floats2half2_rn(b1.z, b1.w);
        uint4 u, v;
        u.x = *(uint32_t*)&h0; u.y = *(uint32_t*)&h1;
        u.z = *(uint32_t*)&h2; u.w = *(uint32_t*)&h3;
        v.x = *(uint32_t*)&g0; v.y = *(uint32_t*)&g1;
        v.z = *(uint32_t*)&g2; v.w = *(uint32_t*)&g3;
        xh[i] = u;
        xh[i + XHALF] = v;
    } else {
        int i = (blockIdx.x - 4096) * 256 + threadIdx.x;
        if (i < CK*CIN) oq[i] = __float2half_rn(wq[i]);
        if (i < CV*CIN) { ov[i] = __float2half_rn(wv[i]); oo[i] = __float2half_rn(wo[i]); }
    }
}

// ---------------------------------------------------------------------------
// PSP adaptive max pool, register-resident phase 1.
// One thread owns one image row (64 halves via 8x LDG.128); 17 column-segment
// maxes in registers; only per-row results go to smem. 4 planes per block.
// mode 0: out[(b*C + c)*112 + cell]   (value: [c][s] pad 112)
// mode 1: out[(b*128 + cell)*C + c]   (key:   [s pad128][c])
// ---------------------------------------------------------------------------
#define RM_STR 65

template<int A, int B>
__device__ __forceinline__ float segmax(const __half2* h) {
    constexpr int a2 = (A + 1) >> 1, b2 = B >> 1;
    __half2 m2 = __floats2half2_rn(-65504.f, -65504.f);
    #pragma unroll
    for (int c = a2; c < b2; ++c) m2 = __hmax2(m2, h[c]);
    float m = fmaxf(__low2float(m2), __high2float(m2));
    if (A & 1) m = fmaxf(m, __high2float(h[A >> 1]));
    if (B & 1) m = fmaxf(m, __low2float(h[B >> 1]));
    return m;
}

__global__ __launch_bounds__(256) void psp_kernel(
    const __half* __restrict__ in, __half* __restrict__ out, int C, int mode)
{
    __shared__ float rm[4][17 * RM_STR];
    __shared__ float s8v[4][64];
    const int pl = threadIdx.x >> 6;
    const int row = threadIdx.x & 63;
    const int bc = blockIdx.x * 4 + pl;
    const int b = bc / C, c = bc - b * C;
    float* rmp = rm[pl];

    __half2 h[32];
    {
        const uint4* rp = (const uint4*)(in + (size_t)bc * 4096 + row * 64);
        uint4* hv = (uint4*)h;
        #pragma unroll
        for (int i = 0; i < 8; ++i) hv[i] = rp[i];
    }

    rmp[ 0*RM_STR + row] = segmax< 0,22>(h);
    rmp[ 1*RM_STR + row] = segmax<21,43>(h);
    rmp[ 2*RM_STR + row] = segmax<42,64>(h);
    rmp[ 3*RM_STR + row] = segmax< 0,11>(h);
    rmp[ 4*RM_STR + row] = segmax<10,22>(h);
    rmp[ 5*RM_STR + row] = segmax<21,32>(h);
    rmp[ 6*RM_STR + row] = segmax<32,43>(h);
    rmp[ 7*RM_STR + row] = segmax<42,54>(h);
    rmp[ 8*RM_STR + row] = segmax<53,64>(h);
    rmp[ 9*RM_STR + row] = segmax< 0, 8>(h);
    rmp[10*RM_STR + row] = segmax< 8,16>(h);
    rmp[11*RM_STR + row] = segmax<16,24>(h);
    rmp[12*RM_STR + row] = segmax<24,32>(h);
    rmp[13*RM_STR + row] = segmax<32,40>(h);
    rmp[14*RM_STR + row] = segmax<40,48>(h);
    rmp[15*RM_STR + row] = segmax<48,56>(h);
    rmp[16*RM_STR + row] = segmax<56,64>(h);
    __syncthreads();

    {
        int i = row >> 3, j = row & 7;
        float m = rmp[(9 + j) * RM_STR + i * 8];
        #pragma unroll
        for (int r = 1; r < 8; ++r) m = fmaxf(m, rmp[(9 + j) * RM_STR + i * 8 + r]);
        s8v[pl][row] = m;
        int cell = 46 + row;
        size_t o = mode ? ((size_t)(b * 128 + cell) * C + c)
                        : ((size_t)bc * 112 + cell);
        out[o] = __float2half_rn(m);
    }
    __syncthreads();

    float m = -3.402823e38f;
    int cell = -1;
    if (row < 36) {
        const int st[6] = {0,10,21,32,42,53}, en[6] = {11,22,32,43,54,64};
        int i = row / 6, j = row - i * 6;
        m = rmp[(3 + j) * RM_STR + st[i]];
        for (int r = st[i] + 1; r < en[i]; ++r) m = fmaxf(m, rmp[(3 + j) * RM_STR + r]);
        cell = 10 + row;
    } else if (row < 45) {
        const int st[3] = {0,21,42}, en[3] = {22,43,64};
        int t = row - 36, i = t / 3, j = t - i * 3;
        m = rmp[j * RM_STR + st[i]];
        for (int r = st[i] + 1; r < en[i]; ++r) m = fmaxf(m, rmp[j * RM_STR + r]);
        cell = 1 + t;
    } else if (row == 45) {
        m = s8v[pl][0];
        for (int i = 1; i < 64; ++i) m = fmaxf(m, s8v[pl][i]);
        cell = 0;
    }
    if (cell >= 0) {
        size_t o = mode ? ((size_t)(b * 128 + cell) * C + c)
                        : ((size_t)bc * 112 + cell);
        out[o] = __float2half_rn(m);
    }
}

// ---------------------------------------------------------------------------
extern "C" void kernel_launch(void* const* d_in, const int* in_sizes, int n_in,
                              void* d_out, int out_size)
{
    const float* x        = (const float*)d_in[0];
    const float* qk_w     = (const float*)d_in[1];
    const float* qk_gamma = (const float*)d_in[2];
    const float* qk_beta  = (const float*)d_in[3];
    const float* qk_mean  = (const float*)d_in[4];
    const float* qk_var   = (const float*)d_in[5];
    const float* v_w      = (const float*)d_in[6];
    const float* v_gamma  = (const float*)d_in[7];
    const float* v_beta   = (const float*)d_in[8];
    const float* v_mean   = (const float*)d_in[9];
    const float* v_var    = (const float*)d_in[10];
    const float* out_w    = (const float*)d_in[11];
    const float* o_gamma  = (const float*)d_in[12];
    const float* o_beta   = (const float*)d_in[13];
    const float* o_mean   = (const float*)d_in[14];
    const float* o_var    = (const float*)d_in[15];
    float* out = (float*)d_out;

    __half *xh, *qkh, *valh, *keyh, *vpsp, *yh, *wq, *wv, *wo;
    cudaGetSymbolAddress((void**)&xh,   g_xh);
    cudaGetSymbolAddress((void**)&qkh,  g_qkh);
    cudaGetSymbolAddress((void**)&valh, g_valh);
    cudaGetSymbolAddress((void**)&keyh, g_keyh);
    cudaGetSymbolAddress((void**)&vpsp, g_vpsp);
    cudaGetSymbolAddress((void**)&yh,   g_yh);
    cudaGetSymbolAddress((void**)&wq,   g_wq);
    cudaGetSymbolAddress((void**)&wv,   g_wv);
    cudaGetSymbolAddress((void**)&wo,   g_wo);

    cudaFuncSetAttribute(gemm_kernel<true, true, false, true>,
                         cudaFuncAttributeMaxDynamicSharedMemorySize, GEMM_SMEM);
    cudaFuncSetAttribute(gemm_kernel<false, false, true, false>,
                         cudaFuncAttributeMaxDynamicSharedMemorySize, GEMM_SMEM);
    cudaFuncSetAttribute(attn_kernel,
                         cudaFuncAttributeMaxDynamicSharedMemorySize, GEMM_SMEM);

    // Side stream + events, created once on the first (uncaptured) call.
    static cudaStream_t s1 = nullptr;
    static cudaEvent_t ev_fork = nullptr, ev_join = nullptr;
    if (s1 == nullptr) {
        cudaStreamCreateWithFlags(&s1, cudaStreamNonBlocking);
        cudaEventCreateWithFlags(&ev_fork, cudaEventDisableTiming);
        cudaEventCreateWithFlags(&ev_join, cudaEventDisableTiming);
    }

    // 0) all fp16 conversions, one launch
    cvt_all_kernel<<<4096 + 1024, 256>>>(
        (const float4*)x, (uint4*)xh, qk_w, v_w, out_w, wq, wv, wo);

    // 1+2) fused: qk = relu(bn(conv(x,wq))), val = relu(bn(conv(x,wv)))
    gemm_kernel<true, true, false, true><<<dim3(32, 6, BB), 256, GEMM_SMEM>>>(
        wq, 0, xh, (size_t)CIN*HW, qk_gamma, qk_beta, qk_mean, qk_var,
        nullptr, qkh, (size_t)CK*HW, CIN,
        wv, v_gamma, v_beta, v_mean, v_var, valh, (size_t)CV*HW);

    // Fork: psp_val runs on side stream, overlapped with psp_qk.
    cudaEventRecord(ev_fork, 0);
    cudaStreamWaitEvent(s1, ev_fork, 0);
    psp_kernel<<<BB * CV / 4, 256, 0, s1>>>(valh, vpsp, CV, 0);
    cudaEventRecord(ev_join, s1);

    // 3a) key = psp(qk) [s][c]   (capture stream)
    psp_kernel<<<BB * CK / 4, 256>>>(qkh, keyh, CK, 1);

    // Join before attention (phase 2 reads vpsp).
    cudaStreamWaitEvent(0, ev_join, 0);

    // 4+5) fused attention: P = softmax((key@qk)/16); y = Vp @ P
    attn_kernel<<<dim3(32, BB), 256, GEMM_SMEM>>>(keyh, qkh, vpsp, yh);

    // 6) out = x + bn(conv(y, wo))
    gemm_kernel<false, false, true, false><<<dim3(32, 4, BB), 256, GEMM_SMEM>>>(
        wo, 0, yh, (size_t)CV*HW, o_gamma, o_beta, o_mean, o_var,
        x, out, (size_t)CIN*HW, CV,
        nullptr, nullptr, nullptr, nullptr, nullptr, nullptr, 0);
}

// round 15
// speedup vs baseline: 1.6368x; 1.0336x over previous
#include <cuda_runtime.h>
#include <cuda_fp16.h>
#include <cstdint>
#include <math.h>

#define BB   8
#define GB   4            // batches per group
#define CIN  512
#define CK   256
#define CV   512
#define HW   4096
#define SS   110

// Scratch (__device__ globals are zero-initialized; pad regions never written
// stay zero -> free zero-padding).
__device__ __align__(16) __half g_xh    [BB*CIN*HW];    // [b][k][n]
__device__ __align__(16) __half g_qkh   [BB*CK*HW];     // [b][c][n]
__device__ __align__(16) __half g_valh  [BB*CV*HW];     // [b][c][n]
__device__ __align__(16) __half g_keyh  [BB*128*CK];    // [b][s(pad128)][c]
__device__ __align__(16) __half g_vpsp  [BB*CV*112];    // [b][c][s(pad112)]
__device__ __align__(16) __half g_yh    [BB*CV*HW];     // [b][c][n]
__device__ __align__(16) __half g_wq    [CK*CIN];
__device__ __align__(16) __half g_wv    [CV*CIN];
__device__ __align__(16) __half g_wo    [CIN*CV];

// ---------------------------------------------------------------------------
__device__ __forceinline__ uint32_t smem_u32(const void* p) {
    uint32_t a;
    asm("{ .reg .u64 t; cvta.to.shared.u64 t, %1; cvt.u32.u64 %0, t; }" : "=r"(a) : "l"(p));
    return a;
}
__device__ __forceinline__ void ldsm_x4(uint32_t* r, uint32_t addr) {
    asm volatile("ldmatrix.sync.aligned.m8n8.x4.shared.b16 {%0,%1,%2,%3}, [%4];"
        : "=r"(r[0]), "=r"(r[1]), "=r"(r[2]), "=r"(r[3]) : "r"(addr));
}
__device__ __forceinline__ void ldsm_x4_t(uint32_t* r, uint32_t addr) {
    asm volatile("ldmatrix.sync.aligned.m8n8.x4.trans.shared.b16 {%0,%1,%2,%3}, [%4];"
        : "=r"(r[0]), "=r"(r[1]), "=r"(r[2]), "=r"(r[3]) : "r"(addr));
}
__device__ __forceinline__ void mma_f16(float* c, const uint32_t* a, const uint32_t* b) {
    asm volatile(
        "mma.sync.aligned.m16n8k16.row.col.f32.f16.f16.f32 "
        "{%0,%1,%2,%3}, {%4,%5,%6,%7}, {%8,%9}, {%0,%1,%2,%3};"
        : "+f"(c[0]), "+f"(c[1]), "+f"(c[2]), "+f"(c[3])
        : "r"(a[0]), "r"(a[1]), "r"(a[2]), "r"(a[3]), "r"(b[0]), "r"(b[1]));
}
__device__ __forceinline__ void cpa16(uint32_t dst, const void* src) {
    asm volatile("cp.async.cg.shared.global [%0], [%1], 16;" :: "r"(dst), "l"(src));
}

// ---------------------------------------------------------------------------
// Generalized GEMM: out[b,m,n] = epi( sum_k A[m,k] * B[b,k,n] )
// CTA 128m x 128n, 8 warps (2x4), warp 64x32. K staged 32, 4-stage pipeline.
// (75.8KB smem/CTA -> 2 CTAs/SM resident; proven best config.)
// ---------------------------------------------------------------------------
#define A_STRH 40
#define B_STRH 136
#define A_STG  (128*A_STRH*2)              // 10240 B
#define B_STG  (32*B_STRH*2)               // 8704 B
#define STG    (A_STG + B_STG)             // 18944 B
#define NSTAGE 4
#define GEMM_SMEM (NSTAGE*STG)             // 75776 B

template<bool FUSED, bool RELU, bool RESID, bool HALF_OUT>
__global__ __launch_bounds__(256, 2) void gemm_kernel(
    const __half* __restrict__ A, size_t a_bstride,
    const __half* __restrict__ Bm, size_t b_bstride,
    const float* __restrict__ gamma, const float* __restrict__ beta,
    const float* __restrict__ mean,  const float* __restrict__ var,
    const float* __restrict__ resid,
    void* __restrict__ outp, size_t o_bstride,
    int Ktot,
    const __half* __restrict__ A2,
    const float* __restrict__ gamma2, const float* __restrict__ beta2,
    const float* __restrict__ mean2,  const float* __restrict__ var2,
    void* __restrict__ outp2, size_t o_bstride2)
{
    extern __shared__ __align__(16) char smc[];
    const uint32_t sb = smem_u32(smc);
    const int tid = threadIdx.x, lane = tid & 31, wid = tid >> 5;
    const int gidr = lane >> 2, t4 = lane & 3;
    const int wm = wid >> 2, wn = wid & 3;
    const int n0 = blockIdx.x * 128, b = blockIdx.z;
    const int NK = Ktot >> 5;

    int m0 = blockIdx.y * 128;
    const __half* Ause = A;
    const float *g_ = gamma, *be_ = beta, *me_ = mean, *va_ = var;
    void* ouse = outp;
    size_t ostr = o_bstride;
    if (FUSED && blockIdx.y >= 2) {
        m0 = (blockIdx.y - 2) * 128;
        Ause = A2; g_ = gamma2; be_ = beta2; me_ = mean2; va_ = var2;
        ouse = outp2; ostr = o_bstride2;
    }

    const __half* gA = Ause + (size_t)m0 * Ktot;
    const __half* gB = Bm + (size_t)b * b_bstride + n0;

    auto load_stage = [&](int s) {
        const uint32_t base = sb + (uint32_t)(s & (NSTAGE-1)) * STG;
        #pragma unroll
        for (int it = 0; it < 2; ++it) {            // A: 128r x 4 chunks
            int idx = it * 256 + tid;
            int r = idx >> 2, c = idx & 3;
            cpa16(base + (uint32_t)(r * A_STRH + c * 8) * 2,
                  gA + (size_t)r * Ktot + s * 32 + c * 8);
        }
        #pragma unroll
        for (int it = 0; it < 2; ++it) {            // B: 32r x 16 chunks
            int idx = it * 256 + tid;
            int r = idx >> 4, c = idx & 15;
            cpa16(base + A_STG + (uint32_t)(r * B_STRH + c * 8) * 2,
                  gB + (size_t)(s * 32 + r) * HW + c * 8);
        }
        asm volatile("cp.async.commit_group;" ::: "memory");
    };

    float acc[4][4][4];
    #pragma unroll
    for (int mt = 0; mt < 4; ++mt)
        #pragma unroll
        for (int nt = 0; nt < 4; ++nt)
            #pragma unroll
            for (int r = 0; r < 4; ++r) acc[mt][nt][r] = 0.f;

    for (int s = 0; s < NSTAGE - 1 && s < NK; ++s) load_stage(s);
    asm volatile("cp.async.wait_group 2;" ::: "memory");
    __syncthreads();

    const int a_row = lane & 15, a_koff = (lane >> 4) * 8;
    const int b_krow = ((lane >> 3) & 1) * 8 + (lane & 7);
    const int b_noff = (lane >> 4) * 8;

    for (int kt = 0; kt < NK; ++kt) {
        if (kt + NSTAGE - 1 < NK) load_stage(kt + NSTAGE - 1);
        else asm volatile("cp.async.commit_group;" ::: "memory");

        const uint32_t sA = sb + (uint32_t)(kt & (NSTAGE-1)) * STG;
        const uint32_t sB = sA + A_STG;
        #pragma unroll
        for (int s16 = 0; s16 < 2; ++s16) {
            const int kk = s16 * 16;
            uint32_t af[4][4], bf[4][2];
            #pragma unroll
            for (int mt = 0; mt < 4; ++mt) {
                int row = wm * 64 + mt * 16 + a_row;
                ldsm_x4(af[mt], sA + (uint32_t)(row * A_STRH + kk + a_koff) * 2);
            }
            #pragma unroll
            for (int nt2 = 0; nt2 < 2; ++nt2) {
                uint32_t r4[4];
                int ncol = wn * 32 + nt2 * 16 + b_noff;
                ldsm_x4_t(r4, sB + (uint32_t)((kk + b_krow) * B_STRH + ncol) * 2);
                bf[nt2*2][0] = r4[0]; bf[nt2*2][1] = r4[1];
                bf[nt2*2+1][0] = r4[2]; bf[nt2*2+1][1] = r4[3];
            }
            #pragma unroll
            for (int mt = 0; mt < 4; ++mt)
                #pragma unroll
                for (int nt = 0; nt < 4; ++nt)
                    mma_f16(acc[mt][nt], af[mt], bf[nt]);
        }
        asm volatile("cp.async.wait_group 2;" ::: "memory");
        __syncthreads();
    }

    // Epilogue: BN (+ReLU) (+residual)
    #pragma unroll
    for (int mt = 0; mt < 4; ++mt) {
        const int ml = m0 + wm * 64 + mt * 16 + gidr;
        const int mh = ml + 8;
        const float scl = g_[ml] * rsqrtf(va_[ml] + 1e-5f);
        const float ttl = be_[ml] - me_[ml] * scl;
        const float sch = g_[mh] * rsqrtf(va_[mh] + 1e-5f);
        const float tth = be_[mh] - me_[mh] * sch;
        #pragma unroll
        for (int nt = 0; nt < 4; ++nt) {
            const int nn = n0 + wn * 32 + nt * 8 + 2 * t4;
            float2 vl, vh;
            vl.x = acc[mt][nt][0] * scl + ttl;
            vl.y = acc[mt][nt][1] * scl + ttl;
            vh.x = acc[mt][nt][2] * sch + tth;
            vh.y = acc[mt][nt][3] * sch + tth;
            if (RELU) {
                vl.x = fmaxf(vl.x, 0.f); vl.y = fmaxf(vl.y, 0.f);
                vh.x = fmaxf(vh.x, 0.f); vh.y = fmaxf(vh.y, 0.f);
            }
            if (HALF_OUT) {
                __half* oh = (__half*)ouse + (size_t)b * ostr;
                *(__half2*)(oh + (size_t)ml * HW + nn) = __floats2half2_rn(vl.x, vl.y);
                *(__half2*)(oh + (size_t)mh * HW + nn) = __floats2half2_rn(vh.x, vh.y);
            } else {
                float* of = (float*)ouse + (size_t)b * ostr;
                if (RESID) {
                    const float* rp = resid + (size_t)b * ostr;
                    float2 rl = *(const float2*)(rp + (size_t)ml * HW + nn);
                    float2 rh = *(const float2*)(rp + (size_t)mh * HW + nn);
                    vl.x += rl.x; vl.y += rl.y; vh.x += rh.x; vh.y += rh.y;
                }
                *(float2*)(of + (size_t)ml * HW + nn) = vl;
                *(float2*)(of + (size_t)mh * HW + nn) = vh;
            }
        }
    }
}

// ---------------------------------------------------------------------------
// Fused attention (per CTA: n-block, batch): scores mma -> register softmax
// -> P to smem -> 4x Vp tiles mma -> y.
// ---------------------------------------------------------------------------
#define AO_ASTR 120
#define ATT_SA  (112*B_STRH*2)          // 30464
#define ATT_RED (ATT_SA + 128*AO_ASTR*2)// 61184

__global__ __launch_bounds__(256, 2) void attn_kernel(
    const __half* __restrict__ Kh, const __half* __restrict__ Q,
    const __half* __restrict__ Vp, __half* __restrict__ y)
{
    extern __shared__ __align__(16) char smc[];
    const uint32_t sb = smem_u32(smc);
    const int tid = threadIdx.x, lane = tid & 31, wid = tid >> 5;
    const int gidr = lane >> 2, t4 = lane & 3;
    const int wm = wid >> 2, wn = wid & 3;
    const int n0 = blockIdx.x * 128, b = blockIdx.y;

    const __half* gA = Kh + (size_t)b * 128 * CK;
    const __half* gB = Q + (size_t)b * CK * HW + n0;

    auto load_stage = [&](int s) {
        const uint32_t base = sb + (uint32_t)(s & (NSTAGE-1)) * STG;
        #pragma unroll
        for (int it = 0; it < 2; ++it) {
            int idx = it * 256 + tid;
            int r = idx >> 2, c = idx & 3;
            cpa16(base + (uint32_t)(r * A_STRH + c * 8) * 2,
                  gA + (size_t)r * CK + s * 32 + c * 8);
        }
        #pragma unroll
        for (int it = 0; it < 2; ++it) {
            int idx = it * 256 + tid;
            int r = idx >> 4, c = idx & 15;
            cpa16(base + A_STG + (uint32_t)(r * B_STRH + c * 8) * 2,
                  gB + (size_t)(s * 32 + r) * HW + c * 8);
        }
        asm volatile("cp.async.commit_group;" ::: "memory");
    };

    float acc[4][4][4];
    #pragma unroll
    for (int mt = 0; mt < 4; ++mt)
        #pragma unroll
        for (int nt = 0; nt < 4; ++nt)
            #pragma unroll
            for (int r = 0; r < 4; ++r) acc[mt][nt][r] = 0.f;

    for (int s = 0; s < NSTAGE - 1; ++s) load_stage(s);
    asm volatile("cp.async.wait_group 2;" ::: "memory");
    __syncthreads();

    const int a_row = lane & 15, a_koff = (lane >> 4) * 8;
    const int b_krow = ((lane >> 3) & 1) * 8 + (lane & 7);
    const int b_noff = (lane >> 4) * 8;

    #pragma unroll 1
    for (int kt = 0; kt < 8; ++kt) {                // K = 256
        if (kt + NSTAGE - 1 < 8) load_stage(kt + NSTAGE - 1);
        else asm volatile("cp.async.commit_group;" ::: "memory");

        const uint32_t sA = sb + (uint32_t)(kt & (NSTAGE-1)) * STG;
        const uint32_t sB = sA + A_STG;
        #pragma unroll
        for (int s16 = 0; s16 < 2; ++s16) {
            const int kk = s16 * 16;
            uint32_t af[4][4], bf[4][2];
            #pragma unroll
            for (int mt = 0; mt < 4; ++mt) {
                int row = wm * 64 + mt * 16 + a_row;
                ldsm_x4(af[mt], sA + (uint32_t)(row * A_STRH + kk + a_koff) * 2);
            }
            #pragma unroll
            for (int nt2 = 0; nt2 < 2; ++nt2) {
                uint32_t r4[4];
                int ncol = wn * 32 + nt2 * 16 + b_noff;
                ldsm_x4_t(r4, sB + (uint32_t)((kk + b_krow) * B_STRH + ncol) * 2);
                bf[nt2*2][0] = r4[0]; bf[nt2*2][1] = r4[1];
                bf[nt2*2+1][0] = r4[2]; bf[nt2*2+1][1] = r4[3];
            }
            #pragma unroll
            for (int mt = 0; mt < 4; ++mt)
                #pragma unroll
                for (int nt = 0; nt < 4; ++nt)
                    mma_f16(acc[mt][nt], af[mt], bf[nt]);
        }
        asm volatile("cp.async.wait_group 2;" ::: "memory");
        __syncthreads();
    }

    // Column softmax over s (valid rows < SS), P -> smem fp16.
    {
        float* red = (float*)(smc + ATT_RED + 2048);
        float cmax[4][2], csum[4][2];
        #pragma unroll
        for (int nt = 0; nt < 4; ++nt) { cmax[nt][0] = -3.4e38f; cmax[nt][1] = -3.4e38f; }
        #pragma unroll
        for (int mt = 0; mt < 4; ++mt) {
            const int r0 = wm * 64 + mt * 16 + gidr, r1 = r0 + 8;
            #pragma unroll
            for (int nt = 0; nt < 4; ++nt) {
                #pragma unroll
                for (int r = 0; r < 4; ++r) acc[mt][nt][r] *= 0.0625f;
                if (r0 < SS) {
                    cmax[nt][0] = fmaxf(cmax[nt][0], acc[mt][nt][0]);
                    cmax[nt][1] = fmaxf(cmax[nt][1], acc[mt][nt][1]);
                }
                if (r1 < SS) {
                    cmax[nt][0] = fmaxf(cmax[nt][0], acc[mt][nt][2]);
                    cmax[nt][1] = fmaxf(cmax[nt][1], acc[mt][nt][3]);
                }
            }
        }
        #pragma unroll
        for (int nt = 0; nt < 4; ++nt)
            #pragma unroll
            for (int j = 0; j < 2; ++j) {
                float v = cmax[nt][j];
                v = fmaxf(v, __shfl_xor_sync(0xffffffffu, v, 4));
                v = fmaxf(v, __shfl_xor_sync(0xffffffffu, v, 8));
                v = fmaxf(v, __shfl_xor_sync(0xffffffffu, v, 16));
                cmax[nt][j] = v;
            }
        if (gidr == 0)
            #pragma unroll
            for (int nt = 0; nt < 4; ++nt)
                #pragma unroll
                for (int j = 0; j < 2; ++j)
                    red[wm*128 + wn*32 + nt*8 + 2*t4 + j] = cmax[nt][j];
        __syncthreads();
        #pragma unroll
        for (int nt = 0; nt < 4; ++nt)
            #pragma unroll
            for (int j = 0; j < 2; ++j)
                cmax[nt][j] = fmaxf(cmax[nt][j], red[(wm^1)*128 + wn*32 + nt*8 + 2*t4 + j]);

        #pragma unroll
        for (int nt = 0; nt < 4; ++nt) { csum[nt][0] = 0.f; csum[nt][1] = 0.f; }
        #pragma unroll
        for (int mt = 0; mt < 4; ++mt) {
            const int r0 = wm * 64 + mt * 16 + gidr, r1 = r0 + 8;
            #pragma unroll
            for (int nt = 0; nt < 4; ++nt) {
                float e0 = (r0 < SS) ? __expf(acc[mt][nt][0] - cmax[nt][0]) : 0.f;
                float e1 = (r0 < SS) ? __expf(acc[mt][nt][1] - cmax[nt][1]) : 0.f;
                float e2 = (r1 < SS) ? __expf(acc[mt][nt][2] - cmax[nt][0]) : 0.f;
                float e3 = (r1 < SS) ? __expf(acc[mt][nt][3] - cmax[nt][1]) : 0.f;
                acc[mt][nt][0] = e0; acc[mt][nt][1] = e1;
                acc[mt][nt][2] = e2; acc[mt][nt][3] = e3;
                csum[nt][0] += e0 + e2; csum[nt][1] += e1 + e3;
            }
        }
        #pragma unroll
        for (int nt = 0; nt < 4; ++nt)
            #pragma unroll
            for (int j = 0; j < 2; ++j) {
                float v = csum[nt][j];
                v += __shfl_xor_sync(0xffffffffu, v, 4);
                v += __shfl_xor_sync(0xffffffffu, v, 8);
                v += __shfl_xor_sync(0xffffffffu, v, 16);
                csum[nt][j] = v;
            }
        if (gidr == 0)
            #pragma unroll
            for (int nt = 0; nt < 4; ++nt)
                #pragma unroll
                for (int j = 0; j < 2; ++j)
                    red[256 + wm*128 + wn*32 + nt*8 + 2*t4 + j] = csum[nt][j];
        __syncthreads();
        #pragma unroll
        for (int nt = 0; nt < 4; ++nt)
            #pragma unroll
            for (int j = 0; j < 2; ++j)
                csum[nt][j] += red[256 + (wm^1)*128 + wn*32 + nt*8 + 2*t4 + j];
        __syncthreads();

        __half* sP = (__half*)smc;
        #pragma unroll
        for (int mt = 0; mt < 4; ++mt) {
            const int r0 = wm * 64 + mt * 16 + gidr, r1 = r0 + 8;
            #pragma unroll
            for (int nt = 0; nt < 4; ++nt) {
                const int nn = wn * 32 + nt * 8 + 2 * t4;
                const float i0 = 1.f / csum[nt][0], i1 = 1.f / csum[nt][1];
                if (r0 < 112)
                    *(__half2*)(sP + r0 * B_STRH + nn) =
                        __floats2half2_rn(acc[mt][nt][0] * i0, acc[mt][nt][1] * i1);
                if (r1 < 112)
                    *(__half2*)(sP + r1 * B_STRH + nn) =
                        __floats2half2_rn(acc[mt][nt][2] * i0, acc[mt][nt][3] * i1);
            }
        }
    }
    __syncthreads();

    // Phase 2: y[c][n] = Vp[c][s] @ P[s][n], 4 Vp tiles of 128c.
    const uint32_t sSP = sb;
    const uint32_t sVA = sb + ATT_SA;
    __half* yb = y + (size_t)b * CV * HW;

    #pragma unroll 1
    for (int cb = 0; cb < 4; ++cb) {
        if (cb) __syncthreads();
        const __half* gV = Vp + (size_t)b * CV * 112 + (size_t)(cb * 128) * 112;
        #pragma unroll
        for (int it = 0; it < 7; ++it) {
            int idx = it * 256 + tid;
            int r = idx / 14, c = idx - r * 14;
            cpa16(sVA + (uint32_t)(r * AO_ASTR + c * 8) * 2, gV + (size_t)r * 112 + c * 8);
        }
        asm volatile("cp.async.commit_group;\ncp.async.wait_group 0;" ::: "memory");
        __syncthreads();

        #pragma unroll
        for (int mt = 0; mt < 4; ++mt)
            #pragma unroll
            for (int nt = 0; nt < 4; ++nt)
                #pragma unroll
                for (int r = 0; r < 4; ++r) acc[mt][nt][r] = 0.f;

        #pragma unroll
        for (int s16 = 0; s16 < 7; ++s16) {
            const int kk = s16 * 16;
            uint32_t af[4][4], bf[4][2];
            #pragma unroll
            for (int mt = 0; mt < 4; ++mt) {
                int row = wm * 64 + mt * 16 + a_row;
                ldsm_x4(af[mt], sVA + (uint32_t)(row * AO_ASTR + kk + a_koff) * 2);
            }
            #pragma unroll
            for (int nt2 = 0; nt2 < 2; ++nt2) {
                uint32_t r4[4];
                int ncol = wn * 32 + nt2 * 16 + b_noff;
                ldsm_x4_t(r4, sSP + (uint32_t)((kk + b_krow) * B_STRH + ncol) * 2);
                bf[nt2*2][0] = r4[0]; bf[nt2*2][1] = r4[1];
                bf[nt2*2+1][0] = r4[2]; bf[nt2*2+1][1] = r4[3];
            }
            #pragma unroll
            for (int mt = 0; mt < 4; ++mt)
                #pragma unroll
                for (int nt = 0; nt < 4; ++nt)
                    mma_f16(acc[mt][nt], af[mt], bf[nt]);
        }

        #pragma unroll
        for (int mt = 0; mt < 4; ++mt) {
            const int ml = cb * 128 + wm * 64 + mt * 16 + gidr;
            #pragma unroll
            for (int nt = 0; nt < 4; ++nt) {
                const int nn = n0 + wn * 32 + nt * 8 + 2 * t4;
                *(__half2*)(yb + (size_t)ml * HW + nn) =
                    __floats2half2_rn(acc[mt][nt][0], acc[mt][nt][1]);
                *(__half2*)(yb + (size_t)(ml + 8) * HW + nn) =
                    __floats2half2_rn(acc[mt][nt][2], acc[mt][nt][3]);
            }
        }
    }
}

// ---------------------------------------------------------------------------
// Conversions: weights (one small launch) + per-group x conversion.
// ---------------------------------------------------------------------------
__global__ __launch_bounds__(256) void cvt_w_kernel(
    const float* __restrict__ wq, const float* __restrict__ wv,
    const float* __restrict__ wo,
    __half* __restrict__ oq, __half* __restrict__ ov, __half* __restrict__ oo)
{
    int i = blockIdx.x * 256 + threadIdx.x;
    if (i < CK*CIN) oq[i] = __float2half_rn(wq[i]);
    if (i < CV*CIN) { ov[i] = __float2half_rn(wv[i]); oo[i] = __float2half_rn(wo[i]); }
}

#define XG (GB*CIN*HW/16)     // 524288 -> 2048 blocks of 256
__global__ __launch_bounds__(256) void cvt_xg_kernel(
    const float4* __restrict__ x, uint4* __restrict__ xh)
{
    int i = blockIdx.x * 256 + threadIdx.x;
    float4 a0 = x[2*i], a1 = x[2*i+1];
    float4 b0 = x[2*(i + XG)], b1 = x[2*(i + XG)+1];
    __half2 h0 = __floats2half2_rn(a0.x, a0.y), h1 = __floats2half2_rn(a0.z, a0.w);
    __half2 h2 = __floats2half2_rn(a1.x, a1.y), h3 = __floats2half2_rn(a1.z, a1.w);
    __half2 g0 = __floats2half2_rn(b0.x, b0.y), g1 = __floats2half2_rn(b0.z, b0.w);
    __half2 g2 = __floats2half2_rn(b1.x, b1.y), g3 = __floats2half2_rn(b1.z, b1.w);
    uint4 u, v;
    u.x = *(uint32_t*)&h0; u.y = *(uint32_t*)&h1;
    u.z = *(uint32_t*)&h2; u.w = *(uint32_t*)&h3;
    v.x = *(uint32_t*)&g0; v.y = *(uint32_t*)&g1;
    v.z = *(uint32_t*)&g2; v.w = *(uint32_t*)&g3;
    xh[i] = u;
    xh[i + XG] = v;
}

// ---------------------------------------------------------------------------
// PSP adaptive max pool, register-resident phase 1. 4 planes per block.
// mode 0: out[(b*C + c)*112 + cell]   (value: [c][s] pad 112)
// mode 1: out[(b*128 + cell)*C + c]   (key:   [s pad128][c])
// ---------------------------------------------------------------------------
#define RM_STR 65

template<int A, int B>
__device__ __forceinline__ float segmax(const __half2* h) {
    constexpr int a2 = (A + 1) >> 1, b2 = B >> 1;
    __half2 m2 = __floats2half2_rn(-65504.f, -65504.f);
    #pragma unroll
    for (int c = a2; c < b2; ++c) m2 = __hmax2(m2, h[c]);
    float m = fmaxf(__low2float(m2), __high2float(m2));
    if (A & 1) m = fmaxf(m, __high2float(h[A >> 1]));
    if (B & 1) m = fmaxf(m, __low2float(h[B >> 1]));
    return m;
}

__global__ __launch_bounds__(256) void psp_kernel(
    const __half* __restrict__ in, __half* __restrict__ out, int C, int mode)
{
    __shared__ float rm[4][17 * RM_STR];
    __shared__ float s8v[4][64];
    const int pl = threadIdx.x >> 6;
    const int row = threadIdx.x & 63;
    const int bc = blockIdx.x * 4 + pl;
    const int b = bc / C, c = bc - b * C;
    float* rmp = rm[pl];

    __half2 h[32];
    {
        const uint4* rp = (const uint4*)(in + (size_t)bc * 4096 + row * 64);
        uint4* hv = (uint4*)h;
        #pragma unroll
        for (int i = 0; i < 8; ++i) hv[i] = rp[i];
    }

    rmp[ 0*RM_STR + row] = segmax< 0,22>(h);
    rmp[ 1*RM_STR + row] = segmax<21,43>(h);
    rmp[ 2*RM_STR + row] = segmax<42,64>(h);
    rmp[ 3*RM_STR + row] = segmax< 0,11>(h);
    rmp[ 4*RM_STR + row] = segmax<10,22>(h);
    rmp[ 5*RM_STR + row] = segmax<21,32>(h);
    rmp[ 6*RM_STR + row] = segmax<32,43>(h);
    rmp[ 7*RM_STR + row] = segmax<42,54>(h);
    rmp[ 8*RM_STR + row] = segmax<53,64>(h);
    rmp[ 9*RM_STR + row] = segmax< 0, 8>(h);
    rmp[10*RM_STR + row] = segmax< 8,16>(h);
    rmp[11*RM_STR + row] = segmax<16,24>(h);
    rmp[12*RM_STR + row] = segmax<24,32>(h);
    rmp[13*RM_STR + row] = segmax<32,40>(h);
    rmp[14*RM_STR + row] = segmax<40,48>(h);
    rmp[15*RM_STR + row] = segmax<48,56>(h);
    rmp[16*RM_STR + row] = segmax<56,64>(h);
    __syncthreads();

    {
        int i = row >> 3, j = row & 7;
        float m = rmp[(9 + j) * RM_STR + i * 8];
        #pragma unroll
        for (int r = 1; r < 8; ++r) m = fmaxf(m, rmp[(9 + j) * RM_STR + i * 8 + r]);
        s8v[pl][row] = m;
        int cell = 46 + row;
        size_t o = mode ? ((size_t)(b * 128 + cell) * C + c)
                        : ((size_t)bc * 112 + cell);
        out[o] = __float2half_rn(m);
    }
    __syncthreads();

    float m = -3.402823e38f;
    int cell = -1;
    if (row < 36) {
        const int st[6] = {0,10,21,32,42,53}, en[6] = {11,22,32,43,54,64};
        int i = row / 6, j = row - i * 6;
        m = rmp[(3 + j) * RM_STR + st[i]];
        for (int r = st[i] + 1; r < en[i]; ++r) m = fmaxf(m, rmp[(3 + j) * RM_STR + r]);
        cell = 10 + row;
    } else if (row < 45) {
        const int st[3] = {0,21,42}, en[3] = {22,43,64};
        int t = row - 36, i = t / 3, j = t - i * 3;
        m = rmp[j * RM_STR + st[i]];
        for (int r = st[i] + 1; r < en[i]; ++r) m = fmaxf(m, rmp[j * RM_STR + r]);
        cell = 1 + t;
    } else if (row == 45) {
        m = s8v[pl][0];
        for (int i = 1; i < 64; ++i) m = fmaxf(m, s8v[pl][i]);
        cell = 0;
    }
    if (cell >= 0) {
        size_t o = mode ? ((size_t)(b * 128 + cell) * C + c)
                        : ((size_t)bc * 112 + cell);
        out[o] = __float2half_rn(m);
    }
}

// ---------------------------------------------------------------------------
extern "C" void kernel_launch(void* const* d_in, const int* in_sizes, int n_in,
                              void* d_out, int out_size)
{
    const float* x        = (const float*)d_in[0];
    const float* qk_w     = (const float*)d_in[1];
    const float* qk_gamma = (const float*)d_in[2];
    const float* qk_beta  = (const float*)d_in[3];
    const float* qk_mean  = (const float*)d_in[4];
    const float* qk_var   = (const float*)d_in[5];
    const float* v_w      = (const float*)d_in[6];
    const float* v_gamma  = (const float*)d_in[7];
    const float* v_beta   = (const float*)d_in[8];
    const float* v_mean   = (const float*)d_in[9];
    const float* v_var    = (const float*)d_in[10];
    const float* out_w    = (const float*)d_in[11];
    const float* o_gamma  = (const float*)d_in[12];
    const float* o_beta   = (const float*)d_in[13];
    const float* o_mean   = (const float*)d_in[14];
    const float* o_var    = (const float*)d_in[15];
    float* out = (float*)d_out;

    __half *xh, *qkh, *valh, *keyh, *vpsp, *yh, *wq, *wv, *wo;
    cudaGetSymbolAddress((void**)&xh,   g_xh);
    cudaGetSymbolAddress((void**)&qkh,  g_qkh);
    cudaGetSymbolAddress((void**)&valh, g_valh);
    cudaGetSymbolAddress((void**)&keyh, g_keyh);
    cudaGetSymbolAddress((void**)&vpsp, g_vpsp);
    cudaGetSymbolAddress((void**)&yh,   g_yh);
    cudaGetSymbolAddress((void**)&wq,   g_wq);
    cudaGetSymbolAddress((void**)&wv,   g_wv);
    cudaGetSymbolAddress((void**)&wo,   g_wo);

    cudaFuncSetAttribute(gemm_kernel<true, true, false, true>,
                         cudaFuncAttributeMaxDynamicSharedMemorySize, GEMM_SMEM);
    cudaFuncSetAttribute(gemm_kernel<false, false, true, false>,
                         cudaFuncAttributeMaxDynamicSharedMemorySize, GEMM_SMEM);
    cudaFuncSetAttribute(attn_kernel,
                         cudaFuncAttributeMaxDynamicSharedMemorySize, GEMM_SMEM);

    // Side stream + events, created once on the first (uncaptured) call.
    static cudaStream_t s1 = nullptr;
    static cudaEvent_t ev_w = nullptr, ev_done = nullptr;
    if (s1 == nullptr) {
        cudaStreamCreateWithFlags(&s1, cudaStreamNonBlocking);
        cudaEventCreateWithFlags(&ev_w, cudaEventDisableTiming);
        cudaEventCreateWithFlags(&ev_done, cudaEventDisableTiming);
    }

    // Run one complete pipeline for batches [g*4, g*4+4) on stream st.
    auto run_group = [&](int g, cudaStream_t st) {
        const size_t xo  = (size_t)g * GB * CIN * HW;
        const float*  xg   = x + xo;
        __half*       xhg  = xh + xo;
        __half*       qkg  = qkh + (size_t)g * GB * CK * HW;
        __half*       valg = valh + (size_t)g * GB * CV * HW;
        __half*       keyg = keyh + (size_t)g * GB * 128 * CK;
        __half*       vpg  = vpsp + (size_t)g * GB * CV * 112;
        __half*       yg   = yh + (size_t)g * GB * CV * HW;
        float*        og   = out + xo;

        cvt_xg_kernel<<<XG / 256, 256, 0, st>>>((const float4*)xg, (uint4*)xhg);
        gemm_kernel<true, true, false, true><<<dim3(32, 6, GB), 256, GEMM_SMEM, st>>>(
            wq, 0, xhg, (size_t)CIN*HW, qk_gamma, qk_beta, qk_mean, qk_var,
            nullptr, qkg, (size_t)CK*HW, CIN,
            wv, v_gamma, v_beta, v_mean, v_var, valg, (size_t)CV*HW);
        psp_kernel<<<GB * CK / 4, 256, 0, st>>>(qkg, keyg, CK, 1);
        psp_kernel<<<GB * CV / 4, 256, 0, st>>>(valg, vpg, CV, 0);
        attn_kernel<<<dim3(32, GB), 256, GEMM_SMEM, st>>>(keyg, qkg, vpg, yg);
        gemm_kernel<false, false, true, false><<<dim3(32, 4, GB), 256, GEMM_SMEM, st>>>(
            wo, 0, yg, (size_t)CV*HW, o_gamma, o_beta, o_mean, o_var,
            xg, og, (size_t)CIN*HW, CV,
            nullptr, nullptr, nullptr, nullptr, nullptr, nullptr, 0);
    };

    // Weights once (main stream); group 1 waits on them via event.
    cvt_w_kernel<<<(CV*CIN + 255) / 256, 256>>>(qk_w, v_w, out_w, wq, wv, wo);
    cudaEventRecord(ev_w, 0);
    cudaStreamWaitEvent(s1, ev_w, 0);

    run_group(0, 0);    // batches 0-3 on capture stream
    run_group(1, s1);   // batches 4-7 on side stream

    cudaEventRecord(ev_done, s1);
    cudaStreamWaitEvent(0, ev_done, 0);
}

// round 16
// speedup vs baseline: 1.6418x; 1.0030x over previous
#include <cuda_runtime.h>
#include <cuda_fp16.h>
#include <cstdint>
#include <math.h>

#define BB   8
#define GB   2            // batches per group
#define NG   4            // number of groups
#define CIN  512
#define CK   256
#define CV   512
#define HW   4096
#define SS   110

// Scratch (__device__ globals are zero-initialized; pad regions never written
// stay zero -> free zero-padding).
__device__ __align__(16) __half g_xh    [BB*CIN*HW];    // [b][k][n]
__device__ __align__(16) __half g_qkh   [BB*CK*HW];     // [b][c][n]
__device__ __align__(16) __half g_valh  [BB*CV*HW];     // [b][c][n]
__device__ __align__(16) __half g_keyh  [BB*128*CK];    // [b][s(pad128)][c]
__device__ __align__(16) __half g_vpsp  [BB*CV*112];    // [b][c][s(pad112)]
__device__ __align__(16) __half g_yh    [BB*CV*HW];     // [b][c][n]
__device__ __align__(16) __half g_wq    [CK*CIN];
__device__ __align__(16) __half g_wv    [CV*CIN];
__device__ __align__(16) __half g_wo    [CIN*CV];

// ---------------------------------------------------------------------------
__device__ __forceinline__ uint32_t smem_u32(const void* p) {
    uint32_t a;
    asm("{ .reg .u64 t; cvta.to.shared.u64 t, %1; cvt.u32.u64 %0, t; }" : "=r"(a) : "l"(p));
    return a;
}
__device__ __forceinline__ void ldsm_x4(uint32_t* r, uint32_t addr) {
    asm volatile("ldmatrix.sync.aligned.m8n8.x4.shared.b16 {%0,%1,%2,%3}, [%4];"
        : "=r"(r[0]), "=r"(r[1]), "=r"(r[2]), "=r"(r[3]) : "r"(addr));
}
__device__ __forceinline__ void ldsm_x4_t(uint32_t* r, uint32_t addr) {
    asm volatile("ldmatrix.sync.aligned.m8n8.x4.trans.shared.b16 {%0,%1,%2,%3}, [%4];"
        : "=r"(r[0]), "=r"(r[1]), "=r"(r[2]), "=r"(r[3]) : "r"(addr));
}
__device__ __forceinline__ void mma_f16(float* c, const uint32_t* a, const uint32_t* b) {
    asm volatile(
        "mma.sync.aligned.m16n8k16.row.col.f32.f16.f16.f32 "
        "{%0,%1,%2,%3}, {%4,%5,%6,%7}, {%8,%9}, {%0,%1,%2,%3};"
        : "+f"(c[0]), "+f"(c[1]), "+f"(c[2]), "+f"(c[3])
        : "r"(a[0]), "r"(a[1]), "r"(a[2]), "r"(a[3]), "r"(b[0]), "r"(b[1]));
}
__device__ __forceinline__ void cpa16(uint32_t dst, const void* src) {
    asm volatile("cp.async.cg.shared.global [%0], [%1], 16;" :: "r"(dst), "l"(src));
}

// ---------------------------------------------------------------------------
// Generalized GEMM: out[b,m,n] = epi( sum_k A[m,k] * B[b,k,n] )
// CTA 128m x 128n, 8 warps (2x4), warp 64x32. K staged 32, 4-stage pipeline.
// (75.8KB smem/CTA -> 2 CTAs/SM resident; proven best config.)
// ---------------------------------------------------------------------------
#define A_STRH 40
#define B_STRH 136
#define A_STG  (128*A_STRH*2)              // 10240 B
#define B_STG  (32*B_STRH*2)               // 8704 B
#define STG    (A_STG + B_STG)             // 18944 B
#define NSTAGE 4
#define GEMM_SMEM (NSTAGE*STG)             // 75776 B

template<bool FUSED, bool RELU, bool RESID, bool HALF_OUT>
__global__ __launch_bounds__(256, 2) void gemm_kernel(
    const __half* __restrict__ A, size_t a_bstride,
    const __half* __restrict__ Bm, size_t b_bstride,
    const float* __restrict__ gamma, const float* __restrict__ beta,
    const float* __restrict__ mean,  const float* __restrict__ var,
    const float* __restrict__ resid,
    void* __restrict__ outp, size_t o_bstride,
    int Ktot,
    const __half* __restrict__ A2,
    const float* __restrict__ gamma2, const float* __restrict__ beta2,
    const float* __restrict__ mean2,  const float* __restrict__ var2,
    void* __restrict__ outp2, size_t o_bstride2)
{
    extern __shared__ __align__(16) char smc[];
    const uint32_t sb = smem_u32(smc);
    const int tid = threadIdx.x, lane = tid & 31, wid = tid >> 5;
    const int gidr = lane >> 2, t4 = lane & 3;
    const int wm = wid >> 2, wn = wid & 3;
    const int n0 = blockIdx.x * 128, b = blockIdx.z;
    const int NK = Ktot >> 5;

    int m0 = blockIdx.y * 128;
    const __half* Ause = A;
    const float *g_ = gamma, *be_ = beta, *me_ = mean, *va_ = var;
    void* ouse = outp;
    size_t ostr = o_bstride;
    if (FUSED && blockIdx.y >= 2) {
        m0 = (blockIdx.y - 2) * 128;
        Ause = A2; g_ = gamma2; be_ = beta2; me_ = mean2; va_ = var2;
        ouse = outp2; ostr = o_bstride2;
    }

    const __half* gA = Ause + (size_t)m0 * Ktot;
    const __half* gB = Bm + (size_t)b * b_bstride + n0;

    auto load_stage = [&](int s) {
        const uint32_t base = sb + (uint32_t)(s & (NSTAGE-1)) * STG;
        #pragma unroll
        for (int it = 0; it < 2; ++it) {            // A: 128r x 4 chunks
            int idx = it * 256 + tid;
            int r = idx >> 2, c = idx & 3;
            cpa16(base + (uint32_t)(r * A_STRH + c * 8) * 2,
                  gA + (size_t)r * Ktot + s * 32 + c * 8);
        }
        #pragma unroll
        for (int it = 0; it < 2; ++it) {            // B: 32r x 16 chunks
            int idx = it * 256 + tid;
            int r = idx >> 4, c = idx & 15;
            cpa16(base + A_STG + (uint32_t)(r * B_STRH + c * 8) * 2,
                  gB + (size_t)(s * 32 + r) * HW + c * 8);
        }
        asm volatile("cp.async.commit_group;" ::: "memory");
    };

    float acc[4][4][4];
    #pragma unroll
    for (int mt = 0; mt < 4; ++mt)
        #pragma unroll
        for (int nt = 0; nt < 4; ++nt)
            #pragma unroll
            for (int r = 0; r < 4; ++r) acc[mt][nt][r] = 0.f;

    for (int s = 0; s < NSTAGE - 1 && s < NK; ++s) load_stage(s);
    asm volatile("cp.async.wait_group 2;" ::: "memory");
    __syncthreads();

    const int a_row = lane & 15, a_koff = (lane >> 4) * 8;
    const int b_krow = ((lane >> 3) & 1) * 8 + (lane & 7);
    const int b_noff = (lane >> 4) * 8;

    for (int kt = 0; kt < NK; ++kt) {
        if (kt + NSTAGE - 1 < NK) load_stage(kt + NSTAGE - 1);
        else asm volatile("cp.async.commit_group;" ::: "memory");

        const uint32_t sA = sb + (uint32_t)(kt & (NSTAGE-1)) * STG;
        const uint32_t sB = sA + A_STG;
        #pragma unroll
        for (int s16 = 0; s16 < 2; ++s16) {
            const int kk = s16 * 16;
            uint32_t af[4][4], bf[4][2];
            #pragma unroll
            for (int mt = 0; mt < 4; ++mt) {
                int row = wm * 64 + mt * 16 + a_row;
                ldsm_x4(af[mt], sA + (uint32_t)(row * A_STRH + kk + a_koff) * 2);
            }
            #pragma unroll
            for (int nt2 = 0; nt2 < 2; ++nt2) {
                uint32_t r4[4];
                int ncol = wn * 32 + nt2 * 16 + b_noff;
                ldsm_x4_t(r4, sB + (uint32_t)((kk + b_krow) * B_STRH + ncol) * 2);
                bf[nt2*2][0] = r4[0]; bf[nt2*2][1] = r4[1];
                bf[nt2*2+1][0] = r4[2]; bf[nt2*2+1][1] = r4[3];
            }
            #pragma unroll
            for (int mt = 0; mt < 4; ++mt)
                #pragma unroll
                for (int nt = 0; nt < 4; ++nt)
                    mma_f16(acc[mt][nt], af[mt], bf[nt]);
        }
        asm volatile("cp.async.wait_group 2;" ::: "memory");
        __syncthreads();
    }

    // Epilogue: BN (+ReLU) (+residual)
    #pragma unroll
    for (int mt = 0; mt < 4; ++mt) {
        const int ml = m0 + wm * 64 + mt * 16 + gidr;
        const int mh = ml + 8;
        const float scl = g_[ml] * rsqrtf(va_[ml] + 1e-5f);
        const float ttl = be_[ml] - me_[ml] * scl;
        const float sch = g_[mh] * rsqrtf(va_[mh] + 1e-5f);
        const float tth = be_[mh] - me_[mh] * sch;
        #pragma unroll
        for (int nt = 0; nt < 4; ++nt) {
            const int nn = n0 + wn * 32 + nt * 8 + 2 * t4;
            float2 vl, vh;
            vl.x = acc[mt][nt][0] * scl + ttl;
            vl.y = acc[mt][nt][1] * scl + ttl;
            vh.x = acc[mt][nt][2] * sch + tth;
            vh.y = acc[mt][nt][3] * sch + tth;
            if (RELU) {
                vl.x = fmaxf(vl.x, 0.f); vl.y = fmaxf(vl.y, 0.f);
                vh.x = fmaxf(vh.x, 0.f); vh.y = fmaxf(vh.y, 0.f);
            }
            if (HALF_OUT) {
                __half* oh = (__half*)ouse + (size_t)b * ostr;
                *(__half2*)(oh + (size_t)ml * HW + nn) = __floats2half2_rn(vl.x, vl.y);
                *(__half2*)(oh + (size_t)mh * HW + nn) = __floats2half2_rn(vh.x, vh.y);
            } else {
                float* of = (float*)ouse + (size_t)b * ostr;
                if (RESID) {
                    const float* rp = resid + (size_t)b * ostr;
                    float2 rl = *(const float2*)(rp + (size_t)ml * HW + nn);
                    float2 rh = *(const float2*)(rp + (size_t)mh * HW + nn);
                    vl.x += rl.x; vl.y += rl.y; vh.x += rh.x; vh.y += rh.y;
                }
                *(float2*)(of + (size_t)ml * HW + nn) = vl;
                *(float2*)(of + (size_t)mh * HW + nn) = vh;
            }
        }
    }
}

// ---------------------------------------------------------------------------
// Fused attention (per CTA: n-block, batch): scores mma -> register softmax
// -> P to smem -> 4x Vp tiles mma -> y.
// ---------------------------------------------------------------------------
#define AO_ASTR 120
#define ATT_SA  (112*B_STRH*2)          // 30464
#define ATT_RED (ATT_SA + 128*AO_ASTR*2)// 61184

__global__ __launch_bounds__(256, 2) void attn_kernel(
    const __half* __restrict__ Kh, const __half* __restrict__ Q,
    const __half* __restrict__ Vp, __half* __restrict__ y)
{
    extern __shared__ __align__(16) char smc[];
    const uint32_t sb = smem_u32(smc);
    const int tid = threadIdx.x, lane = tid & 31, wid = tid >> 5;
    const int gidr = lane >> 2, t4 = lane & 3;
    const int wm = wid >> 2, wn = wid & 3;
    const int n0 = blockIdx.x * 128, b = blockIdx.y;

    const __half* gA = Kh + (size_t)b * 128 * CK;
    const __half* gB = Q + (size_t)b * CK * HW + n0;

    auto load_stage = [&](int s) {
        const uint32_t base = sb + (uint32_t)(s & (NSTAGE-1)) * STG;
        #pragma unroll
        for (int it = 0; it < 2; ++it) {
            int idx = it * 256 + tid;
            int r = idx >> 2, c = idx & 3;
            cpa16(base + (uint32_t)(r * A_STRH + c * 8) * 2,
                  gA + (size_t)r * CK + s * 32 + c * 8);
        }
        #pragma unroll
        for (int it = 0; it < 2; ++it) {
            int idx = it * 256 + tid;
            int r = idx >> 4, c = idx & 15;
            cpa16(base + A_STG + (uint32_t)(r * B_STRH + c * 8) * 2,
                  gB + (size_t)(s * 32 + r) * HW + c * 8);
        }
        asm volatile("cp.async.commit_group;" ::: "memory");
    };

    float acc[4][4][4];
    #pragma unroll
    for (int mt = 0; mt < 4; ++mt)
        #pragma unroll
        for (int nt = 0; nt < 4; ++nt)
            #pragma unroll
            for (int r = 0; r < 4; ++r) acc[mt][nt][r] = 0.f;

    for (int s = 0; s < NSTAGE - 1; ++s) load_stage(s);
    asm volatile("cp.async.wait_group 2;" ::: "memory");
    __syncthreads();

    const int a_row = lane & 15, a_koff = (lane >> 4) * 8;
    const int b_krow = ((lane >> 3) & 1) * 8 + (lane & 7);
    const int b_noff = (lane >> 4) * 8;

    #pragma unroll 1
    for (int kt = 0; kt < 8; ++kt) {                // K = 256
        if (kt + NSTAGE - 1 < 8) load_stage(kt + NSTAGE - 1);
        else asm volatile("cp.async.commit_group;" ::: "memory");

        const uint32_t sA = sb + (uint32_t)(kt & (NSTAGE-1)) * STG;
        const uint32_t sB = sA + A_STG;
        #pragma unroll
        for (int s16 = 0; s16 < 2; ++s16) {
            const int kk = s16 * 16;
            uint32_t af[4][4], bf[4][2];
            #pragma unroll
            for (int mt = 0; mt < 4; ++mt) {
                int row = wm * 64 + mt * 16 + a_row;
                ldsm_x4(af[mt], sA + (uint32_t)(row * A_STRH + kk + a_koff) * 2);
            }
            #pragma unroll
            for (int nt2 = 0; nt2 < 2; ++nt2) {
                uint32_t r4[4];
                int ncol = wn * 32 + nt2 * 16 + b_noff;
                ldsm_x4_t(r4, sB + (uint32_t)((kk + b_krow) * B_STRH + ncol) * 2);
                bf[nt2*2][0] = r4[0]; bf[nt2*2][1] = r4[1];
                bf[nt2*2+1][0] = r4[2]; bf[nt2*2+1][1] = r4[3];
            }
            #pragma unroll
            for (int mt = 0; mt < 4; ++mt)
                #pragma unroll
                for (int nt = 0; nt < 4; ++nt)
                    mma_f16(acc[mt][nt], af[mt], bf[nt]);
        }
        asm volatile("cp.async.wait_group 2;" ::: "memory");
        __syncthreads();
    }

    // Column softmax over s (valid rows < SS), P -> smem fp16.
    {
        float* red = (float*)(smc + ATT_RED + 2048);
        float cmax[4][2], csum[4][2];
        #pragma unroll
        for (int nt = 0; nt < 4; ++nt) { cmax[nt][0] = -3.4e38f; cmax[nt][1] = -3.4e38f; }
        #pragma unroll
        for (int mt = 0; mt < 4; ++mt) {
            const int r0 = wm * 64 + mt * 16 + gidr, r1 = r0 + 8;
            #pragma unroll
            for (int nt = 0; nt < 4; ++nt) {
                #pragma unroll
                for (int r = 0; r < 4; ++r) acc[mt][nt][r] *= 0.0625f;
                if (r0 < SS) {
                    cmax[nt][0] = fmaxf(cmax[nt][0], acc[mt][nt][0]);
                    cmax[nt][1] = fmaxf(cmax[nt][1], acc[mt][nt][1]);
                }
                if (r1 < SS) {
                    cmax[nt][0] = fmaxf(cmax[nt][0], acc[mt][nt][2]);
                    cmax[nt][1] = fmaxf(cmax[nt][1], acc[mt][nt][3]);
                }
            }
        }
        #pragma unroll
        for (int nt = 0; nt < 4; ++nt)
            #pragma unroll
            for (int j = 0; j < 2; ++j) {
                float v = cmax[nt][j];
                v = fmaxf(v, __shfl_xor_sync(0xffffffffu, v, 4));
                v = fmaxf(v, __shfl_xor_sync(0xffffffffu, v, 8));
                v = fmaxf(v, __shfl_xor_sync(0xffffffffu, v, 16));
                cmax[nt][j] = v;
            }
        if (gidr == 0)
            #pragma unroll
            for (int nt = 0; nt < 4; ++nt)
                #pragma unroll
                for (int j = 0; j < 2; ++j)
                    red[wm*128 + wn*32 + nt*8 + 2*t4 + j] = cmax[nt][j];
        __syncthreads();
        #pragma unroll
        for (int nt = 0; nt < 4; ++nt)
            #pragma unroll
            for (int j = 0; j < 2; ++j)
                cmax[nt][j] = fmaxf(cmax[nt][j], red[(wm^1)*128 + wn*32 + nt*8 + 2*t4 + j]);

        #pragma unroll
        for (int nt = 0; nt < 4; ++nt) { csum[nt][0] = 0.f; csum[nt][1] = 0.f; }
        #pragma unroll
        for (int mt = 0; mt < 4; ++mt) {
            const int r0 = wm * 64 + mt * 16 + gidr, r1 = r0 + 8;
            #pragma unroll
            for (int nt = 0; nt < 4; ++nt) {
                float e0 = (r0 < SS) ? __expf(acc[mt][nt][0] - cmax[nt][0]) : 0.f;
                float e1 = (r0 < SS) ? __expf(acc[mt][nt][1] - cmax[nt][1]) : 0.f;
                float e2 = (r1 < SS) ? __expf(acc[mt][nt][2] - cmax[nt][0]) : 0.f;
                float e3 = (r1 < SS) ? __expf(acc[mt][nt][3] - cmax[nt][1]) : 0.f;
                acc[mt][nt][0] = e0; acc[mt][nt][1] = e1;
                acc[mt][nt][2] = e2; acc[mt][nt][3] = e3;
                csum[nt][0] += e0 + e2; csum[nt][1] += e1 + e3;
            }
        }
        #pragma unroll
        for (int nt = 0; nt < 4; ++nt)
            #pragma unroll
            for (int j = 0; j < 2; ++j) {
                float v = csum[nt][j];
                v += __shfl_xor_sync(0xffffffffu, v, 4);
                v += __shfl_xor_sync(0xffffffffu, v, 8);
                v += __shfl_xor_sync(0xffffffffu, v, 16);
                csum[nt][j] = v;
            }
        if (gidr == 0)
            #pragma unroll
            for (int nt = 0; nt < 4; ++nt)
                #pragma unroll
                for (int j = 0; j < 2; ++j)
                    red[256 + wm*128 + wn*32 + nt*8 + 2*t4 + j] = csum[nt][j];
        __syncthreads();
        #pragma unroll
        for (int nt = 0; nt < 4; ++nt)
            #pragma unroll
            for (int j = 0; j < 2; ++j)
                csum[nt][j] += red[256 + (wm^1)*128 + wn*32 + nt*8 + 2*t4 + j];
        __syncthreads();

        __half* sP = (__half*)smc;
        #pragma unroll
        for (int mt = 0; mt < 4; ++mt) {
            const int r0 = wm * 64 + mt * 16 + gidr, r1 = r0 + 8;
            #pragma unroll
            for (int nt = 0; nt < 4; ++nt) {
                const int nn = wn * 32 + nt * 8 + 2 * t4;
                const float i0 = 1.f / csum[nt][0], i1 = 1.f / csum[nt][1];
                if (r0 < 112)
                    *(__half2*)(sP + r0 * B_STRH + nn) =
                        __floats2half2_rn(acc[mt][nt][0] * i0, acc[mt][nt][1] * i1);
                if (r1 < 112)
                    *(__half2*)(sP + r1 * B_STRH + nn) =
                        __floats2half2_rn(acc[mt][nt][2] * i0, acc[mt][nt][3] * i1);
            }
        }
    }
    __syncthreads();

    // Phase 2: y[c][n] = Vp[c][s] @ P[s][n], 4 Vp tiles of 128c.
    const uint32_t sSP = sb;
    const uint32_t sVA = sb + ATT_SA;
    __half* yb = y + (size_t)b * CV * HW;

    #pragma unroll 1
    for (int cb = 0; cb < 4; ++cb) {
        if (cb) __syncthreads();
        const __half* gV = Vp + (size_t)b * CV * 112 + (size_t)(cb * 128) * 112;
        #pragma unroll
        for (int it = 0; it < 7; ++it) {
            int idx = it * 256 + tid;
            int r = idx / 14, c = idx - r * 14;
            cpa16(sVA + (uint32_t)(r * AO_ASTR + c * 8) * 2, gV + (size_t)r * 112 + c * 8);
        }
        asm volatile("cp.async.commit_group;\ncp.async.wait_group 0;" ::: "memory");
        __syncthreads();

        #pragma unroll
        for (int mt = 0; mt < 4; ++mt)
            #pragma unroll
            for (int nt = 0; nt < 4; ++nt)
                #pragma unroll
                for (int r = 0; r < 4; ++r) acc[mt][nt][r] = 0.f;

        #pragma unroll
        for (int s16 = 0; s16 < 7; ++s16) {
            const int kk = s16 * 16;
            uint32_t af[4][4], bf[4][2];
            #pragma unroll
            for (int mt = 0; mt < 4; ++mt) {
                int row = wm * 64 + mt * 16 + a_row;
                ldsm_x4(af[mt], sVA + (uint32_t)(row * AO_ASTR + kk + a_koff) * 2);
            }
            #pragma unroll
            for (int nt2 = 0; nt2 < 2; ++nt2) {
                uint32_t r4[4];
                int ncol = wn * 32 + nt2 * 16 + b_noff;
                ldsm_x4_t(r4, sSP + (uint32_t)((kk + b_krow) * B_STRH + ncol) * 2);
                bf[nt2*2][0] = r4[0]; bf[nt2*2][1] = r4[1];
                bf[nt2*2+1][0] = r4[2]; bf[nt2*2+1][1] = r4[3];
            }
            #pragma unroll
            for (int mt = 0; mt < 4; ++mt)
                #pragma unroll
                for (int nt = 0; nt < 4; ++nt)
                    mma_f16(acc[mt][nt], af[mt], bf[nt]);
        }

        #pragma unroll
        for (int mt = 0; mt < 4; ++mt) {
            const int ml = cb * 128 + wm * 64 + mt * 16 + gidr;
            #pragma unroll
            for (int nt = 0; nt < 4; ++nt) {
                const int nn = n0 + wn * 32 + nt * 8 + 2 * t4;
                *(__half2*)(yb + (size_t)ml * HW + nn) =
                    __floats2half2_rn(acc[mt][nt][0], acc[mt][nt][1]);
                *(__half2*)(yb + (size_t)(ml + 8) * HW + nn) =
                    __floats2half2_rn(acc[mt][nt][2], acc[mt][nt][3]);
            }
        }
    }
}

// ---------------------------------------------------------------------------
// Conversions: weights (one small launch) + per-group x conversion.
// ---------------------------------------------------------------------------
__global__ __launch_bounds__(256) void cvt_w_kernel(
    const float* __restrict__ wq, const float* __restrict__ wv,
    const float* __restrict__ wo,
    __half* __restrict__ oq, __half* __restrict__ ov, __half* __restrict__ oo)
{
    int i = blockIdx.x * 256 + threadIdx.x;
    if (i < CK*CIN) oq[i] = __float2half_rn(wq[i]);
    if (i < CV*CIN) { ov[i] = __float2half_rn(wv[i]); oo[i] = __float2half_rn(wo[i]); }
}

#define XG (GB*CIN*HW/16)     // 262144 -> 1024 blocks of 256
__global__ __launch_bounds__(256) void cvt_xg_kernel(
    const float4* __restrict__ x, uint4* __restrict__ xh)
{
    int i = blockIdx.x * 256 + threadIdx.x;
    float4 a0 = x[2*i], a1 = x[2*i+1];
    float4 b0 = x[2*(i + XG)], b1 = x[2*(i + XG)+1];
    __half2 h0 = __floats2half2_rn(a0.x, a0.y), h1 = __floats2half2_rn(a0.z, a0.w);
    __half2 h2 = __floats2half2_rn(a1.x, a1.y), h3 = __floats2half2_rn(a1.z, a1.w);
    __half2 g0 = __floats2half2_rn(b0.x, b0.y), g1 = __floats2half2_rn(b0.z, b0.w);
    __half2 g2 = __floats2half2_rn(b1.x, b1.y), g3 = __floats2half2_rn(b1.z, b1.w);
    uint4 u, v;
    u.x = *(uint32_t*)&h0; u.y = *(uint32_t*)&h1;
    u.z = *(uint32_t*)&h2; u.w = *(uint32_t*)&h3;
    v.x = *(uint32_t*)&g0; v.y = *(uint32_t*)&g1;
    v.z = *(uint32_t*)&g2; v.w = *(uint32_t*)&g3;
    xh[i] = u;
    xh[i + XG] = v;
}

// ---------------------------------------------------------------------------
// PSP adaptive max pool, register-resident phase 1. 4 planes per block.
// mode 0: out[(b*C + c)*112 + cell]   (value: [c][s] pad 112)
// mode 1: out[(b*128 + cell)*C + c]   (key:   [s pad128][c])
// ---------------------------------------------------------------------------
#define RM_STR 65

template<int A, int B>
__device__ __forceinline__ float segmax(const __half2* h) {
    constexpr int a2 = (A + 1) >> 1, b2 = B >> 1;
    __half2 m2 = __floats2half2_rn(-65504.f, -65504.f);
    #pragma unroll
    for (int c = a2; c < b2; ++c) m2 = __hmax2(m2, h[c]);
    float m = fmaxf(__low2float(m2), __high2float(m2));
    if (A & 1) m = fmaxf(m, __high2float(h[A >> 1]));
    if (B & 1) m = fmaxf(m, __low2float(h[B >> 1]));
    return m;
}

__global__ __launch_bounds__(256) void psp_kernel(
    const __half* __restrict__ in, __half* __restrict__ out, int C, int mode)
{
    __shared__ float rm[4][17 * RM_STR];
    __shared__ float s8v[4][64];
    const int pl = threadIdx.x >> 6;
    const int row = threadIdx.x & 63;
    const int bc = blockIdx.x * 4 + pl;
    const int b = bc / C, c = bc - b * C;
    float* rmp = rm[pl];

    __half2 h[32];
    {
        const uint4* rp = (const uint4*)(in + (size_t)bc * 4096 + row * 64);
        uint4* hv = (uint4*)h;
        #pragma unroll
        for (int i = 0; i < 8; ++i) hv[i] = rp[i];
    }

    rmp[ 0*RM_STR + row] = segmax< 0,22>(h);
    rmp[ 1*RM_STR + row] = segmax<21,43>(h);
    rmp[ 2*RM_STR + row] = segmax<42,64>(h);
    rmp[ 3*RM_STR + row] = segmax< 0,11>(h);
    rmp[ 4*RM_STR + row] = segmax<10,22>(h);
    rmp[ 5*RM_STR + row] = segmax<21,32>(h);
    rmp[ 6*RM_STR + row] = segmax<32,43>(h);
    rmp[ 7*RM_STR + row] = segmax<42,54>(h);
    rmp[ 8*RM_STR + row] = segmax<53,64>(h);
    rmp[ 9*RM_STR + row] = segmax< 0, 8>(h);
    rmp[10*RM_STR + row] = segmax< 8,16>(h);
    rmp[11*RM_STR + row] = segmax<16,24>(h);
    rmp[12*RM_STR + row] = segmax<24,32>(h);
    rmp[13*RM_STR + row] = segmax<32,40>(h);
    rmp[14*RM_STR + row] = segmax<40,48>(h);
    rmp[15*RM_STR + row] = segmax<48,56>(h);
    rmp[16*RM_STR + row] = segmax<56,64>(h);
    __syncthreads();

    {
        int i = row >> 3, j = row & 7;
        float m = rmp[(9 + j) * RM_STR + i * 8];
        #pragma unroll
        for (int r = 1; r < 8; ++r) m = fmaxf(m, rmp[(9 + j) * RM_STR + i * 8 + r]);
        s8v[pl][row] = m;
        int cell = 46 + row;
        size_t o = mode ? ((size_t)(b * 128 + cell) * C + c)
                        : ((size_t)bc * 112 + cell);
        out[o] = __float2half_rn(m);
    }
    __syncthreads();

    float m = -3.402823e38f;
    int cell = -1;
    if (row < 36) {
        const int st[6] = {0,10,21,32,42,53}, en[6] = {11,22,32,43,54,64};
        int i = row / 6, j = row - i * 6;
        m = rmp[(3 + j) * RM_STR + st[i]];
        for (int r = st[i] + 1; r < en[i]; ++r) m = fmaxf(m, rmp[(3 + j) * RM_STR + r]);
        cell = 10 + row;
    } else if (row < 45) {
        const int st[3] = {0,21,42}, en[3] = {22,43,64};
        int t = row - 36, i = t / 3, j = t - i * 3;
        m = rmp[j * RM_STR + st[i]];
        for (int r = st[i] + 1; r < en[i]; ++r) m = fmaxf(m, rmp[j * RM_STR + r]);
        cell = 1 + t;
    } else if (row == 45) {
        m = s8v[pl][0];
        for (int i = 1; i < 64; ++i) m = fmaxf(m, s8v[pl][i]);
        cell = 0;
    }
    if (cell >= 0) {
        size_t o = mode ? ((size_t)(b * 128 + cell) * C + c)
                        : ((size_t)bc * 112 + cell);
        out[o] = __float2half_rn(m);
    }
}

// ---------------------------------------------------------------------------
extern "C" void kernel_launch(void* const* d_in, const int* in_sizes, int n_in,
                              void* d_out, int out_size)
{
    const float* x        = (const float*)d_in[0];
    const float* qk_w     = (const float*)d_in[1];
    const float* qk_gamma = (const float*)d_in[2];
    const float* qk_beta  = (const float*)d_in[3];
    const float* qk_mean  = (const float*)d_in[4];
    const float* qk_var   = (const float*)d_in[5];
    const float* v_w      = (const float*)d_in[6];
    const float* v_gamma  = (const float*)d_in[7];
    const float* v_beta   = (const float*)d_in[8];
    const float* v_mean   = (const float*)d_in[9];
    const float* v_var    = (const float*)d_in[10];
    const float* out_w    = (const float*)d_in[11];
    const float* o_gamma  = (const float*)d_in[12];
    const float* o_beta   = (const float*)d_in[13];
    const float* o_mean   = (const float*)d_in[14];
    const float* o_var    = (const float*)d_in[15];
    float* out = (float*)d_out;

    __half *xh, *qkh, *valh, *keyh, *vpsp, *yh, *wq, *wv, *wo;
    cudaGetSymbolAddress((void**)&xh,   g_xh);
    cudaGetSymbolAddress((void**)&qkh,  g_qkh);
    cudaGetSymbolAddress((void**)&valh, g_valh);
    cudaGetSymbolAddress((void**)&keyh, g_keyh);
    cudaGetSymbolAddress((void**)&vpsp, g_vpsp);
    cudaGetSymbolAddress((void**)&yh,   g_yh);
    cudaGetSymbolAddress((void**)&wq,   g_wq);
    cudaGetSymbolAddress((void**)&wv,   g_wv);
    cudaGetSymbolAddress((void**)&wo,   g_wo);

    cudaFuncSetAttribute(gemm_kernel<true, true, false, true>,
                         cudaFuncAttributeMaxDynamicSharedMemorySize, GEMM_SMEM);
    cudaFuncSetAttribute(gemm_kernel<false, false, true, false>,
                         cudaFuncAttributeMaxDynamicSharedMemorySize, GEMM_SMEM);
    cudaFuncSetAttribute(attn_kernel,
                         cudaFuncAttributeMaxDynamicSharedMemorySize, GEMM_SMEM);

    // Side streams + events, created once on the first (uncaptured) call.
    static cudaStream_t ss[NG-1] = {nullptr, nullptr, nullptr};
    static cudaEvent_t ev_w = nullptr;
    static cudaEvent_t ev_done[NG-1] = {nullptr, nullptr, nullptr};
    if (ss[0] == nullptr) {
        for (int i = 0; i < NG-1; ++i) {
            cudaStreamCreateWithFlags(&ss[i], cudaStreamNonBlocking);
            cudaEventCreateWithFlags(&ev_done[i], cudaEventDisableTiming);
        }
        cudaEventCreateWithFlags(&ev_w, cudaEventDisableTiming);
    }

    // Run one complete pipeline for batches [g*GB, (g+1)*GB) on stream st.
    auto run_group = [&](int g, cudaStream_t st) {
        const size_t xo  = (size_t)g * GB * CIN * HW;
        const float*  xg   = x + xo;
        __half*       xhg  = xh + xo;
        __half*       qkg  = qkh + (size_t)g * GB * CK * HW;
        __half*       valg = valh + (size_t)g * GB * CV * HW;
        __half*       keyg = keyh + (size_t)g * GB * 128 * CK;
        __half*       vpg  = vpsp + (size_t)g * GB * CV * 112;
        __half*       yg   = yh + (size_t)g * GB * CV * HW;
        float*        og   = out + xo;

        cvt_xg_kernel<<<XG / 256, 256, 0, st>>>((const float4*)xg, (uint4*)xhg);
        gemm_kernel<true, true, false, true><<<dim3(32, 6, GB), 256, GEMM_SMEM, st>>>(
            wq, 0, xhg, (size_t)CIN*HW, qk_gamma, qk_beta, qk_mean, qk_var,
            nullptr, qkg, (size_t)CK*HW, CIN,
            wv, v_gamma, v_beta, v_mean, v_var, valg, (size_t)CV*HW);
        psp_kernel<<<GB * CK / 4, 256, 0, st>>>(qkg, keyg, CK, 1);
        psp_kernel<<<GB * CV / 4, 256, 0, st>>>(valg, vpg, CV, 0);
        attn_kernel<<<dim3(32, GB), 256, GEMM_SMEM, st>>>(keyg, qkg, vpg, yg);
        gemm_kernel<false, false, true, false><<<dim3(32, 4, GB), 256, GEMM_SMEM, st>>>(
            wo, 0, yg, (size_t)CV*HW, o_gamma, o_beta, o_mean, o_var,
            xg, og, (size_t)CIN*HW, CV,
            nullptr, nullptr, nullptr, nullptr, nullptr, nullptr, 0);
    };

    // Weights once (main stream); side groups wait on them via event.
    cvt_w_kernel<<<(CV*CIN + 255) / 256, 256>>>(qk_w, v_w, out_w, wq, wv, wo);
    cudaEventRecord(ev_w, 0);
    for (int i = 0; i < NG-1; ++i) cudaStreamWaitEvent(ss[i], ev_w, 0);

    run_group(0, 0);                       // batches 0-1 on capture stream
    for (int i = 0; i < NG-1; ++i)
        run_group(i + 1, ss[i]);           // batches 2-7 on side streams

    for (int i = 0; i < NG-1; ++i) {
        cudaEventRecord(ev_done[i], ss[i]);
        cudaStreamWaitEvent(0, ev_done[i], 0);
    }
}